// round 11
// baseline (speedup 1.0000x reference)
#include <cuda_runtime.h>
#include <cuda_bf16.h>
#include <math.h>
#include <stdint.h>

// ---------------- problem constants ----------------
#define NLAYER   8
#define DMODEL   1024
#define NHEAD    16
#define HEADDIM  64
#define DFF      4096
#define VOCAB    4096
#define BATCH    4
#define SEQ      2048
#define MTOK     (BATCH*SEQ)      // 8192 tokens

// ---------------- scratch (device globals; no allocation allowed) ----------------
__device__ float g_x  [MTOK*DMODEL];       // residual stream (fp32)
__device__ float g_qkv[MTOK*3*DMODEL];     // qkv (fp32)
__device__ float g_att[MTOK*DMODEL];       // attention out (fp32)
__device__ float g_mid[MTOK*DFF];          // gelu out (fp32)
// quantized activations (2-level int8) + per-row scales
__device__ int8_t g_hq1[MTOK*DMODEL];
__device__ int8_t g_hq2[MTOK*DMODEL];
__device__ float  g_sh [MTOK];
__device__ int8_t g_mq1[MTOK*DFF];
__device__ int8_t g_mq2[MTOK*DFF];
__device__ float  g_sm [MTOK];
// quantized weights [L][N][K] int8 (B^T layout) + per-N scales
__device__ int8_t g_wq_q1[NLAYER*3*DMODEL*DMODEL];
__device__ int8_t g_wq_q2[NLAYER*3*DMODEL*DMODEL];
__device__ int8_t g_wp_q1[NLAYER*DMODEL*DMODEL];
__device__ int8_t g_wp_q2[NLAYER*DMODEL*DMODEL];
__device__ int8_t g_w1_q1[NLAYER*DFF*DMODEL];
__device__ int8_t g_w1_q2[NLAYER*DFF*DMODEL];
__device__ int8_t g_w2_q1[NLAYER*DMODEL*DFF];
__device__ int8_t g_w2_q2[NLAYER*DMODEL*DFF];
__device__ int8_t g_tq1[VOCAB*DMODEL];
__device__ int8_t g_tq2[VOCAB*DMODEL];
__device__ float g_sbq[NLAYER*3*DMODEL];
__device__ float g_sbp[NLAYER*DMODEL];
__device__ float g_sb1[NLAYER*DFF];
__device__ float g_sb2[NLAYER*DMODEL];
__device__ float g_st [VOCAB];
__device__ float g_tce[MTOK];
__device__ float g_tw [MTOK];
__device__ int   g_mflag;

// ---------------- block reductions ----------------
__device__ __forceinline__ float blockReduceSum(float val) {
    __shared__ float sh[32];
    const int lane = threadIdx.x & 31, wid = threadIdx.x >> 5;
    #pragma unroll
    for (int o = 16; o; o >>= 1) val += __shfl_xor_sync(0xffffffffu, val, o);
    if (lane == 0) sh[wid] = val;
    __syncthreads();
    const int nw = (blockDim.x + 31) >> 5;
    float t = (threadIdx.x < nw) ? sh[threadIdx.x] : 0.0f;
    #pragma unroll
    for (int o = 16; o; o >>= 1) t += __shfl_xor_sync(0xffffffffu, t, o);
    if (threadIdx.x == 0) sh[0] = t;
    __syncthreads();
    t = sh[0];
    __syncthreads();
    return t;
}

__device__ __forceinline__ float blockReduceMax(float val) {
    __shared__ float sh[32];
    const int lane = threadIdx.x & 31, wid = threadIdx.x >> 5;
    #pragma unroll
    for (int o = 16; o; o >>= 1) val = fmaxf(val, __shfl_xor_sync(0xffffffffu, val, o));
    if (lane == 0) sh[wid] = val;
    __syncthreads();
    const int nw = (blockDim.x + 31) >> 5;
    float t = (threadIdx.x < nw) ? sh[threadIdx.x] : -INFINITY;
    #pragma unroll
    for (int o = 16; o; o >>= 1) t = fmaxf(t, __shfl_xor_sync(0xffffffffu, t, o));
    if (threadIdx.x == 0) sh[0] = t;
    __syncthreads();
    t = sh[0];
    __syncthreads();
    return t;
}

// ---------------- helpers ----------------
__device__ __forceinline__ void cp16(void* sdst, const void* gsrc) {
    uint32_t sa = (uint32_t)__cvta_generic_to_shared(sdst);
    asm volatile("cp.async.cg.shared.global [%0], [%1], 16;" :: "r"(sa), "l"(gsrc));
}
#define CP_COMMIT() asm volatile("cp.async.commit_group;" ::: "memory")

__device__ __forceinline__ uint32_t smem_u32(const void* p) {
    return (uint32_t)__cvta_generic_to_shared(p);
}

#define SWZ128(off) ((off) ^ (((off) >> 3) & 0x70))

__device__ __forceinline__ void imma16832(int* d, const uint32_t* a, const uint32_t* b) {
    asm volatile(
        "mma.sync.aligned.m16n8k32.row.col.s32.s8.s8.s32 "
        "{%0,%1,%2,%3}, {%4,%5,%6,%7}, {%8,%9}, {%0,%1,%2,%3};"
        : "+r"(d[0]), "+r"(d[1]), "+r"(d[2]), "+r"(d[3])
        : "r"(a[0]), "r"(a[1]), "r"(a[2]), "r"(a[3]), "r"(b[0]), "r"(b[1]));
}

__device__ __forceinline__ void ldsm4(uint32_t* r, uint32_t addr) {
    asm volatile("ldmatrix.sync.aligned.m8n8.x4.shared.b16 {%0,%1,%2,%3}, [%4];"
                 : "=r"(r[0]), "=r"(r[1]), "=r"(r[2]), "=r"(r[3]) : "r"(addr));
}

__device__ __forceinline__ int qclamp(float v) {
    v = rintf(v);
    v = fminf(127.0f, fmaxf(-127.0f, v));
    return (int)v;
}
__device__ __forceinline__ uint32_t pack4(int a, int b, int c, int d) {
    return (uint32_t)(a & 0xff) | ((uint32_t)(b & 0xff) << 8) |
           ((uint32_t)(c & 0xff) << 16) | ((uint32_t)(d & 0xff) << 24);
}

// ---------------- weight quantization ----------------
// per-output-channel scale: sB[n] = max_k |W[k][n]| / 127
__global__ __launch_bounds__(256) void colscale_kernel(
    const float* __restrict__ W, float* __restrict__ sB, int K, int N)
{
    const int n = blockIdx.x * 256 + threadIdx.x;
    const int l = blockIdx.y;
    const float* Wl = W + (size_t)l * K * N;
    float m = 0.0f;
    for (int k = 0; k < K; k += 4) {
        m = fmaxf(m, fabsf(Wl[(size_t)k * N + n]));
        m = fmaxf(m, fabsf(Wl[(size_t)(k+1) * N + n]));
        m = fmaxf(m, fabsf(Wl[(size_t)(k+2) * N + n]));
        m = fmaxf(m, fabsf(Wl[(size_t)(k+3) * N + n]));
    }
    sB[(size_t)l * N + n] = fmaxf(m, 1e-20f) * (1.0f / 127.0f);
}

// W [K][N] fp32 -> Q1,Q2 int8 [N][K] (transpose + 2-level quant)
__global__ __launch_bounds__(256) void convw_q8(
    const float* __restrict__ W, const float* __restrict__ sB,
    int8_t* __restrict__ Q1, int8_t* __restrict__ Q2, int K, int N)
{
    __shared__ float tile[32][33];
    const int tx = threadIdx.x & 31, ty = threadIdx.x >> 5;
    const int n0 = blockIdx.x * 32, k0 = blockIdx.y * 32;
    const int l = blockIdx.z;
    const float* Wl = W + (size_t)l * K * N;
    #pragma unroll
    for (int i = ty; i < 32; i += 8)
        tile[i][tx] = Wl[(size_t)(k0 + i) * N + n0 + tx];
    __syncthreads();
    int8_t* Q1l = Q1 + (size_t)l * N * K;
    int8_t* Q2l = Q2 + (size_t)l * N * K;
    #pragma unroll
    for (int i = ty; i < 32; i += 8) {
        const int n = n0 + i;
        const float s1 = sB[(size_t)l * N + n];
        const float w = tile[tx][i];                 // = W[k0+tx][n]
        const int q1 = qclamp(w / s1);
        const float r = w - (float)q1 * s1;
        const int q2 = qclamp(r / (s1 * 0.0078125f));
        Q1l[(size_t)n * K + k0 + tx] = (int8_t)q1;
        Q2l[(size_t)n * K + k0 + tx] = (int8_t)q2;
    }
}

// ---------------- per-row activation quantization ----------------
// src [R][width] fp32 -> q1,q2 int8, scale[row]; width in {1024,4096}
__global__ __launch_bounds__(256) void quant_rows_kernel(
    const float* __restrict__ src, int8_t* __restrict__ q1,
    int8_t* __restrict__ q2, float* __restrict__ scale, int width)
{
    const int row = blockIdx.x;
    const size_t base = (size_t)row * width;
    const int nit = width >> 10;
    float4 v[4];
    float m = 0.0f;
    for (int it = 0; it < nit; it++) {
        v[it] = *(const float4*)(src + base + it * 1024 + threadIdx.x * 4);
        m = fmaxf(m, fmaxf(fmaxf(fabsf(v[it].x), fabsf(v[it].y)),
                           fmaxf(fabsf(v[it].z), fabsf(v[it].w))));
    }
    m = blockReduceMax(m);
    m = fmaxf(m, 1e-20f);
    const float s1 = m * (1.0f / 127.0f);
    const float inv1 = 127.0f / m;
    const float inv2 = inv1 * 128.0f;
    for (int it = 0; it < nit; it++) {
        const int i0 = qclamp(v[it].x * inv1), i1 = qclamp(v[it].y * inv1);
        const int i2 = qclamp(v[it].z * inv1), i3 = qclamp(v[it].w * inv1);
        const int j0 = qclamp((v[it].x - i0 * s1) * inv2);
        const int j1 = qclamp((v[it].y - i1 * s1) * inv2);
        const int j2 = qclamp((v[it].z - i2 * s1) * inv2);
        const int j3 = qclamp((v[it].w - i3 * s1) * inv2);
        const size_t o = base + it * 1024 + threadIdx.x * 4;
        *(uint32_t*)(q1 + o) = pack4(i0, i1, i2, i3);
        *(uint32_t*)(q2 + o) = pack4(j0, j1, j2, j3);
    }
    if (threadIdx.x == 0) scale[row] = s1;
}

// ---------------- value_mask dtype probe ----------------
__global__ __launch_bounds__(256) void detect_mask_kernel(const unsigned char* __restrict__ m)
{
    __shared__ int sh[32];
    int s = 0;
    for (int i = threadIdx.x; i < 8192; i += 256)
        if (i & 3) s += m[i];
    #pragma unroll
    for (int o = 16; o; o >>= 1) s += __shfl_xor_sync(0xffffffffu, s, o);
    const int lane = threadIdx.x & 31, wid = threadIdx.x >> 5;
    if (lane == 0) sh[wid] = s;
    __syncthreads();
    if (threadIdx.x < 8) {
        int t = sh[threadIdx.x];
        #pragma unroll
        for (int o = 4; o; o >>= 1) t += __shfl_xor_sync(0xffu, t, o);
        if (threadIdx.x == 0) g_mflag = (t != 0) ? 1 : 0;
    }
}

// ---------------- embed ----------------
__global__ __launch_bounds__(256) void embed_kernel(
    const int* __restrict__ ids, const float* __restrict__ tok,
    const float* __restrict__ pos, float* __restrict__ x)
{
    const int m = blockIdx.x;
    const int t = m & (SEQ - 1);
    const int id = ids[m];
    const float4 a = ((const float4*)(tok + (size_t)id * DMODEL))[threadIdx.x];
    const float4 b = ((const float4*)(pos + (size_t)t  * DMODEL))[threadIdx.x];
    ((float4*)(x + (size_t)m * DMODEL))[threadIdx.x] =
        make_float4(a.x + b.x, a.y + b.y, a.z + b.z, a.w + b.w);
}

// ---------------- layernorm -> 2-level int8 ----------------
__global__ __launch_bounds__(256) void ln_q8_kernel(
    const float* __restrict__ x, const float* __restrict__ w,
    const float* __restrict__ b, int8_t* __restrict__ q1,
    int8_t* __restrict__ q2, float* __restrict__ scale)
{
    const int row = blockIdx.x;
    const float4 v = ((const float4*)(x + (size_t)row * DMODEL))[threadIdx.x];
    float s = v.x + v.y + v.z + v.w;
    s = blockReduceSum(s);
    const float mu = s * (1.0f / DMODEL);
    const float d0 = v.x - mu, d1 = v.y - mu, d2 = v.z - mu, d3 = v.w - mu;
    float q = d0*d0 + d1*d1 + d2*d2 + d3*d3;
    q = blockReduceSum(q);
    const float rs = rsqrtf(q * (1.0f / DMODEL) + 1e-5f);
    const float4 w4 = ((const float4*)w)[threadIdx.x];
    const float4 b4 = ((const float4*)b)[threadIdx.x];
    const float o0 = d0 * rs * w4.x + b4.x;
    const float o1 = d1 * rs * w4.y + b4.y;
    const float o2 = d2 * rs * w4.z + b4.z;
    const float o3 = d3 * rs * w4.w + b4.w;
    float m = fmaxf(fmaxf(fabsf(o0), fabsf(o1)), fmaxf(fabsf(o2), fabsf(o3)));
    m = blockReduceMax(m);
    m = fmaxf(m, 1e-20f);
    const float s1 = m * (1.0f / 127.0f);
    const float inv1 = 127.0f / m;
    const float inv2 = inv1 * 128.0f;
    const int i0 = qclamp(o0 * inv1), i1 = qclamp(o1 * inv1);
    const int i2 = qclamp(o2 * inv1), i3 = qclamp(o3 * inv1);
    const int j0 = qclamp((o0 - i0 * s1) * inv2);
    const int j1 = qclamp((o1 - i1 * s1) * inv2);
    const int j2 = qclamp((o2 - i2 * s1) * inv2);
    const int j3 = qclamp((o3 - i3 * s1) * inv2);
    const size_t o = (size_t)row * DMODEL + threadIdx.x * 4;
    *(uint32_t*)(q1 + o) = pack4(i0, i1, i2, i3);
    *(uint32_t*)(q2 + o) = pack4(j0, j1, j2, j3);
    if (threadIdx.x == 0) scale[row] = s1;
}

// ---------------- int8 2-level mma GEMM (ldmatrix + 2-stage cp.async) -----------
// C[M,N] = sum over K of sA[m]*sB[n]*(a1b1 + (a1b2+a2b1)/128), fp32 epilogue.
// CTA 128x128, k-chunk 128 (int8). smem: 2 stages x {A1,A2,B1,B2} 128x128B SW128.
enum { EPI_NONE = 0, EPI_RES = 1, EPI_GELU = 2 };

#define STAGE_BYTES 65536
#define GEMM_SMEM_BYTES (2*STAGE_BYTES)   // 131072

template<int EPI>
__global__ __launch_bounds__(256, 1) void gemm_q8_kernel(
    const int8_t* __restrict__ A1, const int8_t* __restrict__ A2,
    const float* __restrict__ sA,
    const int8_t* __restrict__ B1, const int8_t* __restrict__ B2,
    const float* __restrict__ sB,
    const float* __restrict__ bias, const float* __restrict__ res,
    float* __restrict__ C, int M, int N, int K)
{
    extern __shared__ __align__(1024) char smem[];
    const uint32_t sb = smem_u32(smem);
    const int tid = threadIdx.x, lane = tid & 31, wid = tid >> 5;
    const int wm = wid >> 2, wn = wid & 3;              // warp tile (wm*64, wn*32)
    const int bm = blockIdx.y * 128, bn = blockIdx.x * 128;

    int acc11[4][4][4], accmx[4][4][4];
    #pragma unroll
    for (int mt = 0; mt < 4; mt++)
        #pragma unroll
        for (int nt = 0; nt < 4; nt++)
            #pragma unroll
            for (int i = 0; i < 4; i++) { acc11[mt][nt][i] = 0; accmx[mt][nt][i] = 0; }

    // fill stage s with k-chunk kt (128 int8 elems): 4 arrays of 128 rows x 128B
    auto fill = [&](int s, int kt) {
        char* st = smem + s * STAGE_BYTES;
        const int k0 = kt << 7;
        #pragma unroll
        for (int i = 0; i < 4; i++) {
            const int idx = tid + i * 256;              // 0..1023
            const int row = idx >> 3, c16 = idx & 7;
            const uint32_t sw = SWZ128((uint32_t)((row << 7) + (c16 << 4)));
            const size_t ga = (size_t)(bm + row) * K + k0 + c16 * 16;
            const size_t gb = (size_t)(bn + row) * K + k0 + c16 * 16;
            cp16(st + sw,         A1 + ga);
            cp16(st + 16384 + sw, A2 + ga);
            cp16(st + 32768 + sw, B1 + gb);
            cp16(st + 49152 + sw, B2 + gb);
        }
    };

    // per-lane ldmatrix address components (byte-identical to bf16 k16 layout)
    const int laneRA = lane & 15;
    const int laneCA = (lane >> 4) << 4;
    const int laneRB = (lane & 7) + ((lane >> 4) << 3);
    const int laneCB = ((lane >> 3) & 1) << 4;

    const int niter = K >> 7;
    fill(0, 0); CP_COMMIT();

    for (int it = 0; it < niter; it++) {
        const int s = it & 1;
        if (it + 1 < niter) {
            fill(s ^ 1, it + 1); CP_COMMIT();
            asm volatile("cp.async.wait_group 1;" ::: "memory");
        } else {
            asm volatile("cp.async.wait_group 0;" ::: "memory");
        }
        __syncthreads();

        const uint32_t a1b = sb + s * STAGE_BYTES;
        const uint32_t a2b = a1b + 16384;
        const uint32_t b1b = a1b + 32768;
        const uint32_t b2b = a1b + 49152;

        #pragma unroll
        for (int ks = 0; ks < 4; ks++) {                // 4 x k32 per 128B chunk
            const int kb = ks * 32;
            uint32_t a1[4][4], a2[4][4], b1[4][2], b2[4][2];
            #pragma unroll
            for (int mt = 0; mt < 4; mt++) {
                const uint32_t off = SWZ128(
                    (uint32_t)(((wm * 64 + mt * 16 + laneRA) << 7) + kb + laneCA));
                ldsm4(a1[mt], a1b + off);
                ldsm4(a2[mt], a2b + off);
            }
            #pragma unroll
            for (int j = 0; j < 2; j++) {
                const uint32_t off = SWZ128(
                    (uint32_t)(((wn * 32 + j * 16 + laneRB) << 7) + kb + laneCB));
                ldsm4(&b1[j * 2][0], b1b + off);
                ldsm4(&b2[j * 2][0], b2b + off);
            }
            #pragma unroll
            for (int mt = 0; mt < 4; mt++)
                #pragma unroll
                for (int nt = 0; nt < 4; nt++) imma16832(acc11[mt][nt], a1[mt], b1[nt]);
            #pragma unroll
            for (int mt = 0; mt < 4; mt++)
                #pragma unroll
                for (int nt = 0; nt < 4; nt++) imma16832(accmx[mt][nt], a1[mt], b2[nt]);
            #pragma unroll
            for (int mt = 0; mt < 4; mt++)
                #pragma unroll
                for (int nt = 0; nt < 4; nt++) imma16832(accmx[mt][nt], a2[mt], b1[nt]);
        }
        __syncthreads();
    }

    // ---- epilogue: dequant + bias + (gelu | residual) ----
    const int g = lane >> 2, t = lane & 3;
    #pragma unroll
    for (int mt = 0; mt < 4; mt++) {
        #pragma unroll
        for (int nt = 0; nt < 4; nt++) {
            const int col = bn + wn * 32 + nt * 8 + 2 * t;
            const float sb0 = sB[col], sb1 = sB[col + 1];
            #pragma unroll
            for (int half = 0; half < 2; half++) {
                const int row = bm + wm * 64 + mt * 16 + g + half * 8;
                const float sa = sA[row];
                float v0 = sa * sb0 * ((float)acc11[mt][nt][2*half+0]
                                       + 0.0078125f * (float)accmx[mt][nt][2*half+0]);
                float v1 = sa * sb1 * ((float)acc11[mt][nt][2*half+1]
                                       + 0.0078125f * (float)accmx[mt][nt][2*half+1]);
                if (bias) { v0 += bias[col]; v1 += bias[col + 1]; }
                if (EPI == EPI_GELU) {
                    v0 = 0.5f * v0 * (1.0f + erff(v0 * 0.70710678118654752f));
                    v1 = 0.5f * v1 * (1.0f + erff(v1 * 0.70710678118654752f));
                }
                const size_t o = (size_t)row * N + col;
                if (EPI == EPI_RES) {
                    const float2 r2 = *(const float2*)(res + o);
                    v0 += r2.x; v1 += r2.y;
                }
                *(float2*)(C + o) = make_float2(v0, v1);
            }
        }
    }
}

// ---------------- causal flash attention (fp32 in/out, 128 queries/block) --------
__global__ __launch_bounds__(128) void attn_kernel(
    const float* __restrict__ qkv, float* __restrict__ out)
{
    const int qt = blockIdx.x, h = blockIdx.y, b = blockIdx.z;
    const int tid = threadIdx.x;
    const int qg = qt * 128 + tid;
    const size_t mrow = (size_t)b * SEQ + qg;

    __shared__ float Ks[32][64];
    __shared__ float Vs[32][64];
    __shared__ float Sp[32][128];

    float qreg[64];
    {
        const float4* qp = (const float4*)(qkv + mrow * (3 * DMODEL) + h * HEADDIM);
        #pragma unroll
        for (int i = 0; i < 16; i++) {
            const float4 t4 = qp[i];
            qreg[4*i+0] = t4.x; qreg[4*i+1] = t4.y; qreg[4*i+2] = t4.z; qreg[4*i+3] = t4.w;
        }
    }

    float acc[64];
    #pragma unroll
    for (int d = 0; d < 64; d++) acc[d] = 0.0f;
    float m_i = -INFINITY, l_i = 0.0f;
    const float scale = 0.125f;

    const float* kbase = qkv + (size_t)b * SEQ * (3 * DMODEL) + DMODEL     + h * HEADDIM;
    const float* vbase = qkv + (size_t)b * SEQ * (3 * DMODEL) + 2 * DMODEL + h * HEADDIM;

    const int nkt = 4 * qt + 4;
    for (int kt = 0; kt < nkt; kt++) {
        {
            const int r0 = tid >> 4;
            const int c4 = tid & 15;
            #pragma unroll
            for (int it2 = 0; it2 < 4; it2++) {
                const int r = it2 * 8 + r0;
                const size_t roff = (size_t)(kt * 32 + r) * (3 * DMODEL);
                *(float4*)&Ks[r][c4 * 4] = *(const float4*)(kbase + roff + c4 * 4);
                *(float4*)&Vs[r][c4 * 4] = *(const float4*)(vbase + roff + c4 * 4);
            }
        }
        __syncthreads();

        const int kg0 = kt * 32;
        float tmax = -INFINITY;
        #pragma unroll 2
        for (int j = 0; j < 32; j++) {
            float s = 0.0f;
            const float4* kr = (const float4*)Ks[j];
            #pragma unroll
            for (int i = 0; i < 16; i++) {
                const float4 kf = kr[i];
                s += qreg[4*i+0]*kf.x + qreg[4*i+1]*kf.y + qreg[4*i+2]*kf.z + qreg[4*i+3]*kf.w;
            }
            s *= scale;
            s = (kg0 + j <= qg) ? s : -INFINITY;
            Sp[j][tid] = s;
            tmax = fmaxf(tmax, s);
        }

        const float mnew = fmaxf(m_i, tmax);
        const float corr = expf(m_i - mnew);
        #pragma unroll
        for (int d = 0; d < 64; d++) acc[d] *= corr;

        float lsum = 0.0f;
        #pragma unroll 2
        for (int j = 0; j < 32; j++) {
            const float e = expf(Sp[j][tid] - mnew);
            lsum += e;
            const float4* vr = (const float4*)Vs[j];
            #pragma unroll
            for (int i = 0; i < 16; i++) {
                const float4 vf = vr[i];
                acc[4*i+0] += e * vf.x; acc[4*i+1] += e * vf.y;
                acc[4*i+2] += e * vf.z; acc[4*i+3] += e * vf.w;
            }
        }
        l_i = l_i * corr + lsum;
        m_i = mnew;
        __syncthreads();
    }

    const float inv = 1.0f / l_i;
    float4* op = (float4*)(out + mrow * DMODEL + h * HEADDIM);
    #pragma unroll
    for (int i = 0; i < 16; i++)
        op[i] = make_float4(acc[4*i+0]*inv, acc[4*i+1]*inv, acc[4*i+2]*inv, acc[4*i+3]*inv);
}

// ---------------- loss ----------------
__global__ __launch_bounds__(256) void loss_token_kernel(
    const float* __restrict__ logits, const int* __restrict__ targets,
    const void* __restrict__ vmask,
    float* __restrict__ tce, float* __restrict__ tw)
{
    const int row = blockIdx.x;
    const float* lr = logits + (size_t)row * VOCAB;
    float v[16];
    #pragma unroll
    for (int i = 0; i < 16; i++) v[i] = lr[threadIdx.x + 256 * i];
    float mx = v[0];
    #pragma unroll
    for (int i = 1; i < 16; i++) mx = fmaxf(mx, v[i]);
    mx = blockReduceMax(mx);
    float se = 0.0f;
    #pragma unroll
    for (int i = 0; i < 16; i++) se += expf(v[i] - mx);
    se = blockReduceSum(se);
    if (threadIdx.x == 0) {
        const int tgt = targets[row];
        const float lse = mx + logf(se);
        const float nll = lse - lr[tgt];
        int mv;
        if (g_mflag) mv = ((const unsigned char*)vmask)[row];
        else         mv = ((const int*)vmask)[row];
        const float w = 1.0f + 4.0f * ((mv != 0) ? 1.0f : 0.0f);
        tce[row] = (tgt == 0) ? 0.0f : nll * w;
        tw[row]  = w;
    }
}

__global__ __launch_bounds__(256) void loss_final_kernel(
    const float* __restrict__ tce, const float* __restrict__ tw, float* __restrict__ out)
{
    float a = 0.0f, b = 0.0f;
    for (int i = threadIdx.x; i < MTOK; i += 256) { a += tce[i]; b += tw[i]; }
    a = blockReduceSum(a);
    b = blockReduceSum(b);
    if (threadIdx.x == 0) out[0] = a / b;
}

// ---------------- host driver ----------------
extern "C" void kernel_launch(void* const* d_in, const int* in_sizes, int n_in,
                              void* d_out, int out_size)
{
    (void)in_sizes; (void)n_in;
    const int*   ids   = (const int*)d_in[0];
    const int*   tgts  = (const int*)d_in[1];
    const void*  vmask = (const void*)d_in[2];
    const float* tok   = (const float*)d_in[3];
    const float* pos   = (const float*)d_in[4];
    const float* ln1w  = (const float*)d_in[5];
    const float* ln1b  = (const float*)d_in[6];
    const float* wqkv  = (const float*)d_in[7];
    const float* bqkv  = (const float*)d_in[8];
    const float* wproj = (const float*)d_in[9];
    const float* bproj = (const float*)d_in[10];
    const float* ln2w  = (const float*)d_in[11];
    const float* ln2b  = (const float*)d_in[12];
    const float* w1    = (const float*)d_in[13];
    const float* b1    = (const float*)d_in[14];
    const float* w2    = (const float*)d_in[15];
    const float* b2    = (const float*)d_in[16];
    const float* lnfw  = (const float*)d_in[17];
    const float* lnfb  = (const float*)d_in[18];
    float* out = (float*)d_out;

    float *x, *qkv, *att, *mid, *tce, *tw, *sh, *sm;
    float *sbq, *sbp, *sb1, *sb2, *st;
    int8_t *hq1, *hq2, *mq1, *mq2;
    int8_t *wqq1, *wqq2, *wpq1, *wpq2, *w1q1, *w1q2, *w2q1, *w2q2, *tq1, *tq2;
    cudaGetSymbolAddress((void**)&x,    g_x);
    cudaGetSymbolAddress((void**)&qkv,  g_qkv);
    cudaGetSymbolAddress((void**)&att,  g_att);
    cudaGetSymbolAddress((void**)&mid,  g_mid);
    cudaGetSymbolAddress((void**)&hq1,  g_hq1);
    cudaGetSymbolAddress((void**)&hq2,  g_hq2);
    cudaGetSymbolAddress((void**)&sh,   g_sh);
    cudaGetSymbolAddress((void**)&mq1,  g_mq1);
    cudaGetSymbolAddress((void**)&mq2,  g_mq2);
    cudaGetSymbolAddress((void**)&sm,   g_sm);
    cudaGetSymbolAddress((void**)&wqq1, g_wq_q1);
    cudaGetSymbolAddress((void**)&wqq2, g_wq_q2);
    cudaGetSymbolAddress((void**)&wpq1, g_wp_q1);
    cudaGetSymbolAddress((void**)&wpq2, g_wp_q2);
    cudaGetSymbolAddress((void**)&w1q1, g_w1_q1);
    cudaGetSymbolAddress((void**)&w1q2, g_w1_q2);
    cudaGetSymbolAddress((void**)&w2q1, g_w2_q1);
    cudaGetSymbolAddress((void**)&w2q2, g_w2_q2);
    cudaGetSymbolAddress((void**)&tq1,  g_tq1);
    cudaGetSymbolAddress((void**)&tq2,  g_tq2);
    cudaGetSymbolAddress((void**)&sbq,  g_sbq);
    cudaGetSymbolAddress((void**)&sbp,  g_sbp);
    cudaGetSymbolAddress((void**)&sb1,  g_sb1);
    cudaGetSymbolAddress((void**)&sb2,  g_sb2);
    cudaGetSymbolAddress((void**)&st,   g_st);
    cudaGetSymbolAddress((void**)&tce,  g_tce);
    cudaGetSymbolAddress((void**)&tw,   g_tw);

    cudaFuncSetAttribute(gemm_q8_kernel<EPI_NONE>,
                         cudaFuncAttributeMaxDynamicSharedMemorySize, GEMM_SMEM_BYTES);
    cudaFuncSetAttribute(gemm_q8_kernel<EPI_RES>,
                         cudaFuncAttributeMaxDynamicSharedMemorySize, GEMM_SMEM_BYTES);
    cudaFuncSetAttribute(gemm_q8_kernel<EPI_GELU>,
                         cudaFuncAttributeMaxDynamicSharedMemorySize, GEMM_SMEM_BYTES);

    // ---- weight quantization (per replay) ----
    colscale_kernel<<<dim3(3*DMODEL/256, NLAYER), 256>>>(wqkv,  sbq, DMODEL, 3*DMODEL);
    colscale_kernel<<<dim3(DMODEL/256,   NLAYER), 256>>>(wproj, sbp, DMODEL, DMODEL);
    colscale_kernel<<<dim3(DFF/256,      NLAYER), 256>>>(w1,    sb1, DMODEL, DFF);
    colscale_kernel<<<dim3(DMODEL/256,   NLAYER), 256>>>(w2,    sb2, DFF,    DMODEL);
    convw_q8<<<dim3(3*DMODEL/32, DMODEL/32, NLAYER), 256>>>(wqkv,  sbq, wqq1, wqq2, DMODEL, 3*DMODEL);
    convw_q8<<<dim3(DMODEL/32,   DMODEL/32, NLAYER), 256>>>(wproj, sbp, wpq1, wpq2, DMODEL, DMODEL);
    convw_q8<<<dim3(DFF/32,      DMODEL/32, NLAYER), 256>>>(w1,    sb1, w1q1, w1q2, DMODEL, DFF);
    convw_q8<<<dim3(DMODEL/32,   DFF/32,    NLAYER), 256>>>(w2,    sb2, w2q1, w2q2, DFF,    DMODEL);
    // lm_head: tok already [V][K] row-major -> per-row quant, no transpose
    quant_rows_kernel<<<VOCAB, 256>>>(tok, tq1, tq2, st, DMODEL);

    detect_mask_kernel<<<1, 256>>>((const unsigned char*)vmask);
    embed_kernel<<<MTOK, 256>>>(ids, tok, pos, x);

    const size_t wq_s = (size_t)3*DMODEL*DMODEL;
    const size_t wp_s = (size_t)DMODEL*DMODEL;
    const size_t w1_s = (size_t)DFF*DMODEL;
    const size_t w2_s = (size_t)DMODEL*DFF;

    for (int l = 0; l < NLAYER; l++) {
        ln_q8_kernel<<<MTOK, 256>>>(x, ln1w + l*DMODEL, ln1b + l*DMODEL, hq1, hq2, sh);

        gemm_q8_kernel<EPI_NONE><<<dim3(3*DMODEL/128, MTOK/128), 256, GEMM_SMEM_BYTES>>>(
            hq1, hq2, sh, wqq1 + l*wq_s, wqq2 + l*wq_s, sbq + (size_t)l*3*DMODEL,
            bqkv + (size_t)l*3*DMODEL, nullptr, qkv, MTOK, 3*DMODEL, DMODEL);

        attn_kernel<<<dim3(SEQ/128, NHEAD, BATCH), 128>>>(qkv, att);
        quant_rows_kernel<<<MTOK, 256>>>(att, hq1, hq2, sh, DMODEL);

        gemm_q8_kernel<EPI_RES><<<dim3(DMODEL/128, MTOK/128), 256, GEMM_SMEM_BYTES>>>(
            hq1, hq2, sh, wpq1 + l*wp_s, wpq2 + l*wp_s, sbp + (size_t)l*DMODEL,
            bproj + (size_t)l*DMODEL, x, x, MTOK, DMODEL, DMODEL);

        ln_q8_kernel<<<MTOK, 256>>>(x, ln2w + l*DMODEL, ln2b + l*DMODEL, hq1, hq2, sh);

        gemm_q8_kernel<EPI_GELU><<<dim3(DFF/128, MTOK/128), 256, GEMM_SMEM_BYTES>>>(
            hq1, hq2, sh, w1q1 + l*w1_s, w1q2 + l*w1_s, sb1 + (size_t)l*DFF,
            b1 + (size_t)l*DFF, nullptr, mid, MTOK, DFF, DMODEL);

        quant_rows_kernel<<<MTOK, 256>>>(mid, mq1, mq2, sm, DFF);

        gemm_q8_kernel<EPI_RES><<<dim3(DMODEL/128, MTOK/128), 256, GEMM_SMEM_BYTES>>>(
            mq1, mq2, sm, w2q1 + l*w2_s, w2q2 + l*w2_s, sb2 + (size_t)l*DMODEL,
            b2 + (size_t)l*DMODEL, x, x, MTOK, DMODEL, DFF);
    }

    ln_q8_kernel<<<MTOK, 256>>>(x, lnfw, lnfb, hq1, hq2, sh);

    gemm_q8_kernel<EPI_NONE><<<dim3(VOCAB/128, MTOK/128), 256, GEMM_SMEM_BYTES>>>(
        hq1, hq2, sh, tq1, tq2, st, nullptr, nullptr, out, MTOK, VOCAB, DMODEL);

    if (out_size > MTOK * VOCAB) {
        loss_token_kernel<<<MTOK, 256>>>(out, tgts, vmask, tce, tw);
        loss_final_kernel<<<1, 256>>>(tce, tw, out + (size_t)MTOK * VOCAB);
    }
}

// round 12
// speedup vs baseline: 1.0758x; 1.0758x over previous
#include <cuda_runtime.h>
#include <cuda_bf16.h>
#include <math.h>
#include <stdint.h>

// ---------------- problem constants ----------------
#define NLAYER   8
#define DMODEL   1024
#define NHEAD    16
#define HEADDIM  64
#define DFF      4096
#define VOCAB    4096
#define BATCH    4
#define SEQ      2048
#define MTOK     (BATCH*SEQ)      // 8192 tokens

// ---------------- scratch (device globals; no allocation allowed) ----------------
__device__ float g_x  [MTOK*DMODEL];       // residual stream (fp32)
__device__ float g_qkv[MTOK*3*DMODEL];     // qkv (fp32)
__device__ float g_att[MTOK*DMODEL];       // attention out (fp32)
__device__ float g_mid[MTOK*DFF];          // gelu out (fp32)
// quantized activations (2-level int8) + per-row scales
__device__ int8_t g_hq1[MTOK*DMODEL];
__device__ int8_t g_hq2[MTOK*DMODEL];
__device__ float  g_sh [MTOK];
__device__ int8_t g_mq1[MTOK*DFF];
__device__ int8_t g_mq2[MTOK*DFF];
__device__ float  g_sm [MTOK];
// quantized weights [L][N][K] int8 (B^T layout) + per-N scales
__device__ int8_t g_wq_q1[NLAYER*3*DMODEL*DMODEL];
__device__ int8_t g_wq_q2[NLAYER*3*DMODEL*DMODEL];
__device__ int8_t g_wp_q1[NLAYER*DMODEL*DMODEL];
__device__ int8_t g_wp_q2[NLAYER*DMODEL*DMODEL];
__device__ int8_t g_w1_q1[NLAYER*DFF*DMODEL];
__device__ int8_t g_w1_q2[NLAYER*DFF*DMODEL];
__device__ int8_t g_w2_q1[NLAYER*DMODEL*DFF];
__device__ int8_t g_w2_q2[NLAYER*DMODEL*DFF];
__device__ int8_t g_tq1[VOCAB*DMODEL];
__device__ int8_t g_tq2[VOCAB*DMODEL];
__device__ float g_sbq[NLAYER*3*DMODEL];
__device__ float g_sbp[NLAYER*DMODEL];
__device__ float g_sb1[NLAYER*DFF];
__device__ float g_sb2[NLAYER*DMODEL];
__device__ float g_st [VOCAB];
__device__ float g_tce[MTOK];
__device__ float g_tw [MTOK];
__device__ int   g_mflag;

// ---------------- block reductions ----------------
__device__ __forceinline__ float blockReduceSum(float val) {
    __shared__ float sh[32];
    const int lane = threadIdx.x & 31, wid = threadIdx.x >> 5;
    #pragma unroll
    for (int o = 16; o; o >>= 1) val += __shfl_xor_sync(0xffffffffu, val, o);
    if (lane == 0) sh[wid] = val;
    __syncthreads();
    const int nw = (blockDim.x + 31) >> 5;
    float t = (threadIdx.x < nw) ? sh[threadIdx.x] : 0.0f;
    #pragma unroll
    for (int o = 16; o; o >>= 1) t += __shfl_xor_sync(0xffffffffu, t, o);
    if (threadIdx.x == 0) sh[0] = t;
    __syncthreads();
    t = sh[0];
    __syncthreads();
    return t;
}

__device__ __forceinline__ float blockReduceMax(float val) {
    __shared__ float sh[32];
    const int lane = threadIdx.x & 31, wid = threadIdx.x >> 5;
    #pragma unroll
    for (int o = 16; o; o >>= 1) val = fmaxf(val, __shfl_xor_sync(0xffffffffu, val, o));
    if (lane == 0) sh[wid] = val;
    __syncthreads();
    const int nw = (blockDim.x + 31) >> 5;
    float t = (threadIdx.x < nw) ? sh[threadIdx.x] : -INFINITY;
    #pragma unroll
    for (int o = 16; o; o >>= 1) t = fmaxf(t, __shfl_xor_sync(0xffffffffu, t, o));
    if (threadIdx.x == 0) sh[0] = t;
    __syncthreads();
    t = sh[0];
    __syncthreads();
    return t;
}

// ---------------- helpers ----------------
__device__ __forceinline__ void cp16(void* sdst, const void* gsrc) {
    uint32_t sa = (uint32_t)__cvta_generic_to_shared(sdst);
    asm volatile("cp.async.cg.shared.global [%0], [%1], 16;" :: "r"(sa), "l"(gsrc));
}
#define CP_COMMIT() asm volatile("cp.async.commit_group;" ::: "memory")

__device__ __forceinline__ uint32_t smem_u32(const void* p) {
    return (uint32_t)__cvta_generic_to_shared(p);
}

#define SWZ128(off) ((off) ^ (((off) >> 3) & 0x70))

__device__ __forceinline__ void imma16832(int* d, const uint32_t* a, const uint32_t* b) {
    asm volatile(
        "mma.sync.aligned.m16n8k32.row.col.s32.s8.s8.s32 "
        "{%0,%1,%2,%3}, {%4,%5,%6,%7}, {%8,%9}, {%0,%1,%2,%3};"
        : "+r"(d[0]), "+r"(d[1]), "+r"(d[2]), "+r"(d[3])
        : "r"(a[0]), "r"(a[1]), "r"(a[2]), "r"(a[3]), "r"(b[0]), "r"(b[1]));
}

__device__ __forceinline__ void ldsm4(uint32_t* r, uint32_t addr) {
    asm volatile("ldmatrix.sync.aligned.m8n8.x4.shared.b16 {%0,%1,%2,%3}, [%4];"
                 : "=r"(r[0]), "=r"(r[1]), "=r"(r[2]), "=r"(r[3]) : "r"(addr));
}

__device__ __forceinline__ int qclamp(float v) {
    v = rintf(v);
    v = fminf(127.0f, fmaxf(-127.0f, v));
    return (int)v;
}
__device__ __forceinline__ uint32_t pack4(int a, int b, int c, int d) {
    return (uint32_t)(a & 0xff) | ((uint32_t)(b & 0xff) << 8) |
           ((uint32_t)(c & 0xff) << 16) | ((uint32_t)(d & 0xff) << 24);
}

// ---------------- fused weight quantization ----------------
// Block owns 32 output channels (n0..n0+31) for all K of one layer.
// Pass 1: per-channel max (coalesced). Pass 2: tiled transpose + 2-level quant.
__global__ __launch_bounds__(256) void convw_q8f(
    const float* __restrict__ W, float* __restrict__ sB,
    int8_t* __restrict__ Q1, int8_t* __restrict__ Q2, int K, int N)
{
    __shared__ float smax[8][32];
    __shared__ float tile[32][33];
    __shared__ float s_s1[32], s_i1[32], s_i2[32];
    const int tx = threadIdx.x & 31, ty = threadIdx.x >> 5;
    const int n0 = blockIdx.x * 32;
    const int l = blockIdx.y;
    const float* Wl = W + (size_t)l * K * N;

    float m = 0.0f;
    for (int k = ty; k < K; k += 8)
        m = fmaxf(m, fabsf(Wl[(size_t)k * N + n0 + tx]));
    smax[ty][tx] = m;
    __syncthreads();
    if (ty == 0) {
        float mm = smax[0][tx];
        #pragma unroll
        for (int i = 1; i < 8; i++) mm = fmaxf(mm, smax[i][tx]);
        mm = fmaxf(mm, 1e-20f);
        const float s1 = mm * (1.0f / 127.0f);
        s_s1[tx] = s1;
        s_i1[tx] = 127.0f / mm;
        s_i2[tx] = 127.0f / mm * 128.0f;
        sB[(size_t)l * N + n0 + tx] = s1;
    }
    __syncthreads();

    int8_t* Q1l = Q1 + (size_t)l * N * K;
    int8_t* Q2l = Q2 + (size_t)l * N * K;
    for (int k0 = 0; k0 < K; k0 += 32) {
        #pragma unroll
        for (int i = ty; i < 32; i += 8)
            tile[i][tx] = Wl[(size_t)(k0 + i) * N + n0 + tx];
        __syncthreads();
        #pragma unroll
        for (int i = ty; i < 32; i += 8) {
            const int n = n0 + i;
            const float w = tile[tx][i];            // = W[k0+tx][n]
            const int q1 = qclamp(w * s_i1[i]);
            const int q2 = qclamp((w - (float)q1 * s_s1[i]) * s_i2[i]);
            Q1l[(size_t)n * K + k0 + tx] = (int8_t)q1;
            Q2l[(size_t)n * K + k0 + tx] = (int8_t)q2;
        }
        __syncthreads();
    }
}

// ---------------- per-row activation quantization ----------------
__global__ __launch_bounds__(256) void quant_rows_kernel(
    const float* __restrict__ src, int8_t* __restrict__ q1,
    int8_t* __restrict__ q2, float* __restrict__ scale, int width)
{
    const int row = blockIdx.x;
    const size_t base = (size_t)row * width;
    const int nit = width >> 10;
    float4 v[4];
    float m = 0.0f;
    for (int it = 0; it < nit; it++) {
        v[it] = *(const float4*)(src + base + it * 1024 + threadIdx.x * 4);
        m = fmaxf(m, fmaxf(fmaxf(fabsf(v[it].x), fabsf(v[it].y)),
                           fmaxf(fabsf(v[it].z), fabsf(v[it].w))));
    }
    m = blockReduceMax(m);
    m = fmaxf(m, 1e-20f);
    const float s1 = m * (1.0f / 127.0f);
    const float inv1 = 127.0f / m;
    const float inv2 = inv1 * 128.0f;
    for (int it = 0; it < nit; it++) {
        const int i0 = qclamp(v[it].x * inv1), i1 = qclamp(v[it].y * inv1);
        const int i2 = qclamp(v[it].z * inv1), i3 = qclamp(v[it].w * inv1);
        const int j0 = qclamp((v[it].x - i0 * s1) * inv2);
        const int j1 = qclamp((v[it].y - i1 * s1) * inv2);
        const int j2 = qclamp((v[it].z - i2 * s1) * inv2);
        const int j3 = qclamp((v[it].w - i3 * s1) * inv2);
        const size_t o = base + it * 1024 + threadIdx.x * 4;
        *(uint32_t*)(q1 + o) = pack4(i0, i1, i2, i3);
        *(uint32_t*)(q2 + o) = pack4(j0, j1, j2, j3);
    }
    if (threadIdx.x == 0) scale[row] = s1;
}

// ---------------- value_mask dtype probe ----------------
__global__ __launch_bounds__(256) void detect_mask_kernel(const unsigned char* __restrict__ m)
{
    __shared__ int sh[32];
    int s = 0;
    for (int i = threadIdx.x; i < 8192; i += 256)
        if (i & 3) s += m[i];
    #pragma unroll
    for (int o = 16; o; o >>= 1) s += __shfl_xor_sync(0xffffffffu, s, o);
    const int lane = threadIdx.x & 31, wid = threadIdx.x >> 5;
    if (lane == 0) sh[wid] = s;
    __syncthreads();
    if (threadIdx.x < 8) {
        int t = sh[threadIdx.x];
        #pragma unroll
        for (int o = 4; o; o >>= 1) t += __shfl_xor_sync(0xffu, t, o);
        if (threadIdx.x == 0) g_mflag = (t != 0) ? 1 : 0;
    }
}

// ---------------- embed ----------------
__global__ __launch_bounds__(256) void embed_kernel(
    const int* __restrict__ ids, const float* __restrict__ tok,
    const float* __restrict__ pos, float* __restrict__ x)
{
    const int m = blockIdx.x;
    const int t = m & (SEQ - 1);
    const int id = ids[m];
    const float4 a = ((const float4*)(tok + (size_t)id * DMODEL))[threadIdx.x];
    const float4 b = ((const float4*)(pos + (size_t)t  * DMODEL))[threadIdx.x];
    ((float4*)(x + (size_t)m * DMODEL))[threadIdx.x] =
        make_float4(a.x + b.x, a.y + b.y, a.z + b.z, a.w + b.w);
}

// ---------------- layernorm -> 2-level int8 ----------------
__global__ __launch_bounds__(256) void ln_q8_kernel(
    const float* __restrict__ x, const float* __restrict__ w,
    const float* __restrict__ b, int8_t* __restrict__ q1,
    int8_t* __restrict__ q2, float* __restrict__ scale)
{
    const int row = blockIdx.x;
    const float4 v = ((const float4*)(x + (size_t)row * DMODEL))[threadIdx.x];
    float s = v.x + v.y + v.z + v.w;
    s = blockReduceSum(s);
    const float mu = s * (1.0f / DMODEL);
    const float d0 = v.x - mu, d1 = v.y - mu, d2 = v.z - mu, d3 = v.w - mu;
    float q = d0*d0 + d1*d1 + d2*d2 + d3*d3;
    q = blockReduceSum(q);
    const float rs = rsqrtf(q * (1.0f / DMODEL) + 1e-5f);
    const float4 w4 = ((const float4*)w)[threadIdx.x];
    const float4 b4 = ((const float4*)b)[threadIdx.x];
    const float o0 = d0 * rs * w4.x + b4.x;
    const float o1 = d1 * rs * w4.y + b4.y;
    const float o2 = d2 * rs * w4.z + b4.z;
    const float o3 = d3 * rs * w4.w + b4.w;
    float m = fmaxf(fmaxf(fabsf(o0), fabsf(o1)), fmaxf(fabsf(o2), fabsf(o3)));
    m = blockReduceMax(m);
    m = fmaxf(m, 1e-20f);
    const float s1 = m * (1.0f / 127.0f);
    const float inv1 = 127.0f / m;
    const float inv2 = inv1 * 128.0f;
    const int i0 = qclamp(o0 * inv1), i1 = qclamp(o1 * inv1);
    const int i2 = qclamp(o2 * inv1), i3 = qclamp(o3 * inv1);
    const int j0 = qclamp((o0 - i0 * s1) * inv2);
    const int j1 = qclamp((o1 - i1 * s1) * inv2);
    const int j2 = qclamp((o2 - i2 * s1) * inv2);
    const int j3 = qclamp((o3 - i3 * s1) * inv2);
    const size_t o = (size_t)row * DMODEL + threadIdx.x * 4;
    *(uint32_t*)(q1 + o) = pack4(i0, i1, i2, i3);
    *(uint32_t*)(q2 + o) = pack4(j0, j1, j2, j3);
    if (threadIdx.x == 0) scale[row] = s1;
}

// ---------------- int8 2-level mma GEMM (spill-free tiling) ---------------------
// C[M,N] = sA[m]*sB[n]*(a1b1 + (a1b2+a2b1)/128), fp32 epilogue.
// CTA 128x64, warp tile 32x32 (8 warps). k-chunk 128 int8. 2-stage cp.async.
enum { EPI_NONE = 0, EPI_RES = 1, EPI_GELU = 2 };

#define STAGE_BYTES 49152                  // A1,A2: 16KB each; B1,B2: 8KB each
#define GEMM_SMEM_BYTES (2*STAGE_BYTES)    // 98304

template<int EPI>
__global__ __launch_bounds__(256) void gemm_q8_kernel(
    const int8_t* __restrict__ A1, const int8_t* __restrict__ A2,
    const float* __restrict__ sA,
    const int8_t* __restrict__ B1, const int8_t* __restrict__ B2,
    const float* __restrict__ sB,
    const float* __restrict__ bias, const float* __restrict__ res,
    float* __restrict__ C, int M, int N, int K)
{
    extern __shared__ __align__(1024) char smem[];
    const uint32_t sb = smem_u32(smem);
    const int tid = threadIdx.x, lane = tid & 31, wid = tid >> 5;
    const int wm = wid >> 1, wn = wid & 1;              // warp tile (wm*32, wn*32)
    const int bm = blockIdx.y * 128, bn = blockIdx.x * 64;

    int acc11[2][4][4], accmx[2][4][4];
    #pragma unroll
    for (int mt = 0; mt < 2; mt++)
        #pragma unroll
        for (int nt = 0; nt < 4; nt++)
            #pragma unroll
            for (int i = 0; i < 4; i++) { acc11[mt][nt][i] = 0; accmx[mt][nt][i] = 0; }

    // fill stage s with k-chunk kt (128 int8): A 128 rows, B 64 rows, 128B each
    auto fill = [&](int s, int kt) {
        char* st = smem + s * STAGE_BYTES;
        const int k0 = kt << 7;
        #pragma unroll
        for (int i = 0; i < 4; i++) {                   // A: 1024 cp16 per array
            const int idx = tid + i * 256;
            const int row = idx >> 3, c16 = idx & 7;
            const uint32_t sw = SWZ128((uint32_t)((row << 7) + (c16 << 4)));
            const size_t ga = (size_t)(bm + row) * K + k0 + c16 * 16;
            cp16(st + sw,         A1 + ga);
            cp16(st + 16384 + sw, A2 + ga);
        }
        #pragma unroll
        for (int i = 0; i < 2; i++) {                   // B: 512 cp16 per array
            const int idx = tid + i * 256;
            const int row = idx >> 3, c16 = idx & 7;    // row 0..63
            const uint32_t sw = SWZ128((uint32_t)((row << 7) + (c16 << 4)));
            const size_t gb = (size_t)(bn + row) * K + k0 + c16 * 16;
            cp16(st + 32768 + sw, B1 + gb);
            cp16(st + 40960 + sw, B2 + gb);
        }
    };

    // per-lane ldmatrix address components (validated in R9/R11)
    const int laneRA = lane & 15;
    const int laneCA = (lane >> 4) << 4;
    const int laneRB = (lane & 7) + ((lane >> 4) << 3);
    const int laneCB = ((lane >> 3) & 1) << 4;

    const int niter = K >> 7;
    fill(0, 0); CP_COMMIT();

    for (int it = 0; it < niter; it++) {
        const int s = it & 1;
        if (it + 1 < niter) {
            fill(s ^ 1, it + 1); CP_COMMIT();
            asm volatile("cp.async.wait_group 1;" ::: "memory");
        } else {
            asm volatile("cp.async.wait_group 0;" ::: "memory");
        }
        __syncthreads();

        const uint32_t a1b = sb + s * STAGE_BYTES;
        const uint32_t a2b = a1b + 16384;
        const uint32_t b1b = a1b + 32768;
        const uint32_t b2b = a1b + 40960;

        #pragma unroll
        for (int ks = 0; ks < 4; ks++) {                // 4 x k32 per 128B chunk
            const int kb = ks * 32;
            uint32_t a1[2][4], a2[2][4], b1[4][2], b2[4][2];
            #pragma unroll
            for (int mt = 0; mt < 2; mt++) {
                const uint32_t off = SWZ128(
                    (uint32_t)(((wm * 32 + mt * 16 + laneRA) << 7) + kb + laneCA));
                ldsm4(a1[mt], a1b + off);
                ldsm4(a2[mt], a2b + off);
            }
            #pragma unroll
            for (int j = 0; j < 2; j++) {
                const uint32_t off = SWZ128(
                    (uint32_t)(((wn * 32 + j * 16 + laneRB) << 7) + kb + laneCB));
                ldsm4(&b1[j * 2][0], b1b + off);
                ldsm4(&b2[j * 2][0], b2b + off);
            }
            #pragma unroll
            for (int mt = 0; mt < 2; mt++)
                #pragma unroll
                for (int nt = 0; nt < 4; nt++) imma16832(acc11[mt][nt], a1[mt], b1[nt]);
            #pragma unroll
            for (int mt = 0; mt < 2; mt++)
                #pragma unroll
                for (int nt = 0; nt < 4; nt++) imma16832(accmx[mt][nt], a1[mt], b2[nt]);
            #pragma unroll
            for (int mt = 0; mt < 2; mt++)
                #pragma unroll
                for (int nt = 0; nt < 4; nt++) imma16832(accmx[mt][nt], a2[mt], b1[nt]);
        }
        __syncthreads();
    }

    // ---- epilogue: dequant + bias + (gelu | residual) ----
    const int g = lane >> 2, t = lane & 3;
    #pragma unroll
    for (int mt = 0; mt < 2; mt++) {
        #pragma unroll
        for (int nt = 0; nt < 4; nt++) {
            const int col = bn + wn * 32 + nt * 8 + 2 * t;
            const float sb0 = sB[col], sb1 = sB[col + 1];
            #pragma unroll
            for (int half = 0; half < 2; half++) {
                const int row = bm + wm * 32 + mt * 16 + g + half * 8;
                const float sa = sA[row];
                float v0 = sa * sb0 * ((float)acc11[mt][nt][2*half+0]
                                       + 0.0078125f * (float)accmx[mt][nt][2*half+0]);
                float v1 = sa * sb1 * ((float)acc11[mt][nt][2*half+1]
                                       + 0.0078125f * (float)accmx[mt][nt][2*half+1]);
                if (bias) { v0 += bias[col]; v1 += bias[col + 1]; }
                if (EPI == EPI_GELU) {
                    v0 = 0.5f * v0 * (1.0f + erff(v0 * 0.70710678118654752f));
                    v1 = 0.5f * v1 * (1.0f + erff(v1 * 0.70710678118654752f));
                }
                const size_t o = (size_t)row * N + col;
                if (EPI == EPI_RES) {
                    const float2 r2 = *(const float2*)(res + o);
                    v0 += r2.x; v1 += r2.y;
                }
                *(float2*)(C + o) = make_float2(v0, v1);
            }
        }
    }
}

// ---------------- causal flash attention (fp32 in/out, 128 queries/block) --------
__global__ __launch_bounds__(128) void attn_kernel(
    const float* __restrict__ qkv, float* __restrict__ out)
{
    const int qt = blockIdx.x, h = blockIdx.y, b = blockIdx.z;
    const int tid = threadIdx.x;
    const int qg = qt * 128 + tid;
    const size_t mrow = (size_t)b * SEQ + qg;

    __shared__ float Ks[32][64];
    __shared__ float Vs[32][64];
    __shared__ float Sp[32][128];

    float qreg[64];
    {
        const float4* qp = (const float4*)(qkv + mrow * (3 * DMODEL) + h * HEADDIM);
        #pragma unroll
        for (int i = 0; i < 16; i++) {
            const float4 t4 = qp[i];
            qreg[4*i+0] = t4.x; qreg[4*i+1] = t4.y; qreg[4*i+2] = t4.z; qreg[4*i+3] = t4.w;
        }
    }

    float acc[64];
    #pragma unroll
    for (int d = 0; d < 64; d++) acc[d] = 0.0f;
    float m_i = -INFINITY, l_i = 0.0f;
    const float scale = 0.125f;

    const float* kbase = qkv + (size_t)b * SEQ * (3 * DMODEL) + DMODEL     + h * HEADDIM;
    const float* vbase = qkv + (size_t)b * SEQ * (3 * DMODEL) + 2 * DMODEL + h * HEADDIM;

    const int nkt = 4 * qt + 4;
    for (int kt = 0; kt < nkt; kt++) {
        {
            const int r0 = tid >> 4;
            const int c4 = tid & 15;
            #pragma unroll
            for (int it2 = 0; it2 < 4; it2++) {
                const int r = it2 * 8 + r0;
                const size_t roff = (size_t)(kt * 32 + r) * (3 * DMODEL);
                *(float4*)&Ks[r][c4 * 4] = *(const float4*)(kbase + roff + c4 * 4);
                *(float4*)&Vs[r][c4 * 4] = *(const float4*)(vbase + roff + c4 * 4);
            }
        }
        __syncthreads();

        const int kg0 = kt * 32;
        float tmax = -INFINITY;
        #pragma unroll 2
        for (int j = 0; j < 32; j++) {
            float s = 0.0f;
            const float4* kr = (const float4*)Ks[j];
            #pragma unroll
            for (int i = 0; i < 16; i++) {
                const float4 kf = kr[i];
                s += qreg[4*i+0]*kf.x + qreg[4*i+1]*kf.y + qreg[4*i+2]*kf.z + qreg[4*i+3]*kf.w;
            }
            s *= scale;
            s = (kg0 + j <= qg) ? s : -INFINITY;
            Sp[j][tid] = s;
            tmax = fmaxf(tmax, s);
        }

        const float mnew = fmaxf(m_i, tmax);
        const float corr = expf(m_i - mnew);
        #pragma unroll
        for (int d = 0; d < 64; d++) acc[d] *= corr;

        float lsum = 0.0f;
        #pragma unroll 2
        for (int j = 0; j < 32; j++) {
            const float e = expf(Sp[j][tid] - mnew);
            lsum += e;
            const float4* vr = (const float4*)Vs[j];
            #pragma unroll
            for (int i = 0; i < 16; i++) {
                const float4 vf = vr[i];
                acc[4*i+0] += e * vf.x; acc[4*i+1] += e * vf.y;
                acc[4*i+2] += e * vf.z; acc[4*i+3] += e * vf.w;
            }
        }
        l_i = l_i * corr + lsum;
        m_i = mnew;
        __syncthreads();
    }

    const float inv = 1.0f / l_i;
    float4* op = (float4*)(out + mrow * DMODEL + h * HEADDIM);
    #pragma unroll
    for (int i = 0; i < 16; i++)
        op[i] = make_float4(acc[4*i+0]*inv, acc[4*i+1]*inv, acc[4*i+2]*inv, acc[4*i+3]*inv);
}

// ---------------- loss ----------------
__global__ __launch_bounds__(256) void loss_token_kernel(
    const float* __restrict__ logits, const int* __restrict__ targets,
    const void* __restrict__ vmask,
    float* __restrict__ tce, float* __restrict__ tw)
{
    const int row = blockIdx.x;
    const float* lr = logits + (size_t)row * VOCAB;
    float v[16];
    #pragma unroll
    for (int i = 0; i < 16; i++) v[i] = lr[threadIdx.x + 256 * i];
    float mx = v[0];
    #pragma unroll
    for (int i = 1; i < 16; i++) mx = fmaxf(mx, v[i]);
    mx = blockReduceMax(mx);
    float se = 0.0f;
    #pragma unroll
    for (int i = 0; i < 16; i++) se += expf(v[i] - mx);
    se = blockReduceSum(se);
    if (threadIdx.x == 0) {
        const int tgt = targets[row];
        const float lse = mx + logf(se);
        const float nll = lse - lr[tgt];
        int mv;
        if (g_mflag) mv = ((const unsigned char*)vmask)[row];
        else         mv = ((const int*)vmask)[row];
        const float w = 1.0f + 4.0f * ((mv != 0) ? 1.0f : 0.0f);
        tce[row] = (tgt == 0) ? 0.0f : nll * w;
        tw[row]  = w;
    }
}

__global__ __launch_bounds__(256) void loss_final_kernel(
    const float* __restrict__ tce, const float* __restrict__ tw, float* __restrict__ out)
{
    float a = 0.0f, b = 0.0f;
    for (int i = threadIdx.x; i < MTOK; i += 256) { a += tce[i]; b += tw[i]; }
    a = blockReduceSum(a);
    b = blockReduceSum(b);
    if (threadIdx.x == 0) out[0] = a / b;
}

// ---------------- host driver ----------------
extern "C" void kernel_launch(void* const* d_in, const int* in_sizes, int n_in,
                              void* d_out, int out_size)
{
    (void)in_sizes; (void)n_in;
    const int*   ids   = (const int*)d_in[0];
    const int*   tgts  = (const int*)d_in[1];
    const void*  vmask = (const void*)d_in[2];
    const float* tok   = (const float*)d_in[3];
    const float* pos   = (const float*)d_in[4];
    const float* ln1w  = (const float*)d_in[5];
    const float* ln1b  = (const float*)d_in[6];
    const float* wqkv  = (const float*)d_in[7];
    const float* bqkv  = (const float*)d_in[8];
    const float* wproj = (const float*)d_in[9];
    const float* bproj = (const float*)d_in[10];
    const float* ln2w  = (const float*)d_in[11];
    const float* ln2b  = (const float*)d_in[12];
    const float* w1    = (const float*)d_in[13];
    const float* b1    = (const float*)d_in[14];
    const float* w2    = (const float*)d_in[15];
    const float* b2    = (const float*)d_in[16];
    const float* lnfw  = (const float*)d_in[17];
    const float* lnfb  = (const float*)d_in[18];
    float* out = (float*)d_out;

    float *x, *qkv, *att, *mid, *tce, *tw, *sh, *sm;
    float *sbq, *sbp, *sb1, *sb2, *st;
    int8_t *hq1, *hq2, *mq1, *mq2;
    int8_t *wqq1, *wqq2, *wpq1, *wpq2, *w1q1, *w1q2, *w2q1, *w2q2, *tq1, *tq2;
    cudaGetSymbolAddress((void**)&x,    g_x);
    cudaGetSymbolAddress((void**)&qkv,  g_qkv);
    cudaGetSymbolAddress((void**)&att,  g_att);
    cudaGetSymbolAddress((void**)&mid,  g_mid);
    cudaGetSymbolAddress((void**)&hq1,  g_hq1);
    cudaGetSymbolAddress((void**)&hq2,  g_hq2);
    cudaGetSymbolAddress((void**)&sh,   g_sh);
    cudaGetSymbolAddress((void**)&mq1,  g_mq1);
    cudaGetSymbolAddress((void**)&mq2,  g_mq2);
    cudaGetSymbolAddress((void**)&sm,   g_sm);
    cudaGetSymbolAddress((void**)&wqq1, g_wq_q1);
    cudaGetSymbolAddress((void**)&wqq2, g_wq_q2);
    cudaGetSymbolAddress((void**)&wpq1, g_wp_q1);
    cudaGetSymbolAddress((void**)&wpq2, g_wp_q2);
    cudaGetSymbolAddress((void**)&w1q1, g_w1_q1);
    cudaGetSymbolAddress((void**)&w1q2, g_w1_q2);
    cudaGetSymbolAddress((void**)&w2q1, g_w2_q1);
    cudaGetSymbolAddress((void**)&w2q2, g_w2_q2);
    cudaGetSymbolAddress((void**)&tq1,  g_tq1);
    cudaGetSymbolAddress((void**)&tq2,  g_tq2);
    cudaGetSymbolAddress((void**)&sbq,  g_sbq);
    cudaGetSymbolAddress((void**)&sbp,  g_sbp);
    cudaGetSymbolAddress((void**)&sb1,  g_sb1);
    cudaGetSymbolAddress((void**)&sb2,  g_sb2);
    cudaGetSymbolAddress((void**)&st,   g_st);
    cudaGetSymbolAddress((void**)&tce,  g_tce);
    cudaGetSymbolAddress((void**)&tw,   g_tw);

    cudaFuncSetAttribute(gemm_q8_kernel<EPI_NONE>,
                         cudaFuncAttributeMaxDynamicSharedMemorySize, GEMM_SMEM_BYTES);
    cudaFuncSetAttribute(gemm_q8_kernel<EPI_RES>,
                         cudaFuncAttributeMaxDynamicSharedMemorySize, GEMM_SMEM_BYTES);
    cudaFuncSetAttribute(gemm_q8_kernel<EPI_GELU>,
                         cudaFuncAttributeMaxDynamicSharedMemorySize, GEMM_SMEM_BYTES);

    // ---- weight quantization (fused scale+quant; per replay) ----
    convw_q8f<<<dim3(3*DMODEL/32, NLAYER), 256>>>(wqkv,  sbq, wqq1, wqq2, DMODEL, 3*DMODEL);
    convw_q8f<<<dim3(DMODEL/32,   NLAYER), 256>>>(wproj, sbp, wpq1, wpq2, DMODEL, DMODEL);
    convw_q8f<<<dim3(DFF/32,      NLAYER), 256>>>(w1,    sb1, w1q1, w1q2, DMODEL, DFF);
    convw_q8f<<<dim3(DMODEL/32,   NLAYER), 256>>>(w2,    sb2, w2q1, w2q2, DFF,    DMODEL);
    // lm_head: tok already [V][K] row-major -> per-row quant, no transpose
    quant_rows_kernel<<<VOCAB, 256>>>(tok, tq1, tq2, st, DMODEL);

    detect_mask_kernel<<<1, 256>>>((const unsigned char*)vmask);
    embed_kernel<<<MTOK, 256>>>(ids, tok, pos, x);

    const size_t wq_s = (size_t)3*DMODEL*DMODEL;
    const size_t wp_s = (size_t)DMODEL*DMODEL;
    const size_t w1_s = (size_t)DFF*DMODEL;
    const size_t w2_s = (size_t)DMODEL*DFF;

    for (int l = 0; l < NLAYER; l++) {
        ln_q8_kernel<<<MTOK, 256>>>(x, ln1w + l*DMODEL, ln1b + l*DMODEL, hq1, hq2, sh);

        gemm_q8_kernel<EPI_NONE><<<dim3(3*DMODEL/64, MTOK/128), 256, GEMM_SMEM_BYTES>>>(
            hq1, hq2, sh, wqq1 + l*wq_s, wqq2 + l*wq_s, sbq + (size_t)l*3*DMODEL,
            bqkv + (size_t)l*3*DMODEL, nullptr, qkv, MTOK, 3*DMODEL, DMODEL);

        attn_kernel<<<dim3(SEQ/128, NHEAD, BATCH), 128>>>(qkv, att);
        quant_rows_kernel<<<MTOK, 256>>>(att, hq1, hq2, sh, DMODEL);

        gemm_q8_kernel<EPI_RES><<<dim3(DMODEL/64, MTOK/128), 256, GEMM_SMEM_BYTES>>>(
            hq1, hq2, sh, wpq1 + l*wp_s, wpq2 + l*wp_s, sbp + (size_t)l*DMODEL,
            bproj + (size_t)l*DMODEL, x, x, MTOK, DMODEL, DMODEL);

        ln_q8_kernel<<<MTOK, 256>>>(x, ln2w + l*DMODEL, ln2b + l*DMODEL, hq1, hq2, sh);

        gemm_q8_kernel<EPI_GELU><<<dim3(DFF/64, MTOK/128), 256, GEMM_SMEM_BYTES>>>(
            hq1, hq2, sh, w1q1 + l*w1_s, w1q2 + l*w1_s, sb1 + (size_t)l*DFF,
            b1 + (size_t)l*DFF, nullptr, mid, MTOK, DFF, DMODEL);

        quant_rows_kernel<<<MTOK, 256>>>(mid, mq1, mq2, sm, DFF);

        gemm_q8_kernel<EPI_RES><<<dim3(DMODEL/64, MTOK/128), 256, GEMM_SMEM_BYTES>>>(
            mq1, mq2, sm, w2q1 + l*w2_s, w2q2 + l*w2_s, sb2 + (size_t)l*DMODEL,
            b2 + (size_t)l*DMODEL, x, x, MTOK, DMODEL, DFF);
    }

    ln_q8_kernel<<<MTOK, 256>>>(x, lnfw, lnfb, hq1, hq2, sh);

    gemm_q8_kernel<EPI_NONE><<<dim3(VOCAB/64, MTOK/128), 256, GEMM_SMEM_BYTES>>>(
        hq1, hq2, sh, tq1, tq2, st, nullptr, nullptr, out, MTOK, VOCAB, DMODEL);

    if (out_size > MTOK * VOCAB) {
        loss_token_kernel<<<MTOK, 256>>>(out, tgts, vmask, tce, tw);
        loss_final_kernel<<<1, 256>>>(tce, tw, out + (size_t)MTOK * VOCAB);
    }
}

// round 13
// speedup vs baseline: 2.0909x; 1.9437x over previous
#include <cuda_runtime.h>
#include <cuda_bf16.h>
#include <math.h>
#include <stdint.h>

// ---------------- problem constants ----------------
#define NLAYER   8
#define DMODEL   1024
#define NHEAD    16
#define HEADDIM  64
#define DFF      4096
#define VOCAB    4096
#define BATCH    4
#define SEQ      2048
#define MTOK     (BATCH*SEQ)      // 8192 tokens

// ---------------- scratch (device globals; no allocation allowed) ----------------
__device__ float g_x  [MTOK*DMODEL];       // residual stream (fp32)
__device__ float g_qkv[MTOK*3*DMODEL];     // qkv (fp32, attention input)
__device__ __nv_bfloat16 g_hhi[MTOK*DMODEL];
__device__ __nv_bfloat16 g_hlo[MTOK*DMODEL];
__device__ __nv_bfloat16 g_mhi[MTOK*DFF];
__device__ __nv_bfloat16 g_mlo[MTOK*DFF];
// split weights, N-major [L][N][K] bf16 (B^T layout; TN gemm via ldmatrix)
__device__ __nv_bfloat16 g_wqkv_hi[NLAYER*3*DMODEL*DMODEL];
__device__ __nv_bfloat16 g_wqkv_lo[NLAYER*3*DMODEL*DMODEL];
__device__ __nv_bfloat16 g_wproj_hi[NLAYER*DMODEL*DMODEL];
__device__ __nv_bfloat16 g_wproj_lo[NLAYER*DMODEL*DMODEL];
__device__ __nv_bfloat16 g_w1_hi[NLAYER*DFF*DMODEL];
__device__ __nv_bfloat16 g_w1_lo[NLAYER*DFF*DMODEL];
__device__ __nv_bfloat16 g_w2_hi[NLAYER*DMODEL*DFF];
__device__ __nv_bfloat16 g_w2_lo[NLAYER*DMODEL*DFF];
__device__ __nv_bfloat16 g_lmh_hi[VOCAB*DMODEL];
__device__ __nv_bfloat16 g_lmh_lo[VOCAB*DMODEL];
__device__ float g_tce[MTOK];
__device__ float g_tw [MTOK];
__device__ int   g_mflag;

// ---------------- block reductions ----------------
__device__ __forceinline__ float blockReduceSum(float val) {
    __shared__ float sh[32];
    const int lane = threadIdx.x & 31, wid = threadIdx.x >> 5;
    #pragma unroll
    for (int o = 16; o; o >>= 1) val += __shfl_xor_sync(0xffffffffu, val, o);
    if (lane == 0) sh[wid] = val;
    __syncthreads();
    const int nw = (blockDim.x + 31) >> 5;
    float t = (threadIdx.x < nw) ? sh[threadIdx.x] : 0.0f;
    #pragma unroll
    for (int o = 16; o; o >>= 1) t += __shfl_xor_sync(0xffffffffu, t, o);
    if (threadIdx.x == 0) sh[0] = t;
    __syncthreads();
    t = sh[0];
    __syncthreads();
    return t;
}

__device__ __forceinline__ float blockReduceMax(float val) {
    __shared__ float sh[32];
    const int lane = threadIdx.x & 31, wid = threadIdx.x >> 5;
    #pragma unroll
    for (int o = 16; o; o >>= 1) val = fmaxf(val, __shfl_xor_sync(0xffffffffu, val, o));
    if (lane == 0) sh[wid] = val;
    __syncthreads();
    const int nw = (blockDim.x + 31) >> 5;
    float t = (threadIdx.x < nw) ? sh[threadIdx.x] : -INFINITY;
    #pragma unroll
    for (int o = 16; o; o >>= 1) t = fmaxf(t, __shfl_xor_sync(0xffffffffu, t, o));
    if (threadIdx.x == 0) sh[0] = t;
    __syncthreads();
    t = sh[0];
    __syncthreads();
    return t;
}

// ---------------- helpers ----------------
__device__ __forceinline__ void split_bf16(float a, __nv_bfloat16& hi, __nv_bfloat16& lo) {
    hi = __float2bfloat16(a);
    lo = __float2bfloat16(a - __bfloat162float(hi));
}

__device__ __forceinline__ void cp16(void* sdst, const void* gsrc) {
    uint32_t sa = (uint32_t)__cvta_generic_to_shared(sdst);
    asm volatile("cp.async.cg.shared.global [%0], [%1], 16;" :: "r"(sa), "l"(gsrc));
}
#define CP_COMMIT() asm volatile("cp.async.commit_group;" ::: "memory")

__device__ __forceinline__ uint32_t smem_u32(const void* p) {
    return (uint32_t)__cvta_generic_to_shared(p);
}

#define SWZ128(off) ((off) ^ (((off) >> 3) & 0x70))

__device__ __forceinline__ void mma16816(float* d, const uint32_t* a, const uint32_t* b) {
    asm volatile(
        "mma.sync.aligned.m16n8k16.row.col.f32.bf16.bf16.f32 "
        "{%0,%1,%2,%3}, {%4,%5,%6,%7}, {%8,%9}, {%0,%1,%2,%3};"
        : "+f"(d[0]), "+f"(d[1]), "+f"(d[2]), "+f"(d[3])
        : "r"(a[0]), "r"(a[1]), "r"(a[2]), "r"(a[3]), "r"(b[0]), "r"(b[1]));
}

__device__ __forceinline__ void ldsm4(uint32_t* r, uint32_t addr) {
    asm volatile("ldmatrix.sync.aligned.m8n8.x4.shared.b16 {%0,%1,%2,%3}, [%4];"
                 : "=r"(r[0]), "=r"(r[1]), "=r"(r[2]), "=r"(r[3]) : "r"(addr));
}

// ---------------- weight pack kernels ----------------
// W [K][N] fp32 -> Whi/Wlo bf16 [N][K] (tiled transpose + split)
__global__ __launch_bounds__(256) void convw_nt(
    const float* __restrict__ W, __nv_bfloat16* __restrict__ Whi,
    __nv_bfloat16* __restrict__ Wlo, int K, int N)
{
    __shared__ float tile[32][33];
    const int tx = threadIdx.x & 31, ty = threadIdx.x >> 5;
    const int n0 = blockIdx.x * 32, k0 = blockIdx.y * 32;
    const int l = blockIdx.z;
    const float* Wl = W + (size_t)l * K * N;
    #pragma unroll
    for (int i = ty; i < 32; i += 8)
        tile[i][tx] = Wl[(size_t)(k0 + i) * N + n0 + tx];
    __syncthreads();
    __nv_bfloat16* Hl = Whi + (size_t)l * N * K;
    __nv_bfloat16* Ll = Wlo + (size_t)l * N * K;
    #pragma unroll
    for (int i = ty; i < 32; i += 8) {
        __nv_bfloat16 h, lo;
        split_bf16(tile[tx][i], h, lo);   // = W[k0+tx][n0+i]
        Hl[(size_t)(n0 + i) * K + k0 + tx] = h;
        Ll[(size_t)(n0 + i) * K + k0 + tx] = lo;
    }
}

// elementwise split (lm_head: tok already [V][K])
__global__ __launch_bounds__(256) void convsplit(
    const float* __restrict__ W, __nv_bfloat16* __restrict__ hi, __nv_bfloat16* __restrict__ lo)
{
    const int i = blockIdx.x * 256 + threadIdx.x;
    __nv_bfloat16 h, l;
    split_bf16(W[i], h, l);
    hi[i] = h; lo[i] = l;
}

// ---------------- value_mask dtype probe ----------------
__global__ __launch_bounds__(256) void detect_mask_kernel(const unsigned char* __restrict__ m)
{
    __shared__ int sh[32];
    int s = 0;
    for (int i = threadIdx.x; i < 8192; i += 256)
        if (i & 3) s += m[i];
    #pragma unroll
    for (int o = 16; o; o >>= 1) s += __shfl_xor_sync(0xffffffffu, s, o);
    const int lane = threadIdx.x & 31, wid = threadIdx.x >> 5;
    if (lane == 0) sh[wid] = s;
    __syncthreads();
    if (threadIdx.x < 8) {
        int t = sh[threadIdx.x];
        #pragma unroll
        for (int o = 4; o; o >>= 1) t += __shfl_xor_sync(0xffu, t, o);
        if (threadIdx.x == 0) g_mflag = (t != 0) ? 1 : 0;
    }
}

// ---------------- embed ----------------
__global__ __launch_bounds__(256) void embed_kernel(
    const int* __restrict__ ids, const float* __restrict__ tok,
    const float* __restrict__ pos, float* __restrict__ x)
{
    const int m = blockIdx.x;
    const int t = m & (SEQ - 1);
    const int id = ids[m];
    const float4 a = ((const float4*)(tok + (size_t)id * DMODEL))[threadIdx.x];
    const float4 b = ((const float4*)(pos + (size_t)t  * DMODEL))[threadIdx.x];
    ((float4*)(x + (size_t)m * DMODEL))[threadIdx.x] =
        make_float4(a.x + b.x, a.y + b.y, a.z + b.z, a.w + b.w);
}

// ---------------- layernorm -> split bf16 ----------------
__global__ __launch_bounds__(256) void ln_bf16_kernel(
    const float* __restrict__ x, const float* __restrict__ w,
    const float* __restrict__ b, __nv_bfloat16* __restrict__ yhi,
    __nv_bfloat16* __restrict__ ylo)
{
    const int row = blockIdx.x;
    const float4 v = ((const float4*)(x + (size_t)row * DMODEL))[threadIdx.x];
    float s = v.x + v.y + v.z + v.w;
    s = blockReduceSum(s);
    const float mu = s * (1.0f / DMODEL);
    const float d0 = v.x - mu, d1 = v.y - mu, d2 = v.z - mu, d3 = v.w - mu;
    float q = d0*d0 + d1*d1 + d2*d2 + d3*d3;
    q = blockReduceSum(q);
    const float rs = rsqrtf(q * (1.0f / DMODEL) + 1e-5f);
    const float4 w4 = ((const float4*)w)[threadIdx.x];
    const float4 b4 = ((const float4*)b)[threadIdx.x];
    float o0 = d0 * rs * w4.x + b4.x;
    float o1 = d1 * rs * w4.y + b4.y;
    float o2 = d2 * rs * w4.z + b4.z;
    float o3 = d3 * rs * w4.w + b4.w;
    __nv_bfloat16 h0,l0,h1,l1,h2,l2,h3,l3;
    split_bf16(o0,h0,l0); split_bf16(o1,h1,l1); split_bf16(o2,h2,l2); split_bf16(o3,h3,l3);
    const size_t base = (size_t)row * DMODEL + threadIdx.x * 4;
    *(__nv_bfloat162*)(yhi + base)     = __halves2bfloat162(h0, h1);
    *(__nv_bfloat162*)(yhi + base + 2) = __halves2bfloat162(h2, h3);
    *(__nv_bfloat162*)(ylo + base)     = __halves2bfloat162(l0, l1);
    *(__nv_bfloat162*)(ylo + base + 2) = __halves2bfloat162(l2, l3);
}

// ---------------- split-bf16 mma GEMM: 2-CTA/SM geometry ------------------------
// C[M,N] = (Ahi+Alo)[M][K] @ (Bhi+Blo)[N][K]^T, fp32 accum, 3 products.
// CTA 128x64, warp tile 32x32 (8 warps = 4x2). BK=64. 2-stage cp.async.
// smem/stage: Ah,Al 16KB each + Bh,Bl 8KB each = 48KB; 2 stages = 96KB -> 2 CTAs/SM.
// Regs ~100/thread (launch_bounds cap 128) -> 2 CTAs/SM by regs too.
enum { EPI_NONE = 0, EPI_RES = 1, EPI_GELU = 2 };

#define STAGE_BYTES 49152
#define GEMM_SMEM_BYTES (2*STAGE_BYTES)   // 98304

template<int EPI>
__global__ __launch_bounds__(256, 2) void gemm_ldsm_kernel(
    const __nv_bfloat16* __restrict__ Ahi, const __nv_bfloat16* __restrict__ Alo,
    const __nv_bfloat16* __restrict__ Bhi, const __nv_bfloat16* __restrict__ Blo,
    const float* __restrict__ bias, const float* __restrict__ res,
    float* __restrict__ C, __nv_bfloat16* __restrict__ Chi, __nv_bfloat16* __restrict__ Clo,
    int M, int N, int K)
{
    extern __shared__ __align__(1024) char smem[];
    const uint32_t sb = smem_u32(smem);
    const int tid = threadIdx.x, lane = tid & 31, wid = tid >> 5;
    const int wm = wid >> 1, wn = wid & 1;              // warp tile (wm*32, wn*32)
    const int bm = blockIdx.y * 128, bn = blockIdx.x * 64;

    float acc[2][4][4];
    #pragma unroll
    for (int mt = 0; mt < 2; mt++)
        #pragma unroll
        for (int nt = 0; nt < 4; nt++)
            #pragma unroll
            for (int i = 0; i < 4; i++) acc[mt][nt][i] = 0.0f;

    // fill stage s with k-atom kt (64 k elems): A 128 rows x 128B, B 64 rows x 128B
    auto fill = [&](int s, int kt) {
        char* st = smem + s * STAGE_BYTES;
        const int k0 = kt << 6;
        #pragma unroll
        for (int i = 0; i < 4; i++) {                   // A hi/lo: 1024 rows*slots
            const int idx = tid + i * 256;              // 0..1023
            const int row = idx >> 3, c16 = idx & 7;
            const uint32_t sw = SWZ128((uint32_t)((row << 7) + (c16 << 4)));
            const size_t ga = (size_t)(bm + row) * K + k0 + c16 * 8;
            cp16(st + sw,         Ahi + ga);
            cp16(st + 16384 + sw, Alo + ga);
        }
        #pragma unroll
        for (int i = 0; i < 2; i++) {                   // B hi/lo: 512 rows*slots
            const int idx = tid + i * 256;              // 0..511
            const int row = idx >> 3, c16 = idx & 7;    // row 0..63
            const uint32_t sw = SWZ128((uint32_t)((row << 7) + (c16 << 4)));
            const size_t gb = (size_t)(bn + row) * K + k0 + c16 * 8;
            cp16(st + 32768 + sw, Bhi + gb);
            cp16(st + 40960 + sw, Blo + gb);
        }
    };

    // per-lane ldmatrix address components (validated R9)
    const int laneRA = lane & 15;                       // A: row within m16
    const int laneCA = (lane >> 4) << 4;                // A: +16B for k-hi half
    const int laneRB = (lane & 7) + ((lane >> 4) << 3); // B: row within n16
    const int laneCB = ((lane >> 3) & 1) << 4;          // B: +16B for k-hi half

    const int niter = K >> 6;
    fill(0, 0); CP_COMMIT();

    for (int it = 0; it < niter; it++) {
        const int s = it & 1;
        if (it + 1 < niter) {
            fill(s ^ 1, it + 1); CP_COMMIT();
            asm volatile("cp.async.wait_group 1;" ::: "memory");
        } else {
            asm volatile("cp.async.wait_group 0;" ::: "memory");
        }
        __syncthreads();

        const uint32_t aH = sb + s * STAGE_BYTES;
        const uint32_t aL = aH + 16384;
        const uint32_t bH = aH + 32768;
        const uint32_t bL = aH + 40960;

        #pragma unroll
        for (int k16 = 0; k16 < 4; k16++) {
            const int kb = k16 * 32;                    // byte offset of this k16
            uint32_t ah[2][4], al[2][4], bh[4][2], bl[4][2];
            #pragma unroll
            for (int mt = 0; mt < 2; mt++) {
                const uint32_t off = SWZ128(
                    (uint32_t)(((wm * 32 + mt * 16 + laneRA) << 7) + kb + laneCA));
                ldsm4(ah[mt], aH + off);
                ldsm4(al[mt], aL + off);
            }
            #pragma unroll
            for (int j = 0; j < 2; j++) {               // two n16 groups -> 4 n8 tiles
                const uint32_t off = SWZ128(
                    (uint32_t)(((wn * 32 + j * 16 + laneRB) << 7) + kb + laneCB));
                ldsm4(&bh[j * 2][0], bH + off);
                ldsm4(&bl[j * 2][0], bL + off);
            }
            // product-major: RAW distance on each acc = 8 HMMAs
            #pragma unroll
            for (int mt = 0; mt < 2; mt++)
                #pragma unroll
                for (int nt = 0; nt < 4; nt++) mma16816(acc[mt][nt], ah[mt], bh[nt]);
            #pragma unroll
            for (int mt = 0; mt < 2; mt++)
                #pragma unroll
                for (int nt = 0; nt < 4; nt++) mma16816(acc[mt][nt], ah[mt], bl[nt]);
            #pragma unroll
            for (int mt = 0; mt < 2; mt++)
                #pragma unroll
                for (int nt = 0; nt < 4; nt++) mma16816(acc[mt][nt], al[mt], bh[nt]);
        }
        __syncthreads();
    }

    // ---- epilogue ----
    const int g = lane >> 2, t = lane & 3;
    #pragma unroll
    for (int mt = 0; mt < 2; mt++) {
        #pragma unroll
        for (int nt = 0; nt < 4; nt++) {
            const int col = bn + wn * 32 + nt * 8 + 2 * t;
            #pragma unroll
            for (int half = 0; half < 2; half++) {
                const int row = bm + wm * 32 + mt * 16 + g + half * 8;
                float v0 = acc[mt][nt][2 * half + 0];
                float v1 = acc[mt][nt][2 * half + 1];
                if (bias) { v0 += bias[col]; v1 += bias[col + 1]; }
                const size_t o = (size_t)row * N + col;
                if (EPI == EPI_GELU) {
                    v0 = 0.5f * v0 * (1.0f + erff(v0 * 0.70710678118654752f));
                    v1 = 0.5f * v1 * (1.0f + erff(v1 * 0.70710678118654752f));
                    __nv_bfloat16 h0, l0, h1, l1;
                    split_bf16(v0, h0, l0);
                    split_bf16(v1, h1, l1);
                    *(__nv_bfloat162*)(Chi + o) = __halves2bfloat162(h0, h1);
                    *(__nv_bfloat162*)(Clo + o) = __halves2bfloat162(l0, l1);
                } else {
                    if (EPI == EPI_RES) {
                        const float2 r2 = *(const float2*)(res + o);
                        v0 += r2.x; v1 += r2.y;
                    }
                    *(float2*)(C + o) = make_float2(v0, v1);
                }
            }
        }
    }
}

// ---------------- causal flash attention (fp32, 128 queries/block) ----------------
__global__ __launch_bounds__(128) void attn_kernel(
    const float* __restrict__ qkv,
    __nv_bfloat16* __restrict__ ohi, __nv_bfloat16* __restrict__ olo)
{
    const int qt = blockIdx.x, h = blockIdx.y, b = blockIdx.z;
    const int tid = threadIdx.x;
    const int qg = qt * 128 + tid;
    const size_t mrow = (size_t)b * SEQ + qg;

    __shared__ float Ks[32][64];
    __shared__ float Vs[32][64];
    __shared__ float Sp[32][128];

    float qreg[64];
    {
        const float4* qp = (const float4*)(qkv + mrow * (3 * DMODEL) + h * HEADDIM);
        #pragma unroll
        for (int i = 0; i < 16; i++) {
            const float4 t4 = qp[i];
            qreg[4*i+0] = t4.x; qreg[4*i+1] = t4.y; qreg[4*i+2] = t4.z; qreg[4*i+3] = t4.w;
        }
    }

    float acc[64];
    #pragma unroll
    for (int d = 0; d < 64; d++) acc[d] = 0.0f;
    float m_i = -INFINITY, l_i = 0.0f;
    const float scale = 0.125f;

    const float* kbase = qkv + (size_t)b * SEQ * (3 * DMODEL) + DMODEL     + h * HEADDIM;
    const float* vbase = qkv + (size_t)b * SEQ * (3 * DMODEL) + 2 * DMODEL + h * HEADDIM;

    const int nkt = 4 * qt + 4;
    for (int kt = 0; kt < nkt; kt++) {
        {
            const int r0 = tid >> 4;
            const int c4 = tid & 15;
            #pragma unroll
            for (int it2 = 0; it2 < 4; it2++) {
                const int r = it2 * 8 + r0;
                const size_t roff = (size_t)(kt * 32 + r) * (3 * DMODEL);
                *(float4*)&Ks[r][c4 * 4] = *(const float4*)(kbase + roff + c4 * 4);
                *(float4*)&Vs[r][c4 * 4] = *(const float4*)(vbase + roff + c4 * 4);
            }
        }
        __syncthreads();

        const int kg0 = kt * 32;
        float tmax = -INFINITY;
        #pragma unroll 2
        for (int j = 0; j < 32; j++) {
            float s = 0.0f;
            const float4* kr = (const float4*)Ks[j];
            #pragma unroll
            for (int i = 0; i < 16; i++) {
                const float4 kf = kr[i];
                s += qreg[4*i+0]*kf.x + qreg[4*i+1]*kf.y + qreg[4*i+2]*kf.z + qreg[4*i+3]*kf.w;
            }
            s *= scale;
            s = (kg0 + j <= qg) ? s : -INFINITY;
            Sp[j][tid] = s;
            tmax = fmaxf(tmax, s);
        }

        const float mnew = fmaxf(m_i, tmax);
        const float corr = expf(m_i - mnew);
        #pragma unroll
        for (int d = 0; d < 64; d++) acc[d] *= corr;

        float lsum = 0.0f;
        #pragma unroll 2
        for (int j = 0; j < 32; j++) {
            const float e = expf(Sp[j][tid] - mnew);
            lsum += e;
            const float4* vr = (const float4*)Vs[j];
            #pragma unroll
            for (int i = 0; i < 16; i++) {
                const float4 vf = vr[i];
                acc[4*i+0] += e * vf.x; acc[4*i+1] += e * vf.y;
                acc[4*i+2] += e * vf.z; acc[4*i+3] += e * vf.w;
            }
        }
        l_i = l_i * corr + lsum;
        m_i = mnew;
        __syncthreads();
    }

    const float inv = 1.0f / l_i;
    const size_t obase = mrow * DMODEL + h * HEADDIM;
    #pragma unroll
    for (int i = 0; i < 16; i++) {
        const float v0 = acc[4*i+0]*inv, v1 = acc[4*i+1]*inv;
        const float v2 = acc[4*i+2]*inv, v3 = acc[4*i+3]*inv;
        __nv_bfloat16 h0,l0,h1,l1,h2,l2,h3,l3;
        split_bf16(v0,h0,l0); split_bf16(v1,h1,l1); split_bf16(v2,h2,l2); split_bf16(v3,h3,l3);
        *(__nv_bfloat162*)(ohi + obase + 4*i)     = __halves2bfloat162(h0, h1);
        *(__nv_bfloat162*)(ohi + obase + 4*i + 2) = __halves2bfloat162(h2, h3);
        *(__nv_bfloat162*)(olo + obase + 4*i)     = __halves2bfloat162(l0, l1);
        *(__nv_bfloat162*)(olo + obase + 4*i + 2) = __halves2bfloat162(l2, l3);
    }
}

// ---------------- loss ----------------
__global__ __launch_bounds__(256) void loss_token_kernel(
    const float* __restrict__ logits, const int* __restrict__ targets,
    const void* __restrict__ vmask,
    float* __restrict__ tce, float* __restrict__ tw)
{
    const int row = blockIdx.x;
    const float* lr = logits + (size_t)row * VOCAB;
    float v[16];
    #pragma unroll
    for (int i = 0; i < 16; i++) v[i] = lr[threadIdx.x + 256 * i];
    float mx = v[0];
    #pragma unroll
    for (int i = 1; i < 16; i++) mx = fmaxf(mx, v[i]);
    mx = blockReduceMax(mx);
    float se = 0.0f;
    #pragma unroll
    for (int i = 0; i < 16; i++) se += expf(v[i] - mx);
    se = blockReduceSum(se);
    if (threadIdx.x == 0) {
        const int tgt = targets[row];
        const float lse = mx + logf(se);
        const float nll = lse - lr[tgt];
        int mv;
        if (g_mflag) mv = ((const unsigned char*)vmask)[row];
        else         mv = ((const int*)vmask)[row];
        const float w = 1.0f + 4.0f * ((mv != 0) ? 1.0f : 0.0f);
        tce[row] = (tgt == 0) ? 0.0f : nll * w;
        tw[row]  = w;
    }
}

__global__ __launch_bounds__(256) void loss_final_kernel(
    const float* __restrict__ tce, const float* __restrict__ tw, float* __restrict__ out)
{
    float a = 0.0f, b = 0.0f;
    for (int i = threadIdx.x; i < MTOK; i += 256) { a += tce[i]; b += tw[i]; }
    a = blockReduceSum(a);
    b = blockReduceSum(b);
    if (threadIdx.x == 0) out[0] = a / b;
}

// ---------------- host driver ----------------
extern "C" void kernel_launch(void* const* d_in, const int* in_sizes, int n_in,
                              void* d_out, int out_size)
{
    (void)in_sizes; (void)n_in;
    const int*   ids   = (const int*)d_in[0];
    const int*   tgts  = (const int*)d_in[1];
    const void*  vmask = (const void*)d_in[2];
    const float* tok   = (const float*)d_in[3];
    const float* pos   = (const float*)d_in[4];
    const float* ln1w  = (const float*)d_in[5];
    const float* ln1b  = (const float*)d_in[6];
    const float* wqkv  = (const float*)d_in[7];
    const float* bqkv  = (const float*)d_in[8];
    const float* wproj = (const float*)d_in[9];
    const float* bproj = (const float*)d_in[10];
    const float* ln2w  = (const float*)d_in[11];
    const float* ln2b  = (const float*)d_in[12];
    const float* w1    = (const float*)d_in[13];
    const float* b1    = (const float*)d_in[14];
    const float* w2    = (const float*)d_in[15];
    const float* b2    = (const float*)d_in[16];
    const float* lnfw  = (const float*)d_in[17];
    const float* lnfb  = (const float*)d_in[18];
    float* out = (float*)d_out;

    float *x, *qkv, *tce, *tw;
    __nv_bfloat16 *hhi, *hlo, *mhi, *mlo;
    __nv_bfloat16 *wq_hi, *wq_lo, *wp_hi, *wp_lo, *w1_hi, *w1_lo, *w2_hi, *w2_lo, *lm_hi, *lm_lo;
    cudaGetSymbolAddress((void**)&x,    g_x);
    cudaGetSymbolAddress((void**)&qkv,  g_qkv);
    cudaGetSymbolAddress((void**)&hhi,  g_hhi);
    cudaGetSymbolAddress((void**)&hlo,  g_hlo);
    cudaGetSymbolAddress((void**)&mhi,  g_mhi);
    cudaGetSymbolAddress((void**)&mlo,  g_mlo);
    cudaGetSymbolAddress((void**)&wq_hi, g_wqkv_hi);
    cudaGetSymbolAddress((void**)&wq_lo, g_wqkv_lo);
    cudaGetSymbolAddress((void**)&wp_hi, g_wproj_hi);
    cudaGetSymbolAddress((void**)&wp_lo, g_wproj_lo);
    cudaGetSymbolAddress((void**)&w1_hi, g_w1_hi);
    cudaGetSymbolAddress((void**)&w1_lo, g_w1_lo);
    cudaGetSymbolAddress((void**)&w2_hi, g_w2_hi);
    cudaGetSymbolAddress((void**)&w2_lo, g_w2_lo);
    cudaGetSymbolAddress((void**)&lm_hi, g_lmh_hi);
    cudaGetSymbolAddress((void**)&lm_lo, g_lmh_lo);
    cudaGetSymbolAddress((void**)&tce,  g_tce);
    cudaGetSymbolAddress((void**)&tw,   g_tw);

    cudaFuncSetAttribute(gemm_ldsm_kernel<EPI_NONE>,
                         cudaFuncAttributeMaxDynamicSharedMemorySize, GEMM_SMEM_BYTES);
    cudaFuncSetAttribute(gemm_ldsm_kernel<EPI_RES>,
                         cudaFuncAttributeMaxDynamicSharedMemorySize, GEMM_SMEM_BYTES);
    cudaFuncSetAttribute(gemm_ldsm_kernel<EPI_GELU>,
                         cudaFuncAttributeMaxDynamicSharedMemorySize, GEMM_SMEM_BYTES);

    // ---- pack weights: [K][N] fp32 -> [N][K] bf16 hi/lo ----
    convw_nt<<<dim3(3*DMODEL/32, DMODEL/32, NLAYER), 256>>>(wqkv,  wq_hi, wq_lo, DMODEL, 3*DMODEL);
    convw_nt<<<dim3(DMODEL/32,   DMODEL/32, NLAYER), 256>>>(wproj, wp_hi, wp_lo, DMODEL, DMODEL);
    convw_nt<<<dim3(DFF/32,      DMODEL/32, NLAYER), 256>>>(w1,    w1_hi, w1_lo, DMODEL, DFF);
    convw_nt<<<dim3(DMODEL/32,   DFF/32,    NLAYER), 256>>>(w2,    w2_hi, w2_lo, DFF,    DMODEL);
    convsplit<<<VOCAB*DMODEL/256, 256>>>(tok, lm_hi, lm_lo);

    detect_mask_kernel<<<1, 256>>>((const unsigned char*)vmask);
    embed_kernel<<<MTOK, 256>>>(ids, tok, pos, x);

    const size_t wq_s = (size_t)3*DMODEL*DMODEL;
    const size_t wp_s = (size_t)DMODEL*DMODEL;
    const size_t w1_s = (size_t)DFF*DMODEL;
    const size_t w2_s = (size_t)DMODEL*DFF;

    for (int l = 0; l < NLAYER; l++) {
        ln_bf16_kernel<<<MTOK, 256>>>(x, ln1w + l*DMODEL, ln1b + l*DMODEL, hhi, hlo);

        gemm_ldsm_kernel<EPI_NONE><<<dim3(3*DMODEL/64, MTOK/128), 256, GEMM_SMEM_BYTES>>>(
            hhi, hlo, wq_hi + l*wq_s, wq_lo + l*wq_s,
            bqkv + (size_t)l*3*DMODEL, nullptr, qkv, nullptr, nullptr,
            MTOK, 3*DMODEL, DMODEL);

        attn_kernel<<<dim3(SEQ/128, NHEAD, BATCH), 128>>>(qkv, hhi, hlo);

        gemm_ldsm_kernel<EPI_RES><<<dim3(DMODEL/64, MTOK/128), 256, GEMM_SMEM_BYTES>>>(
            hhi, hlo, wp_hi + l*wp_s, wp_lo + l*wp_s,
            bproj + (size_t)l*DMODEL, x, x, nullptr, nullptr,
            MTOK, DMODEL, DMODEL);

        ln_bf16_kernel<<<MTOK, 256>>>(x, ln2w + l*DMODEL, ln2b + l*DMODEL, hhi, hlo);

        gemm_ldsm_kernel<EPI_GELU><<<dim3(DFF/64, MTOK/128), 256, GEMM_SMEM_BYTES>>>(
            hhi, hlo, w1_hi + l*w1_s, w1_lo + l*w1_s,
            b1 + (size_t)l*DFF, nullptr, nullptr, mhi, mlo,
            MTOK, DFF, DMODEL);

        gemm_ldsm_kernel<EPI_RES><<<dim3(DMODEL/64, MTOK/128), 256, GEMM_SMEM_BYTES>>>(
            mhi, mlo, w2_hi + l*w2_s, w2_lo + l*w2_s,
            b2 + (size_t)l*DMODEL, x, x, nullptr, nullptr,
            MTOK, DMODEL, DFF);
    }

    ln_bf16_kernel<<<MTOK, 256>>>(x, lnfw, lnfb, hhi, hlo);

    gemm_ldsm_kernel<EPI_NONE><<<dim3(VOCAB/64, MTOK/128), 256, GEMM_SMEM_BYTES>>>(
        hhi, hlo, lm_hi, lm_lo, nullptr, nullptr, out, nullptr, nullptr,
        MTOK, VOCAB, DMODEL);

    if (out_size > MTOK * VOCAB) {
        loss_token_kernel<<<MTOK, 256>>>(out, tgts, vmask, tce, tw);
        loss_final_kernel<<<1, 256>>>(tce, tw, out + (size_t)MTOK * VOCAB);
    }
}

// round 14
// speedup vs baseline: 2.2063x; 1.0552x over previous
#include <cuda_runtime.h>
#include <cuda_bf16.h>
#include <math.h>
#include <stdint.h>

// ---------------- problem constants ----------------
#define NLAYER   8
#define DMODEL   1024
#define NHEAD    16
#define HEADDIM  64
#define DFF      4096
#define VOCAB    4096
#define BATCH    4
#define SEQ      2048
#define MTOK     (BATCH*SEQ)      // 8192 tokens

// ---------------- scratch (device globals; no allocation allowed) ----------------
__device__ float g_x  [MTOK*DMODEL];       // residual stream (fp32)
__device__ float g_qkv[MTOK*3*DMODEL];     // qkv (fp32, attention input)
__device__ __nv_bfloat16 g_hhi[MTOK*DMODEL];
__device__ __nv_bfloat16 g_hlo[MTOK*DMODEL];
__device__ __nv_bfloat16 g_mhi[MTOK*DFF];
__device__ __nv_bfloat16 g_mlo[MTOK*DFF];
// split weights, N-major [L][N][K] bf16 (B^T layout; TN gemm via ldmatrix)
__device__ __nv_bfloat16 g_wqkv_hi[NLAYER*3*DMODEL*DMODEL];
__device__ __nv_bfloat16 g_wqkv_lo[NLAYER*3*DMODEL*DMODEL];
__device__ __nv_bfloat16 g_wproj_hi[NLAYER*DMODEL*DMODEL];
__device__ __nv_bfloat16 g_wproj_lo[NLAYER*DMODEL*DMODEL];
__device__ __nv_bfloat16 g_w1_hi[NLAYER*DFF*DMODEL];
__device__ __nv_bfloat16 g_w1_lo[NLAYER*DFF*DMODEL];
__device__ __nv_bfloat16 g_w2_hi[NLAYER*DMODEL*DFF];
__device__ __nv_bfloat16 g_w2_lo[NLAYER*DMODEL*DFF];
__device__ __nv_bfloat16 g_lmh_hi[VOCAB*DMODEL];
__device__ __nv_bfloat16 g_lmh_lo[VOCAB*DMODEL];
__device__ float g_tce[MTOK];
__device__ float g_tw [MTOK];
__device__ int   g_mflag;

// ---------------- block reductions ----------------
__device__ __forceinline__ float blockReduceSum(float val) {
    __shared__ float sh[32];
    const int lane = threadIdx.x & 31, wid = threadIdx.x >> 5;
    #pragma unroll
    for (int o = 16; o; o >>= 1) val += __shfl_xor_sync(0xffffffffu, val, o);
    if (lane == 0) sh[wid] = val;
    __syncthreads();
    const int nw = (blockDim.x + 31) >> 5;
    float t = (threadIdx.x < nw) ? sh[threadIdx.x] : 0.0f;
    #pragma unroll
    for (int o = 16; o; o >>= 1) t += __shfl_xor_sync(0xffffffffu, t, o);
    if (threadIdx.x == 0) sh[0] = t;
    __syncthreads();
    t = sh[0];
    __syncthreads();
    return t;
}

__device__ __forceinline__ float blockReduceMax(float val) {
    __shared__ float sh[32];
    const int lane = threadIdx.x & 31, wid = threadIdx.x >> 5;
    #pragma unroll
    for (int o = 16; o; o >>= 1) val = fmaxf(val, __shfl_xor_sync(0xffffffffu, val, o));
    if (lane == 0) sh[wid] = val;
    __syncthreads();
    const int nw = (blockDim.x + 31) >> 5;
    float t = (threadIdx.x < nw) ? sh[threadIdx.x] : -INFINITY;
    #pragma unroll
    for (int o = 16; o; o >>= 1) t = fmaxf(t, __shfl_xor_sync(0xffffffffu, t, o));
    if (threadIdx.x == 0) sh[0] = t;
    __syncthreads();
    t = sh[0];
    __syncthreads();
    return t;
}

// ---------------- helpers ----------------
__device__ __forceinline__ void split_bf16(float a, __nv_bfloat16& hi, __nv_bfloat16& lo) {
    hi = __float2bfloat16(a);
    lo = __float2bfloat16(a - __bfloat162float(hi));
}

__device__ __forceinline__ void cp16(void* sdst, const void* gsrc) {
    uint32_t sa = (uint32_t)__cvta_generic_to_shared(sdst);
    asm volatile("cp.async.cg.shared.global [%0], [%1], 16;" :: "r"(sa), "l"(gsrc));
}
#define CP_COMMIT() asm volatile("cp.async.commit_group;" ::: "memory")

__device__ __forceinline__ uint32_t smem_u32(const void* p) {
    return (uint32_t)__cvta_generic_to_shared(p);
}

#define SWZ128(off) ((off) ^ (((off) >> 3) & 0x70))

__device__ __forceinline__ void mma16816(float* d, const uint32_t* a, const uint32_t* b) {
    asm volatile(
        "mma.sync.aligned.m16n8k16.row.col.f32.bf16.bf16.f32 "
        "{%0,%1,%2,%3}, {%4,%5,%6,%7}, {%8,%9}, {%0,%1,%2,%3};"
        : "+f"(d[0]), "+f"(d[1]), "+f"(d[2]), "+f"(d[3])
        : "r"(a[0]), "r"(a[1]), "r"(a[2]), "r"(a[3]), "r"(b[0]), "r"(b[1]));
}

__device__ __forceinline__ void ldsm4(uint32_t* r, uint32_t addr) {
    asm volatile("ldmatrix.sync.aligned.m8n8.x4.shared.b16 {%0,%1,%2,%3}, [%4];"
                 : "=r"(r[0]), "=r"(r[1]), "=r"(r[2]), "=r"(r[3]) : "r"(addr));
}

// ---------------- packed f32x2 helpers (Blackwell FFMA2 path) ----------------
__device__ __forceinline__ uint64_t x2_fma(uint64_t a, uint64_t b, uint64_t c) {
    uint64_t d;
    asm("fma.rn.f32x2 %0, %1, %2, %3;" : "=l"(d) : "l"(a), "l"(b), "l"(c));
    return d;
}
__device__ __forceinline__ uint64_t x2_mul(uint64_t a, uint64_t b) {
    uint64_t d;
    asm("mul.rn.f32x2 %0, %1, %2;" : "=l"(d) : "l"(a), "l"(b));
    return d;
}
__device__ __forceinline__ uint64_t x2_pack(float lo, float hi) {
    uint64_t d;
    asm("mov.b64 %0, {%1, %2};" : "=l"(d) : "f"(lo), "f"(hi));
    return d;
}
__device__ __forceinline__ void x2_unpack(uint64_t v, float& lo, float& hi) {
    asm("mov.b64 {%0, %1}, %2;" : "=f"(lo), "=f"(hi) : "l"(v));
}

// ---------------- weight pack kernels ----------------
// W [K][N] fp32 -> Whi/Wlo bf16 [N][K] (tiled transpose + split)
__global__ __launch_bounds__(256) void convw_nt(
    const float* __restrict__ W, __nv_bfloat16* __restrict__ Whi,
    __nv_bfloat16* __restrict__ Wlo, int K, int N)
{
    __shared__ float tile[32][33];
    const int tx = threadIdx.x & 31, ty = threadIdx.x >> 5;
    const int n0 = blockIdx.x * 32, k0 = blockIdx.y * 32;
    const int l = blockIdx.z;
    const float* Wl = W + (size_t)l * K * N;
    #pragma unroll
    for (int i = ty; i < 32; i += 8)
        tile[i][tx] = Wl[(size_t)(k0 + i) * N + n0 + tx];
    __syncthreads();
    __nv_bfloat16* Hl = Whi + (size_t)l * N * K;
    __nv_bfloat16* Ll = Wlo + (size_t)l * N * K;
    #pragma unroll
    for (int i = ty; i < 32; i += 8) {
        __nv_bfloat16 h, lo;
        split_bf16(tile[tx][i], h, lo);   // = W[k0+tx][n0+i]
        Hl[(size_t)(n0 + i) * K + k0 + tx] = h;
        Ll[(size_t)(n0 + i) * K + k0 + tx] = lo;
    }
}

// elementwise split (lm_head: tok already [V][K])
__global__ __launch_bounds__(256) void convsplit(
    const float* __restrict__ W, __nv_bfloat16* __restrict__ hi, __nv_bfloat16* __restrict__ lo)
{
    const int i = blockIdx.x * 256 + threadIdx.x;
    __nv_bfloat16 h, l;
    split_bf16(W[i], h, l);
    hi[i] = h; lo[i] = l;
}

// ---------------- value_mask dtype probe ----------------
__global__ __launch_bounds__(256) void detect_mask_kernel(const unsigned char* __restrict__ m)
{
    __shared__ int sh[32];
    int s = 0;
    for (int i = threadIdx.x; i < 8192; i += 256)
        if (i & 3) s += m[i];
    #pragma unroll
    for (int o = 16; o; o >>= 1) s += __shfl_xor_sync(0xffffffffu, s, o);
    const int lane = threadIdx.x & 31, wid = threadIdx.x >> 5;
    if (lane == 0) sh[wid] = s;
    __syncthreads();
    if (threadIdx.x < 8) {
        int t = sh[threadIdx.x];
        #pragma unroll
        for (int o = 4; o; o >>= 1) t += __shfl_xor_sync(0xffu, t, o);
        if (threadIdx.x == 0) g_mflag = (t != 0) ? 1 : 0;
    }
}

// ---------------- embed ----------------
__global__ __launch_bounds__(256) void embed_kernel(
    const int* __restrict__ ids, const float* __restrict__ tok,
    const float* __restrict__ pos, float* __restrict__ x)
{
    const int m = blockIdx.x;
    const int t = m & (SEQ - 1);
    const int id = ids[m];
    const float4 a = ((const float4*)(tok + (size_t)id * DMODEL))[threadIdx.x];
    const float4 b = ((const float4*)(pos + (size_t)t  * DMODEL))[threadIdx.x];
    ((float4*)(x + (size_t)m * DMODEL))[threadIdx.x] =
        make_float4(a.x + b.x, a.y + b.y, a.z + b.z, a.w + b.w);
}

// ---------------- layernorm -> split bf16 ----------------
__global__ __launch_bounds__(256) void ln_bf16_kernel(
    const float* __restrict__ x, const float* __restrict__ w,
    const float* __restrict__ b, __nv_bfloat16* __restrict__ yhi,
    __nv_bfloat16* __restrict__ ylo)
{
    const int row = blockIdx.x;
    const float4 v = ((const float4*)(x + (size_t)row * DMODEL))[threadIdx.x];
    float s = v.x + v.y + v.z + v.w;
    s = blockReduceSum(s);
    const float mu = s * (1.0f / DMODEL);
    const float d0 = v.x - mu, d1 = v.y - mu, d2 = v.z - mu, d3 = v.w - mu;
    float q = d0*d0 + d1*d1 + d2*d2 + d3*d3;
    q = blockReduceSum(q);
    const float rs = rsqrtf(q * (1.0f / DMODEL) + 1e-5f);
    const float4 w4 = ((const float4*)w)[threadIdx.x];
    const float4 b4 = ((const float4*)b)[threadIdx.x];
    float o0 = d0 * rs * w4.x + b4.x;
    float o1 = d1 * rs * w4.y + b4.y;
    float o2 = d2 * rs * w4.z + b4.z;
    float o3 = d3 * rs * w4.w + b4.w;
    __nv_bfloat16 h0,l0,h1,l1,h2,l2,h3,l3;
    split_bf16(o0,h0,l0); split_bf16(o1,h1,l1); split_bf16(o2,h2,l2); split_bf16(o3,h3,l3);
    const size_t base = (size_t)row * DMODEL + threadIdx.x * 4;
    *(__nv_bfloat162*)(yhi + base)     = __halves2bfloat162(h0, h1);
    *(__nv_bfloat162*)(yhi + base + 2) = __halves2bfloat162(h2, h3);
    *(__nv_bfloat162*)(ylo + base)     = __halves2bfloat162(l0, l1);
    *(__nv_bfloat162*)(ylo + base + 2) = __halves2bfloat162(l2, l3);
}

// ---------------- split-bf16 mma GEMM: 2-CTA/SM geometry (R13 winner) -----------
enum { EPI_NONE = 0, EPI_RES = 1, EPI_GELU = 2 };

#define STAGE_BYTES 49152
#define GEMM_SMEM_BYTES (2*STAGE_BYTES)   // 98304

template<int EPI>
__global__ __launch_bounds__(256, 2) void gemm_ldsm_kernel(
    const __nv_bfloat16* __restrict__ Ahi, const __nv_bfloat16* __restrict__ Alo,
    const __nv_bfloat16* __restrict__ Bhi, const __nv_bfloat16* __restrict__ Blo,
    const float* __restrict__ bias, const float* __restrict__ res,
    float* __restrict__ C, __nv_bfloat16* __restrict__ Chi, __nv_bfloat16* __restrict__ Clo,
    int M, int N, int K)
{
    extern __shared__ __align__(1024) char smem[];
    const uint32_t sb = smem_u32(smem);
    const int tid = threadIdx.x, lane = tid & 31, wid = tid >> 5;
    const int wm = wid >> 1, wn = wid & 1;              // warp tile (wm*32, wn*32)
    const int bm = blockIdx.y * 128, bn = blockIdx.x * 64;

    float acc[2][4][4];
    #pragma unroll
    for (int mt = 0; mt < 2; mt++)
        #pragma unroll
        for (int nt = 0; nt < 4; nt++)
            #pragma unroll
            for (int i = 0; i < 4; i++) acc[mt][nt][i] = 0.0f;

    auto fill = [&](int s, int kt) {
        char* st = smem + s * STAGE_BYTES;
        const int k0 = kt << 6;
        #pragma unroll
        for (int i = 0; i < 4; i++) {
            const int idx = tid + i * 256;
            const int row = idx >> 3, c16 = idx & 7;
            const uint32_t sw = SWZ128((uint32_t)((row << 7) + (c16 << 4)));
            const size_t ga = (size_t)(bm + row) * K + k0 + c16 * 8;
            cp16(st + sw,         Ahi + ga);
            cp16(st + 16384 + sw, Alo + ga);
        }
        #pragma unroll
        for (int i = 0; i < 2; i++) {
            const int idx = tid + i * 256;
            const int row = idx >> 3, c16 = idx & 7;
            const uint32_t sw = SWZ128((uint32_t)((row << 7) + (c16 << 4)));
            const size_t gb = (size_t)(bn + row) * K + k0 + c16 * 8;
            cp16(st + 32768 + sw, Bhi + gb);
            cp16(st + 40960 + sw, Blo + gb);
        }
    };

    const int laneRA = lane & 15;
    const int laneCA = (lane >> 4) << 4;
    const int laneRB = (lane & 7) + ((lane >> 4) << 3);
    const int laneCB = ((lane >> 3) & 1) << 4;

    const int niter = K >> 6;
    fill(0, 0); CP_COMMIT();

    for (int it = 0; it < niter; it++) {
        const int s = it & 1;
        if (it + 1 < niter) {
            fill(s ^ 1, it + 1); CP_COMMIT();
            asm volatile("cp.async.wait_group 1;" ::: "memory");
        } else {
            asm volatile("cp.async.wait_group 0;" ::: "memory");
        }
        __syncthreads();

        const uint32_t aH = sb + s * STAGE_BYTES;
        const uint32_t aL = aH + 16384;
        const uint32_t bH = aH + 32768;
        const uint32_t bL = aH + 40960;

        #pragma unroll
        for (int k16 = 0; k16 < 4; k16++) {
            const int kb = k16 * 32;
            uint32_t ah[2][4], al[2][4], bh[4][2], bl[4][2];
            #pragma unroll
            for (int mt = 0; mt < 2; mt++) {
                const uint32_t off = SWZ128(
                    (uint32_t)(((wm * 32 + mt * 16 + laneRA) << 7) + kb + laneCA));
                ldsm4(ah[mt], aH + off);
                ldsm4(al[mt], aL + off);
            }
            #pragma unroll
            for (int j = 0; j < 2; j++) {
                const uint32_t off = SWZ128(
                    (uint32_t)(((wn * 32 + j * 16 + laneRB) << 7) + kb + laneCB));
                ldsm4(&bh[j * 2][0], bH + off);
                ldsm4(&bl[j * 2][0], bL + off);
            }
            #pragma unroll
            for (int mt = 0; mt < 2; mt++)
                #pragma unroll
                for (int nt = 0; nt < 4; nt++) mma16816(acc[mt][nt], ah[mt], bh[nt]);
            #pragma unroll
            for (int mt = 0; mt < 2; mt++)
                #pragma unroll
                for (int nt = 0; nt < 4; nt++) mma16816(acc[mt][nt], ah[mt], bl[nt]);
            #pragma unroll
            for (int mt = 0; mt < 2; mt++)
                #pragma unroll
                for (int nt = 0; nt < 4; nt++) mma16816(acc[mt][nt], al[mt], bh[nt]);
        }
        __syncthreads();
    }

    // ---- epilogue ----
    const int g = lane >> 2, t = lane & 3;
    #pragma unroll
    for (int mt = 0; mt < 2; mt++) {
        #pragma unroll
        for (int nt = 0; nt < 4; nt++) {
            const int col = bn + wn * 32 + nt * 8 + 2 * t;
            #pragma unroll
            for (int half = 0; half < 2; half++) {
                const int row = bm + wm * 32 + mt * 16 + g + half * 8;
                float v0 = acc[mt][nt][2 * half + 0];
                float v1 = acc[mt][nt][2 * half + 1];
                if (bias) { v0 += bias[col]; v1 += bias[col + 1]; }
                const size_t o = (size_t)row * N + col;
                if (EPI == EPI_GELU) {
                    v0 = 0.5f * v0 * (1.0f + erff(v0 * 0.70710678118654752f));
                    v1 = 0.5f * v1 * (1.0f + erff(v1 * 0.70710678118654752f));
                    __nv_bfloat16 h0, l0, h1, l1;
                    split_bf16(v0, h0, l0);
                    split_bf16(v1, h1, l1);
                    *(__nv_bfloat162*)(Chi + o) = __halves2bfloat162(h0, h1);
                    *(__nv_bfloat162*)(Clo + o) = __halves2bfloat162(l0, l1);
                } else {
                    if (EPI == EPI_RES) {
                        const float2 r2 = *(const float2*)(res + o);
                        v0 += r2.x; v1 += r2.y;
                    }
                    *(float2*)(C + o) = make_float2(v0, v1);
                }
            }
        }
    }
}

// ---------------- causal flash attention (packed f32x2 math) --------------------
__global__ __launch_bounds__(128) void attn_kernel(
    const float* __restrict__ qkv,
    __nv_bfloat16* __restrict__ ohi, __nv_bfloat16* __restrict__ olo)
{
    const int qt = blockIdx.x, h = blockIdx.y, b = blockIdx.z;
    const int tid = threadIdx.x;
    const int qg = qt * 128 + tid;
    const size_t mrow = (size_t)b * SEQ + qg;

    __shared__ __align__(16) float Ks[32][64];
    __shared__ __align__(16) float Vs[32][64];
    __shared__ __align__(16) float Sp[32][128];

    uint64_t q2[32];                       // packed (q[2i], q[2i+1])
    {
        const ulonglong2* qp = (const ulonglong2*)(qkv + mrow * (3 * DMODEL) + h * HEADDIM);
        #pragma unroll
        for (int i = 0; i < 16; i++) {
            const ulonglong2 t2 = qp[i];
            q2[2 * i]     = t2.x;
            q2[2 * i + 1] = t2.y;
        }
    }

    uint64_t acc2[32];                     // packed output accumulator
    #pragma unroll
    for (int d = 0; d < 32; d++) acc2[d] = 0ull;   // 0x0 == (0.0f, 0.0f)
    float m_i = -INFINITY, l_i = 0.0f;
    const float scale = 0.125f;

    const float* kbase = qkv + (size_t)b * SEQ * (3 * DMODEL) + DMODEL     + h * HEADDIM;
    const float* vbase = qkv + (size_t)b * SEQ * (3 * DMODEL) + 2 * DMODEL + h * HEADDIM;

    const int nkt = 4 * qt + 4;
    for (int kt = 0; kt < nkt; kt++) {
        {
            const int r0 = tid >> 4;
            const int c4 = tid & 15;
            #pragma unroll
            for (int it2 = 0; it2 < 4; it2++) {
                const int r = it2 * 8 + r0;
                const size_t roff = (size_t)(kt * 32 + r) * (3 * DMODEL);
                *(float4*)&Ks[r][c4 * 4] = *(const float4*)(kbase + roff + c4 * 4);
                *(float4*)&Vs[r][c4 * 4] = *(const float4*)(vbase + roff + c4 * 4);
            }
        }
        __syncthreads();

        const int kg0 = kt * 32;
        float tmax = -INFINITY;
        #pragma unroll 2
        for (int j = 0; j < 32; j++) {
            uint64_t p0 = 0ull, p1 = 0ull;
            const ulonglong2* kr = (const ulonglong2*)Ks[j];
            #pragma unroll
            for (int i = 0; i < 16; i++) {
                const ulonglong2 kk = kr[i];
                p0 = x2_fma(q2[2 * i],     kk.x, p0);
                p1 = x2_fma(q2[2 * i + 1], kk.y, p1);
            }
            float a0, a1, b0, b1;
            x2_unpack(p0, a0, a1);
            x2_unpack(p1, b0, b1);
            float s = (a0 + a1) + (b0 + b1);
            s *= scale;
            s = (kg0 + j <= qg) ? s : -INFINITY;
            Sp[j][tid] = s;
            tmax = fmaxf(tmax, s);
        }

        const float mnew = fmaxf(m_i, tmax);
        const float corr = expf(m_i - mnew);
        const uint64_t corr2 = x2_pack(corr, corr);
        #pragma unroll
        for (int d = 0; d < 32; d++) acc2[d] = x2_mul(acc2[d], corr2);

        float lsum = 0.0f;
        #pragma unroll 2
        for (int j = 0; j < 32; j++) {
            const float e = expf(Sp[j][tid] - mnew);
            lsum += e;
            const uint64_t e2 = x2_pack(e, e);
            const ulonglong2* vr = (const ulonglong2*)Vs[j];
            #pragma unroll
            for (int i = 0; i < 16; i++) {
                const ulonglong2 vv = vr[i];
                acc2[2 * i]     = x2_fma(e2, vv.x, acc2[2 * i]);
                acc2[2 * i + 1] = x2_fma(e2, vv.y, acc2[2 * i + 1]);
            }
        }
        l_i = l_i * corr + lsum;
        m_i = mnew;
        __syncthreads();
    }

    const float inv = 1.0f / l_i;
    const size_t obase = mrow * DMODEL + h * HEADDIM;
    #pragma unroll
    for (int i = 0; i < 16; i++) {
        float v0, v1, v2, v3;
        x2_unpack(acc2[2 * i],     v0, v1);
        x2_unpack(acc2[2 * i + 1], v2, v3);
        v0 *= inv; v1 *= inv; v2 *= inv; v3 *= inv;
        __nv_bfloat16 h0,l0,h1,l1,h2,l2,h3,l3;
        split_bf16(v0,h0,l0); split_bf16(v1,h1,l1); split_bf16(v2,h2,l2); split_bf16(v3,h3,l3);
        *(__nv_bfloat162*)(ohi + obase + 4*i)     = __halves2bfloat162(h0, h1);
        *(__nv_bfloat162*)(ohi + obase + 4*i + 2) = __halves2bfloat162(h2, h3);
        *(__nv_bfloat162*)(olo + obase + 4*i)     = __halves2bfloat162(l0, l1);
        *(__nv_bfloat162*)(olo + obase + 4*i + 2) = __halves2bfloat162(l2, l3);
    }
}

// ---------------- loss ----------------
__global__ __launch_bounds__(256) void loss_token_kernel(
    const float* __restrict__ logits, const int* __restrict__ targets,
    const void* __restrict__ vmask,
    float* __restrict__ tce, float* __restrict__ tw)
{
    const int row = blockIdx.x;
    const float* lr = logits + (size_t)row * VOCAB;
    float v[16];
    #pragma unroll
    for (int i = 0; i < 16; i++) v[i] = lr[threadIdx.x + 256 * i];
    float mx = v[0];
    #pragma unroll
    for (int i = 1; i < 16; i++) mx = fmaxf(mx, v[i]);
    mx = blockReduceMax(mx);
    float se = 0.0f;
    #pragma unroll
    for (int i = 0; i < 16; i++) se += expf(v[i] - mx);
    se = blockReduceSum(se);
    if (threadIdx.x == 0) {
        const int tgt = targets[row];
        const float lse = mx + logf(se);
        const float nll = lse - lr[tgt];
        int mv;
        if (g_mflag) mv = ((const unsigned char*)vmask)[row];
        else         mv = ((const int*)vmask)[row];
        const float w = 1.0f + 4.0f * ((mv != 0) ? 1.0f : 0.0f);
        tce[row] = (tgt == 0) ? 0.0f : nll * w;
        tw[row]  = w;
    }
}

__global__ __launch_bounds__(256) void loss_final_kernel(
    const float* __restrict__ tce, const float* __restrict__ tw, float* __restrict__ out)
{
    float a = 0.0f, b = 0.0f;
    for (int i = threadIdx.x; i < MTOK; i += 256) { a += tce[i]; b += tw[i]; }
    a = blockReduceSum(a);
    b = blockReduceSum(b);
    if (threadIdx.x == 0) out[0] = a / b;
}

// ---------------- host driver ----------------
extern "C" void kernel_launch(void* const* d_in, const int* in_sizes, int n_in,
                              void* d_out, int out_size)
{
    (void)in_sizes; (void)n_in;
    const int*   ids   = (const int*)d_in[0];
    const int*   tgts  = (const int*)d_in[1];
    const void*  vmask = (const void*)d_in[2];
    const float* tok   = (const float*)d_in[3];
    const float* pos   = (const float*)d_in[4];
    const float* ln1w  = (const float*)d_in[5];
    const float* ln1b  = (const float*)d_in[6];
    const float* wqkv  = (const float*)d_in[7];
    const float* bqkv  = (const float*)d_in[8];
    const float* wproj = (const float*)d_in[9];
    const float* bproj = (const float*)d_in[10];
    const float* ln2w  = (const float*)d_in[11];
    const float* ln2b  = (const float*)d_in[12];
    const float* w1    = (const float*)d_in[13];
    const float* b1    = (const float*)d_in[14];
    const float* w2    = (const float*)d_in[15];
    const float* b2    = (const float*)d_in[16];
    const float* lnfw  = (const float*)d_in[17];
    const float* lnfb  = (const float*)d_in[18];
    float* out = (float*)d_out;

    float *x, *qkv, *tce, *tw;
    __nv_bfloat16 *hhi, *hlo, *mhi, *mlo;
    __nv_bfloat16 *wq_hi, *wq_lo, *wp_hi, *wp_lo, *w1_hi, *w1_lo, *w2_hi, *w2_lo, *lm_hi, *lm_lo;
    cudaGetSymbolAddress((void**)&x,    g_x);
    cudaGetSymbolAddress((void**)&qkv,  g_qkv);
    cudaGetSymbolAddress((void**)&hhi,  g_hhi);
    cudaGetSymbolAddress((void**)&hlo,  g_hlo);
    cudaGetSymbolAddress((void**)&mhi,  g_mhi);
    cudaGetSymbolAddress((void**)&mlo,  g_mlo);
    cudaGetSymbolAddress((void**)&wq_hi, g_wqkv_hi);
    cudaGetSymbolAddress((void**)&wq_lo, g_wqkv_lo);
    cudaGetSymbolAddress((void**)&wp_hi, g_wproj_hi);
    cudaGetSymbolAddress((void**)&wp_lo, g_wproj_lo);
    cudaGetSymbolAddress((void**)&w1_hi, g_w1_hi);
    cudaGetSymbolAddress((void**)&w1_lo, g_w1_lo);
    cudaGetSymbolAddress((void**)&w2_hi, g_w2_hi);
    cudaGetSymbolAddress((void**)&w2_lo, g_w2_lo);
    cudaGetSymbolAddress((void**)&lm_hi, g_lmh_hi);
    cudaGetSymbolAddress((void**)&lm_lo, g_lmh_lo);
    cudaGetSymbolAddress((void**)&tce,  g_tce);
    cudaGetSymbolAddress((void**)&tw,   g_tw);

    cudaFuncSetAttribute(gemm_ldsm_kernel<EPI_NONE>,
                         cudaFuncAttributeMaxDynamicSharedMemorySize, GEMM_SMEM_BYTES);
    cudaFuncSetAttribute(gemm_ldsm_kernel<EPI_RES>,
                         cudaFuncAttributeMaxDynamicSharedMemorySize, GEMM_SMEM_BYTES);
    cudaFuncSetAttribute(gemm_ldsm_kernel<EPI_GELU>,
                         cudaFuncAttributeMaxDynamicSharedMemorySize, GEMM_SMEM_BYTES);

    // ---- pack weights: [K][N] fp32 -> [N][K] bf16 hi/lo ----
    convw_nt<<<dim3(3*DMODEL/32, DMODEL/32, NLAYER), 256>>>(wqkv,  wq_hi, wq_lo, DMODEL, 3*DMODEL);
    convw_nt<<<dim3(DMODEL/32,   DMODEL/32, NLAYER), 256>>>(wproj, wp_hi, wp_lo, DMODEL, DMODEL);
    convw_nt<<<dim3(DFF/32,      DMODEL/32, NLAYER), 256>>>(w1,    w1_hi, w1_lo, DMODEL, DFF);
    convw_nt<<<dim3(DMODEL/32,   DFF/32,    NLAYER), 256>>>(w2,    w2_hi, w2_lo, DFF,    DMODEL);
    convsplit<<<VOCAB*DMODEL/256, 256>>>(tok, lm_hi, lm_lo);

    detect_mask_kernel<<<1, 256>>>((const unsigned char*)vmask);
    embed_kernel<<<MTOK, 256>>>(ids, tok, pos, x);

    const size_t wq_s = (size_t)3*DMODEL*DMODEL;
    const size_t wp_s = (size_t)DMODEL*DMODEL;
    const size_t w1_s = (size_t)DFF*DMODEL;
    const size_t w2_s = (size_t)DMODEL*DFF;

    for (int l = 0; l < NLAYER; l++) {
        ln_bf16_kernel<<<MTOK, 256>>>(x, ln1w + l*DMODEL, ln1b + l*DMODEL, hhi, hlo);

        gemm_ldsm_kernel<EPI_NONE><<<dim3(3*DMODEL/64, MTOK/128), 256, GEMM_SMEM_BYTES>>>(
            hhi, hlo, wq_hi + l*wq_s, wq_lo + l*wq_s,
            bqkv + (size_t)l*3*DMODEL, nullptr, qkv, nullptr, nullptr,
            MTOK, 3*DMODEL, DMODEL);

        attn_kernel<<<dim3(SEQ/128, NHEAD, BATCH), 128>>>(qkv, hhi, hlo);

        gemm_ldsm_kernel<EPI_RES><<<dim3(DMODEL/64, MTOK/128), 256, GEMM_SMEM_BYTES>>>(
            hhi, hlo, wp_hi + l*wp_s, wp_lo + l*wp_s,
            bproj + (size_t)l*DMODEL, x, x, nullptr, nullptr,
            MTOK, DMODEL, DMODEL);

        ln_bf16_kernel<<<MTOK, 256>>>(x, ln2w + l*DMODEL, ln2b + l*DMODEL, hhi, hlo);

        gemm_ldsm_kernel<EPI_GELU><<<dim3(DFF/64, MTOK/128), 256, GEMM_SMEM_BYTES>>>(
            hhi, hlo, w1_hi + l*w1_s, w1_lo + l*w1_s,
            b1 + (size_t)l*DFF, nullptr, nullptr, mhi, mlo,
            MTOK, DFF, DMODEL);

        gemm_ldsm_kernel<EPI_RES><<<dim3(DMODEL/64, MTOK/128), 256, GEMM_SMEM_BYTES>>>(
            mhi, mlo, w2_hi + l*w2_s, w2_lo + l*w2_s,
            b2 + (size_t)l*DMODEL, x, x, nullptr, nullptr,
            MTOK, DMODEL, DFF);
    }

    ln_bf16_kernel<<<MTOK, 256>>>(x, lnfw, lnfb, hhi, hlo);

    gemm_ldsm_kernel<EPI_NONE><<<dim3(VOCAB/64, MTOK/128), 256, GEMM_SMEM_BYTES>>>(
        hhi, hlo, lm_hi, lm_lo, nullptr, nullptr, out, nullptr, nullptr,
        MTOK, VOCAB, DMODEL);

    if (out_size > MTOK * VOCAB) {
        loss_token_kernel<<<MTOK, 256>>>(out, tgts, vmask, tce, tw);
        loss_final_kernel<<<1, 256>>>(tce, tw, out + (size_t)MTOK * VOCAB);
    }
}

// round 15
// speedup vs baseline: 3.3908x; 1.5369x over previous
#include <cuda_runtime.h>
#include <cuda_bf16.h>
#include <math.h>
#include <stdint.h>

// ---------------- problem constants ----------------
#define NLAYER   8
#define DMODEL   1024
#define NHEAD    16
#define HEADDIM  64
#define DFF      4096
#define VOCAB    4096
#define BATCH    4
#define SEQ      2048
#define MTOK     (BATCH*SEQ)      // 8192 tokens

// ---------------- scratch (device globals; no allocation allowed) ----------------
__device__ float g_x  [MTOK*DMODEL];       // residual stream (fp32)
__device__ float g_qkv[MTOK*3*DMODEL];     // qkv (fp32, attention input)
__device__ __nv_bfloat16 g_hhi[MTOK*DMODEL];
__device__ __nv_bfloat16 g_hlo[MTOK*DMODEL];
__device__ __nv_bfloat16 g_mhi[MTOK*DFF];
__device__ __nv_bfloat16 g_mlo[MTOK*DFF];
// split weights, N-major [L][N][K] bf16 (B^T layout; TN gemm via ldmatrix)
__device__ __nv_bfloat16 g_wqkv_hi[NLAYER*3*DMODEL*DMODEL];
__device__ __nv_bfloat16 g_wqkv_lo[NLAYER*3*DMODEL*DMODEL];
__device__ __nv_bfloat16 g_wproj_hi[NLAYER*DMODEL*DMODEL];
__device__ __nv_bfloat16 g_wproj_lo[NLAYER*DMODEL*DMODEL];
__device__ __nv_bfloat16 g_w1_hi[NLAYER*DFF*DMODEL];
__device__ __nv_bfloat16 g_w1_lo[NLAYER*DFF*DMODEL];
__device__ __nv_bfloat16 g_w2_hi[NLAYER*DMODEL*DFF];
__device__ __nv_bfloat16 g_w2_lo[NLAYER*DMODEL*DFF];
__device__ __nv_bfloat16 g_lmh_hi[VOCAB*DMODEL];
__device__ __nv_bfloat16 g_lmh_lo[VOCAB*DMODEL];
__device__ float g_tce[MTOK];
__device__ float g_tw [MTOK];
__device__ int   g_mflag;

// ---------------- block reductions ----------------
__device__ __forceinline__ float blockReduceSum(float val) {
    __shared__ float sh[32];
    const int lane = threadIdx.x & 31, wid = threadIdx.x >> 5;
    #pragma unroll
    for (int o = 16; o; o >>= 1) val += __shfl_xor_sync(0xffffffffu, val, o);
    if (lane == 0) sh[wid] = val;
    __syncthreads();
    const int nw = (blockDim.x + 31) >> 5;
    float t = (threadIdx.x < nw) ? sh[threadIdx.x] : 0.0f;
    #pragma unroll
    for (int o = 16; o; o >>= 1) t += __shfl_xor_sync(0xffffffffu, t, o);
    if (threadIdx.x == 0) sh[0] = t;
    __syncthreads();
    t = sh[0];
    __syncthreads();
    return t;
}

__device__ __forceinline__ float blockReduceMax(float val) {
    __shared__ float sh[32];
    const int lane = threadIdx.x & 31, wid = threadIdx.x >> 5;
    #pragma unroll
    for (int o = 16; o; o >>= 1) val = fmaxf(val, __shfl_xor_sync(0xffffffffu, val, o));
    if (lane == 0) sh[wid] = val;
    __syncthreads();
    const int nw = (blockDim.x + 31) >> 5;
    float t = (threadIdx.x < nw) ? sh[threadIdx.x] : -INFINITY;
    #pragma unroll
    for (int o = 16; o; o >>= 1) t = fmaxf(t, __shfl_xor_sync(0xffffffffu, t, o));
    if (threadIdx.x == 0) sh[0] = t;
    __syncthreads();
    t = sh[0];
    __syncthreads();
    return t;
}

// ---------------- helpers ----------------
__device__ __forceinline__ void split_bf16(float a, __nv_bfloat16& hi, __nv_bfloat16& lo) {
    hi = __float2bfloat16(a);
    lo = __float2bfloat16(a - __bfloat162float(hi));
}
// pack two bf16 (c0 low, c1 high) into u32 (mma operand ordering)
__device__ __forceinline__ uint32_t packbf(__nv_bfloat16 c0, __nv_bfloat16 c1) {
    return (uint32_t)__bfloat16_as_ushort(c0) | ((uint32_t)__bfloat16_as_ushort(c1) << 16);
}

__device__ __forceinline__ void cp16(void* sdst, const void* gsrc) {
    uint32_t sa = (uint32_t)__cvta_generic_to_shared(sdst);
    asm volatile("cp.async.cg.shared.global [%0], [%1], 16;" :: "r"(sa), "l"(gsrc));
}
#define CP_COMMIT() asm volatile("cp.async.commit_group;" ::: "memory")

__device__ __forceinline__ uint32_t smem_u32(const void* p) {
    return (uint32_t)__cvta_generic_to_shared(p);
}

#define SWZ128(off) ((off) ^ (((off) >> 3) & 0x70))

__device__ __forceinline__ void mma16816(float* d, const uint32_t* a, const uint32_t* b) {
    asm volatile(
        "mma.sync.aligned.m16n8k16.row.col.f32.bf16.bf16.f32 "
        "{%0,%1,%2,%3}, {%4,%5,%6,%7}, {%8,%9}, {%0,%1,%2,%3};"
        : "+f"(d[0]), "+f"(d[1]), "+f"(d[2]), "+f"(d[3])
        : "r"(a[0]), "r"(a[1]), "r"(a[2]), "r"(a[3]), "r"(b[0]), "r"(b[1]));
}

__device__ __forceinline__ void ldsm4(uint32_t* r, uint32_t addr) {
    asm volatile("ldmatrix.sync.aligned.m8n8.x4.shared.b16 {%0,%1,%2,%3}, [%4];"
                 : "=r"(r[0]), "=r"(r[1]), "=r"(r[2]), "=r"(r[3]) : "r"(addr));
}

// ---------------- weight pack kernels ----------------
__global__ __launch_bounds__(256) void convw_nt(
    const float* __restrict__ W, __nv_bfloat16* __restrict__ Whi,
    __nv_bfloat16* __restrict__ Wlo, int K, int N)
{
    __shared__ float tile[32][33];
    const int tx = threadIdx.x & 31, ty = threadIdx.x >> 5;
    const int n0 = blockIdx.x * 32, k0 = blockIdx.y * 32;
    const int l = blockIdx.z;
    const float* Wl = W + (size_t)l * K * N;
    #pragma unroll
    for (int i = ty; i < 32; i += 8)
        tile[i][tx] = Wl[(size_t)(k0 + i) * N + n0 + tx];
    __syncthreads();
    __nv_bfloat16* Hl = Whi + (size_t)l * N * K;
    __nv_bfloat16* Ll = Wlo + (size_t)l * N * K;
    #pragma unroll
    for (int i = ty; i < 32; i += 8) {
        __nv_bfloat16 h, lo;
        split_bf16(tile[tx][i], h, lo);
        Hl[(size_t)(n0 + i) * K + k0 + tx] = h;
        Ll[(size_t)(n0 + i) * K + k0 + tx] = lo;
    }
}

__global__ __launch_bounds__(256) void convsplit(
    const float* __restrict__ W, __nv_bfloat16* __restrict__ hi, __nv_bfloat16* __restrict__ lo)
{
    const int i = blockIdx.x * 256 + threadIdx.x;
    __nv_bfloat16 h, l;
    split_bf16(W[i], h, l);
    hi[i] = h; lo[i] = l;
}

// ---------------- value_mask dtype probe ----------------
__global__ __launch_bounds__(256) void detect_mask_kernel(const unsigned char* __restrict__ m)
{
    __shared__ int sh[32];
    int s = 0;
    for (int i = threadIdx.x; i < 8192; i += 256)
        if (i & 3) s += m[i];
    #pragma unroll
    for (int o = 16; o; o >>= 1) s += __shfl_xor_sync(0xffffffffu, s, o);
    const int lane = threadIdx.x & 31, wid = threadIdx.x >> 5;
    if (lane == 0) sh[wid] = s;
    __syncthreads();
    if (threadIdx.x < 8) {
        int t = sh[threadIdx.x];
        #pragma unroll
        for (int o = 4; o; o >>= 1) t += __shfl_xor_sync(0xffu, t, o);
        if (threadIdx.x == 0) g_mflag = (t != 0) ? 1 : 0;
    }
}

// ---------------- embed ----------------
__global__ __launch_bounds__(256) void embed_kernel(
    const int* __restrict__ ids, const float* __restrict__ tok,
    const float* __restrict__ pos, float* __restrict__ x)
{
    const int m = blockIdx.x;
    const int t = m & (SEQ - 1);
    const int id = ids[m];
    const float4 a = ((const float4*)(tok + (size_t)id * DMODEL))[threadIdx.x];
    const float4 b = ((const float4*)(pos + (size_t)t  * DMODEL))[threadIdx.x];
    ((float4*)(x + (size_t)m * DMODEL))[threadIdx.x] =
        make_float4(a.x + b.x, a.y + b.y, a.z + b.z, a.w + b.w);
}

// ---------------- layernorm -> split bf16 ----------------
__global__ __launch_bounds__(256) void ln_bf16_kernel(
    const float* __restrict__ x, const float* __restrict__ w,
    const float* __restrict__ b, __nv_bfloat16* __restrict__ yhi,
    __nv_bfloat16* __restrict__ ylo)
{
    const int row = blockIdx.x;
    const float4 v = ((const float4*)(x + (size_t)row * DMODEL))[threadIdx.x];
    float s = v.x + v.y + v.z + v.w;
    s = blockReduceSum(s);
    const float mu = s * (1.0f / DMODEL);
    const float d0 = v.x - mu, d1 = v.y - mu, d2 = v.z - mu, d3 = v.w - mu;
    float q = d0*d0 + d1*d1 + d2*d2 + d3*d3;
    q = blockReduceSum(q);
    const float rs = rsqrtf(q * (1.0f / DMODEL) + 1e-5f);
    const float4 w4 = ((const float4*)w)[threadIdx.x];
    const float4 b4 = ((const float4*)b)[threadIdx.x];
    float o0 = d0 * rs * w4.x + b4.x;
    float o1 = d1 * rs * w4.y + b4.y;
    float o2 = d2 * rs * w4.z + b4.z;
    float o3 = d3 * rs * w4.w + b4.w;
    __nv_bfloat16 h0,l0,h1,l1,h2,l2,h3,l3;
    split_bf16(o0,h0,l0); split_bf16(o1,h1,l1); split_bf16(o2,h2,l2); split_bf16(o3,h3,l3);
    const size_t base = (size_t)row * DMODEL + threadIdx.x * 4;
    *(__nv_bfloat162*)(yhi + base)     = __halves2bfloat162(h0, h1);
    *(__nv_bfloat162*)(yhi + base + 2) = __halves2bfloat162(h2, h3);
    *(__nv_bfloat162*)(ylo + base)     = __halves2bfloat162(l0, l1);
    *(__nv_bfloat162*)(ylo + base + 2) = __halves2bfloat162(l2, l3);
}

// ---------------- split-bf16 mma GEMM: 2-CTA/SM geometry (R13 winner) -----------
enum { EPI_NONE = 0, EPI_RES = 1, EPI_GELU = 2 };

#define STAGE_BYTES 49152
#define GEMM_SMEM_BYTES (2*STAGE_BYTES)   // 98304

template<int EPI>
__global__ __launch_bounds__(256, 2) void gemm_ldsm_kernel(
    const __nv_bfloat16* __restrict__ Ahi, const __nv_bfloat16* __restrict__ Alo,
    const __nv_bfloat16* __restrict__ Bhi, const __nv_bfloat16* __restrict__ Blo,
    const float* __restrict__ bias, const float* __restrict__ res,
    float* __restrict__ C, __nv_bfloat16* __restrict__ Chi, __nv_bfloat16* __restrict__ Clo,
    int M, int N, int K)
{
    extern __shared__ __align__(1024) char smem[];
    const uint32_t sb = smem_u32(smem);
    const int tid = threadIdx.x, lane = tid & 31, wid = tid >> 5;
    const int wm = wid >> 1, wn = wid & 1;
    const int bm = blockIdx.y * 128, bn = blockIdx.x * 64;

    float acc[2][4][4];
    #pragma unroll
    for (int mt = 0; mt < 2; mt++)
        #pragma unroll
        for (int nt = 0; nt < 4; nt++)
            #pragma unroll
            for (int i = 0; i < 4; i++) acc[mt][nt][i] = 0.0f;

    auto fill = [&](int s, int kt) {
        char* st = smem + s * STAGE_BYTES;
        const int k0 = kt << 6;
        #pragma unroll
        for (int i = 0; i < 4; i++) {
            const int idx = tid + i * 256;
            const int row = idx >> 3, c16 = idx & 7;
            const uint32_t sw = SWZ128((uint32_t)((row << 7) + (c16 << 4)));
            const size_t ga = (size_t)(bm + row) * K + k0 + c16 * 8;
            cp16(st + sw,         Ahi + ga);
            cp16(st + 16384 + sw, Alo + ga);
        }
        #pragma unroll
        for (int i = 0; i < 2; i++) {
            const int idx = tid + i * 256;
            const int row = idx >> 3, c16 = idx & 7;
            const uint32_t sw = SWZ128((uint32_t)((row << 7) + (c16 << 4)));
            const size_t gb = (size_t)(bn + row) * K + k0 + c16 * 8;
            cp16(st + 32768 + sw, Bhi + gb);
            cp16(st + 40960 + sw, Blo + gb);
        }
    };

    const int laneRA = lane & 15;
    const int laneCA = (lane >> 4) << 4;
    const int laneRB = (lane & 7) + ((lane >> 4) << 3);
    const int laneCB = ((lane >> 3) & 1) << 4;

    const int niter = K >> 6;
    fill(0, 0); CP_COMMIT();

    for (int it = 0; it < niter; it++) {
        const int s = it & 1;
        if (it + 1 < niter) {
            fill(s ^ 1, it + 1); CP_COMMIT();
            asm volatile("cp.async.wait_group 1;" ::: "memory");
        } else {
            asm volatile("cp.async.wait_group 0;" ::: "memory");
        }
        __syncthreads();

        const uint32_t aH = sb + s * STAGE_BYTES;
        const uint32_t aL = aH + 16384;
        const uint32_t bH = aH + 32768;
        const uint32_t bL = aH + 40960;

        #pragma unroll
        for (int k16 = 0; k16 < 4; k16++) {
            const int kb = k16 * 32;
            uint32_t ah[2][4], al[2][4], bh[4][2], bl[4][2];
            #pragma unroll
            for (int mt = 0; mt < 2; mt++) {
                const uint32_t off = SWZ128(
                    (uint32_t)(((wm * 32 + mt * 16 + laneRA) << 7) + kb + laneCA));
                ldsm4(ah[mt], aH + off);
                ldsm4(al[mt], aL + off);
            }
            #pragma unroll
            for (int j = 0; j < 2; j++) {
                const uint32_t off = SWZ128(
                    (uint32_t)(((wn * 32 + j * 16 + laneRB) << 7) + kb + laneCB));
                ldsm4(&bh[j * 2][0], bH + off);
                ldsm4(&bl[j * 2][0], bL + off);
            }
            #pragma unroll
            for (int mt = 0; mt < 2; mt++)
                #pragma unroll
                for (int nt = 0; nt < 4; nt++) mma16816(acc[mt][nt], ah[mt], bh[nt]);
            #pragma unroll
            for (int mt = 0; mt < 2; mt++)
                #pragma unroll
                for (int nt = 0; nt < 4; nt++) mma16816(acc[mt][nt], ah[mt], bl[nt]);
            #pragma unroll
            for (int mt = 0; mt < 2; mt++)
                #pragma unroll
                for (int nt = 0; nt < 4; nt++) mma16816(acc[mt][nt], al[mt], bh[nt]);
        }
        __syncthreads();
    }

    const int g = lane >> 2, t = lane & 3;
    #pragma unroll
    for (int mt = 0; mt < 2; mt++) {
        #pragma unroll
        for (int nt = 0; nt < 4; nt++) {
            const int col = bn + wn * 32 + nt * 8 + 2 * t;
            #pragma unroll
            for (int half = 0; half < 2; half++) {
                const int row = bm + wm * 32 + mt * 16 + g + half * 8;
                float v0 = acc[mt][nt][2 * half + 0];
                float v1 = acc[mt][nt][2 * half + 1];
                if (bias) { v0 += bias[col]; v1 += bias[col + 1]; }
                const size_t o = (size_t)row * N + col;
                if (EPI == EPI_GELU) {
                    v0 = 0.5f * v0 * (1.0f + erff(v0 * 0.70710678118654752f));
                    v1 = 0.5f * v1 * (1.0f + erff(v1 * 0.70710678118654752f));
                    __nv_bfloat16 h0, l0, h1, l1;
                    split_bf16(v0, h0, l0);
                    split_bf16(v1, h1, l1);
                    *(__nv_bfloat162*)(Chi + o) = __halves2bfloat162(h0, h1);
                    *(__nv_bfloat162*)(Clo + o) = __halves2bfloat162(l0, l1);
                } else {
                    if (EPI == EPI_RES) {
                        const float2 r2 = *(const float2*)(res + o);
                        v0 += r2.x; v1 += r2.y;
                    }
                    *(float2*)(C + o) = make_float2(v0, v1);
                }
            }
        }
    }
}

// ---------------- causal flash attention on tensor cores -------------------------
// Block: 128 threads (4 warps), 128 queries. K-tile = 64 keys.
// QK: Q(A,hi/lo validated path) x K[key][dim](B path, no transpose), 3 products.
// PV: P via C->A fragment identity (regs), V transposed into smem (B path), 3 products.
#define ATTN_SMEM_BYTES 65536

__global__ __launch_bounds__(128) void attn_mma_kernel(
    const float* __restrict__ qkv,
    __nv_bfloat16* __restrict__ ohi, __nv_bfloat16* __restrict__ olo)
{
    extern __shared__ __align__(1024) char asmem[];
    char* Qh = asmem;                 // 128 x 128B
    char* Ql = asmem + 16384;
    char* Kh = asmem + 32768;         // 64 x 128B
    char* Kl = asmem + 40960;
    char* Vh = asmem + 49152;         // Vt[d][key] 64 x 128B
    char* Vl = asmem + 57344;
    const uint32_t uQh = smem_u32(Qh), uQl = smem_u32(Ql);
    const uint32_t uKh = smem_u32(Kh), uKl = smem_u32(Kl);
    const uint32_t uVh = smem_u32(Vh), uVl = smem_u32(Vl);

    const int qt = blockIdx.x, h = blockIdx.y, b = blockIdx.z;
    const int tid = threadIdx.x, lane = tid & 31, w = tid >> 5;
    const int g = lane >> 2, t = lane & 3;
    const int qBase = qt * 128;

    const float* qpB = qkv + (size_t)b * SEQ * (3 * DMODEL) + h * HEADDIM;
    const float* kpB = qpB + DMODEL;
    const float* vpB = qpB + 2 * DMODEL;

    // ---- Q tile: 128 rows x 64 dims -> bf16 hi/lo, SWZ128 rows ----
    {
        const float* qrow = qpB + (size_t)(qBase + tid) * (3 * DMODEL);
        #pragma unroll
        for (int i = 0; i < 16; i++) {
            const float4 v = *(const float4*)(qrow + 4 * i);
            __nv_bfloat16 h0,l0,h1,l1,h2,l2,h3,l3;
            split_bf16(v.x,h0,l0); split_bf16(v.y,h1,l1);
            split_bf16(v.z,h2,l2); split_bf16(v.w,h3,l3);
            const uint32_t sw = SWZ128((uint32_t)(tid * 128 + i * 8));
            *(uint32_t*)(Qh + sw)     = packbf(h0, h1);
            *(uint32_t*)(Qh + sw + 4) = packbf(h2, h3);
            *(uint32_t*)(Ql + sw)     = packbf(l0, l1);
            *(uint32_t*)(Ql + sw + 4) = packbf(l2, l3);
        }
    }

    float m_s[4], l_s[4];
    #pragma unroll
    for (int r = 0; r < 4; r++) { m_s[r] = -INFINITY; l_s[r] = 0.0f; }
    float acc_o[2][8][4];
    #pragma unroll
    for (int mt = 0; mt < 2; mt++)
        #pragma unroll
        for (int j = 0; j < 8; j++)
            #pragma unroll
            for (int i = 0; i < 4; i++) acc_o[mt][j][i] = 0.0f;

    const int laneRA = lane & 15;
    const int laneCA = (lane >> 4) << 4;
    const int laneRB = (lane & 7) + ((lane >> 4) << 3);
    const int laneCB = ((lane >> 3) & 1) << 4;

    const int nkt = 2 * qt + 2;
    for (int kt = 0; kt < nkt; kt++) {
        __syncthreads();   // previous tile's smem reads complete
        // ---- K,V tile load+split: 64 keys x 64 dims; V transposed ----
        {
            const int key = tid >> 1, hf = tid & 1;
            const float* krow = kpB + (size_t)(kt * 64 + key) * (3 * DMODEL) + hf * 32;
            const float* vrow = vpB + (size_t)(kt * 64 + key) * (3 * DMODEL) + hf * 32;
            #pragma unroll
            for (int i = 0; i < 8; i++) {
                const int d = hf * 32 + 4 * i;
                const float4 kv = *(const float4*)(krow + 4 * i);
                __nv_bfloat16 h0,l0,h1,l1,h2,l2,h3,l3;
                split_bf16(kv.x,h0,l0); split_bf16(kv.y,h1,l1);
                split_bf16(kv.z,h2,l2); split_bf16(kv.w,h3,l3);
                const uint32_t sw = SWZ128((uint32_t)(key * 128 + d * 2));
                *(uint32_t*)(Kh + sw)     = packbf(h0, h1);
                *(uint32_t*)(Kh + sw + 4) = packbf(h2, h3);
                *(uint32_t*)(Kl + sw)     = packbf(l0, l1);
                *(uint32_t*)(Kl + sw + 4) = packbf(l2, l3);

                const float4 vv = *(const float4*)(vrow + 4 * i);
                const float vf[4] = {vv.x, vv.y, vv.z, vv.w};
                #pragma unroll
                for (int c = 0; c < 4; c++) {
                    __nv_bfloat16 vh_, vl_;
                    split_bf16(vf[c], vh_, vl_);
                    const uint32_t swv = SWZ128((uint32_t)((d + c) * 128 + key * 2));
                    *(__nv_bfloat16*)(Vh + swv) = vh_;
                    *(__nv_bfloat16*)(Vl + swv) = vl_;
                }
            }
        }
        __syncthreads();

        // ---- S = Q K^T (scaled later) ----
        float s[2][8][4];
        #pragma unroll
        for (int mt = 0; mt < 2; mt++)
            #pragma unroll
            for (int j = 0; j < 8; j++)
                #pragma unroll
                for (int i = 0; i < 4; i++) s[mt][j][i] = 0.0f;

        #pragma unroll
        for (int kk = 0; kk < 4; kk++) {
            const int kb = kk * 32;
            uint32_t qh[2][4], ql[2][4], kh[8][2], kl[8][2];
            #pragma unroll
            for (int mt = 0; mt < 2; mt++) {
                const uint32_t off = SWZ128(
                    (uint32_t)(((w * 32 + mt * 16 + laneRA) << 7) + kb + laneCA));
                ldsm4(qh[mt], uQh + off);
                ldsm4(ql[mt], uQl + off);
            }
            #pragma unroll
            for (int j = 0; j < 4; j++) {
                const uint32_t off = SWZ128(
                    (uint32_t)(((j * 16 + laneRB) << 7) + kb + laneCB));
                ldsm4(&kh[j * 2][0], uKh + off);
                ldsm4(&kl[j * 2][0], uKl + off);
            }
            #pragma unroll
            for (int mt = 0; mt < 2; mt++)
                #pragma unroll
                for (int n = 0; n < 8; n++) mma16816(s[mt][n], qh[mt], kh[n]);
            #pragma unroll
            for (int mt = 0; mt < 2; mt++)
                #pragma unroll
                for (int n = 0; n < 8; n++) mma16816(s[mt][n], qh[mt], kl[n]);
            #pragma unroll
            for (int mt = 0; mt < 2; mt++)
                #pragma unroll
                for (int n = 0; n < 8; n++) mma16816(s[mt][n], ql[mt], kh[n]);
        }

        // ---- online softmax in fragments (rows: g within quad; shfl over t) ----
        const int k0g = kt * 64;
        #pragma unroll
        for (int mt = 0; mt < 2; mt++) {
            #pragma unroll
            for (int half = 0; half < 2; half++) {
                const int qrow = qBase + w * 32 + mt * 16 + g + half * 8;
                const int r = mt * 2 + half;
                float tmax = -INFINITY;
                #pragma unroll
                for (int j = 0; j < 8; j++) {
                    const int key = k0g + j * 8 + 2 * t;
                    float v0 = s[mt][j][2 * half]     * 0.125f;
                    float v1 = s[mt][j][2 * half + 1] * 0.125f;
                    v0 = (key     <= qrow) ? v0 : -INFINITY;
                    v1 = (key + 1 <= qrow) ? v1 : -INFINITY;
                    s[mt][j][2 * half]     = v0;
                    s[mt][j][2 * half + 1] = v1;
                    tmax = fmaxf(tmax, fmaxf(v0, v1));
                }
                tmax = fmaxf(tmax, __shfl_xor_sync(0xffffffffu, tmax, 1));
                tmax = fmaxf(tmax, __shfl_xor_sync(0xffffffffu, tmax, 2));
                const float mnew = fmaxf(m_s[r], tmax);
                const float corr = __expf(m_s[r] - mnew);
                float lsum = 0.0f;
                #pragma unroll
                for (int j = 0; j < 8; j++) {
                    const float e0 = __expf(s[mt][j][2 * half]     - mnew);
                    const float e1 = __expf(s[mt][j][2 * half + 1] - mnew);
                    s[mt][j][2 * half]     = e0;
                    s[mt][j][2 * half + 1] = e1;
                    lsum += e0 + e1;
                }
                lsum += __shfl_xor_sync(0xffffffffu, lsum, 1);
                lsum += __shfl_xor_sync(0xffffffffu, lsum, 2);
                l_s[r] = l_s[r] * corr + lsum;
                m_s[r] = mnew;
                #pragma unroll
                for (int j = 0; j < 8; j++) {
                    acc_o[mt][j][2 * half]     *= corr;
                    acc_o[mt][j][2 * half + 1] *= corr;
                }
            }
        }

        // ---- O += P V  (P from S fragments via C->A identity) ----
        #pragma unroll
        for (int kk = 0; kk < 4; kk++) {
            uint32_t aPh[2][4], aPl[2][4];
            #pragma unroll
            for (int mt = 0; mt < 2; mt++) {
                #pragma unroll
                for (int half2 = 0; half2 < 2; half2++) {   // which n8 of the k16
                    const int j = 2 * kk + half2;
                    __nv_bfloat16 h0,l0,h1,l1,h2,l2,h3,l3;
                    split_bf16(s[mt][j][0], h0, l0);
                    split_bf16(s[mt][j][1], h1, l1);
                    split_bf16(s[mt][j][2], h2, l2);
                    split_bf16(s[mt][j][3], h3, l3);
                    aPh[mt][2 * half2]     = packbf(h0, h1);   // rows g,   keys lo
                    aPh[mt][2 * half2 + 1] = packbf(h2, h3);   // rows g+8
                    aPl[mt][2 * half2]     = packbf(l0, l1);
                    aPl[mt][2 * half2 + 1] = packbf(l2, l3);
                }
            }
            uint32_t vh[8][2], vl[8][2];
            #pragma unroll
            for (int j = 0; j < 4; j++) {
                const uint32_t off = SWZ128(
                    (uint32_t)(((j * 16 + laneRB) << 7) + kk * 32 + laneCB));
                ldsm4(&vh[j * 2][0], uVh + off);
                ldsm4(&vl[j * 2][0], uVl + off);
            }
            #pragma unroll
            for (int mt = 0; mt < 2; mt++)
                #pragma unroll
                for (int n = 0; n < 8; n++) mma16816(acc_o[mt][n], aPh[mt], vh[n]);
            #pragma unroll
            for (int mt = 0; mt < 2; mt++)
                #pragma unroll
                for (int n = 0; n < 8; n++) mma16816(acc_o[mt][n], aPh[mt], vl[n]);
            #pragma unroll
            for (int mt = 0; mt < 2; mt++)
                #pragma unroll
                for (int n = 0; n < 8; n++) mma16816(acc_o[mt][n], aPl[mt], vh[n]);
        }
    }

    // ---- epilogue: normalize, split bf16, store ----
    #pragma unroll
    for (int mt = 0; mt < 2; mt++) {
        #pragma unroll
        for (int half = 0; half < 2; half++) {
            const int qrow = qBase + w * 32 + mt * 16 + g + half * 8;
            const float inv = 1.0f / l_s[mt * 2 + half];
            const size_t obase = ((size_t)b * SEQ + qrow) * DMODEL + h * HEADDIM;
            #pragma unroll
            for (int j = 0; j < 8; j++) {
                const float v0 = acc_o[mt][j][2 * half]     * inv;
                const float v1 = acc_o[mt][j][2 * half + 1] * inv;
                __nv_bfloat16 h0, l0, h1, l1;
                split_bf16(v0, h0, l0);
                split_bf16(v1, h1, l1);
                const size_t o = obase + j * 8 + 2 * t;
                *(__nv_bfloat162*)(ohi + o) = __halves2bfloat162(h0, h1);
                *(__nv_bfloat162*)(olo + o) = __halves2bfloat162(l0, l1);
            }
        }
    }
}

// ---------------- loss ----------------
__global__ __launch_bounds__(256) void loss_token_kernel(
    const float* __restrict__ logits, const int* __restrict__ targets,
    const void* __restrict__ vmask,
    float* __restrict__ tce, float* __restrict__ tw)
{
    const int row = blockIdx.x;
    const float* lr = logits + (size_t)row * VOCAB;
    float v[16];
    #pragma unroll
    for (int i = 0; i < 16; i++) v[i] = lr[threadIdx.x + 256 * i];
    float mx = v[0];
    #pragma unroll
    for (int i = 1; i < 16; i++) mx = fmaxf(mx, v[i]);
    mx = blockReduceMax(mx);
    float se = 0.0f;
    #pragma unroll
    for (int i = 0; i < 16; i++) se += __expf(v[i] - mx);
    se = blockReduceSum(se);
    if (threadIdx.x == 0) {
        const int tgt = targets[row];
        const float lse = mx + logf(se);
        const float nll = lse - lr[tgt];
        int mv;
        if (g_mflag) mv = ((const unsigned char*)vmask)[row];
        else         mv = ((const int*)vmask)[row];
        const float w = 1.0f + 4.0f * ((mv != 0) ? 1.0f : 0.0f);
        tce[row] = (tgt == 0) ? 0.0f : nll * w;
        tw[row]  = w;
    }
}

__global__ __launch_bounds__(256) void loss_final_kernel(
    const float* __restrict__ tce, const float* __restrict__ tw, float* __restrict__ out)
{
    float a = 0.0f, b = 0.0f;
    for (int i = threadIdx.x; i < MTOK; i += 256) { a += tce[i]; b += tw[i]; }
    a = blockReduceSum(a);
    b = blockReduceSum(b);
    if (threadIdx.x == 0) out[0] = a / b;
}

// ---------------- host driver ----------------
extern "C" void kernel_launch(void* const* d_in, const int* in_sizes, int n_in,
                              void* d_out, int out_size)
{
    (void)in_sizes; (void)n_in;
    const int*   ids   = (const int*)d_in[0];
    const int*   tgts  = (const int*)d_in[1];
    const void*  vmask = (const void*)d_in[2];
    const float* tok   = (const float*)d_in[3];
    const float* pos   = (const float*)d_in[4];
    const float* ln1w  = (const float*)d_in[5];
    const float* ln1b  = (const float*)d_in[6];
    const float* wqkv  = (const float*)d_in[7];
    const float* bqkv  = (const float*)d_in[8];
    const float* wproj = (const float*)d_in[9];
    const float* bproj = (const float*)d_in[10];
    const float* ln2w  = (const float*)d_in[11];
    const float* ln2b  = (const float*)d_in[12];
    const float* w1    = (const float*)d_in[13];
    const float* b1    = (const float*)d_in[14];
    const float* w2    = (const float*)d_in[15];
    const float* b2    = (const float*)d_in[16];
    const float* lnfw  = (const float*)d_in[17];
    const float* lnfb  = (const float*)d_in[18];
    float* out = (float*)d_out;

    float *x, *qkv, *tce, *tw;
    __nv_bfloat16 *hhi, *hlo, *mhi, *mlo;
    __nv_bfloat16 *wq_hi, *wq_lo, *wp_hi, *wp_lo, *w1_hi, *w1_lo, *w2_hi, *w2_lo, *lm_hi, *lm_lo;
    cudaGetSymbolAddress((void**)&x,    g_x);
    cudaGetSymbolAddress((void**)&qkv,  g_qkv);
    cudaGetSymbolAddress((void**)&hhi,  g_hhi);
    cudaGetSymbolAddress((void**)&hlo,  g_hlo);
    cudaGetSymbolAddress((void**)&mhi,  g_mhi);
    cudaGetSymbolAddress((void**)&mlo,  g_mlo);
    cudaGetSymbolAddress((void**)&wq_hi, g_wqkv_hi);
    cudaGetSymbolAddress((void**)&wq_lo, g_wqkv_lo);
    cudaGetSymbolAddress((void**)&wp_hi, g_wproj_hi);
    cudaGetSymbolAddress((void**)&wp_lo, g_wproj_lo);
    cudaGetSymbolAddress((void**)&w1_hi, g_w1_hi);
    cudaGetSymbolAddress((void**)&w1_lo, g_w1_lo);
    cudaGetSymbolAddress((void**)&w2_hi, g_w2_hi);
    cudaGetSymbolAddress((void**)&w2_lo, g_w2_lo);
    cudaGetSymbolAddress((void**)&lm_hi, g_lmh_hi);
    cudaGetSymbolAddress((void**)&lm_lo, g_lmh_lo);
    cudaGetSymbolAddress((void**)&tce,  g_tce);
    cudaGetSymbolAddress((void**)&tw,   g_tw);

    cudaFuncSetAttribute(gemm_ldsm_kernel<EPI_NONE>,
                         cudaFuncAttributeMaxDynamicSharedMemorySize, GEMM_SMEM_BYTES);
    cudaFuncSetAttribute(gemm_ldsm_kernel<EPI_RES>,
                         cudaFuncAttributeMaxDynamicSharedMemorySize, GEMM_SMEM_BYTES);
    cudaFuncSetAttribute(gemm_ldsm_kernel<EPI_GELU>,
                         cudaFuncAttributeMaxDynamicSharedMemorySize, GEMM_SMEM_BYTES);
    cudaFuncSetAttribute(attn_mma_kernel,
                         cudaFuncAttributeMaxDynamicSharedMemorySize, ATTN_SMEM_BYTES);

    // ---- pack weights: [K][N] fp32 -> [N][K] bf16 hi/lo ----
    convw_nt<<<dim3(3*DMODEL/32, DMODEL/32, NLAYER), 256>>>(wqkv,  wq_hi, wq_lo, DMODEL, 3*DMODEL);
    convw_nt<<<dim3(DMODEL/32,   DMODEL/32, NLAYER), 256>>>(wproj, wp_hi, wp_lo, DMODEL, DMODEL);
    convw_nt<<<dim3(DFF/32,      DMODEL/32, NLAYER), 256>>>(w1,    w1_hi, w1_lo, DMODEL, DFF);
    convw_nt<<<dim3(DMODEL/32,   DFF/32,    NLAYER), 256>>>(w2,    w2_hi, w2_lo, DFF,    DMODEL);
    convsplit<<<VOCAB*DMODEL/256, 256>>>(tok, lm_hi, lm_lo);

    detect_mask_kernel<<<1, 256>>>((const unsigned char*)vmask);
    embed_kernel<<<MTOK, 256>>>(ids, tok, pos, x);

    const size_t wq_s = (size_t)3*DMODEL*DMODEL;
    const size_t wp_s = (size_t)DMODEL*DMODEL;
    const size_t w1_s = (size_t)DFF*DMODEL;
    const size_t w2_s = (size_t)DMODEL*DFF;

    for (int l = 0; l < NLAYER; l++) {
        ln_bf16_kernel<<<MTOK, 256>>>(x, ln1w + l*DMODEL, ln1b + l*DMODEL, hhi, hlo);

        gemm_ldsm_kernel<EPI_NONE><<<dim3(3*DMODEL/64, MTOK/128), 256, GEMM_SMEM_BYTES>>>(
            hhi, hlo, wq_hi + l*wq_s, wq_lo + l*wq_s,
            bqkv + (size_t)l*3*DMODEL, nullptr, qkv, nullptr, nullptr,
            MTOK, 3*DMODEL, DMODEL);

        attn_mma_kernel<<<dim3(SEQ/128, NHEAD, BATCH), 128, ATTN_SMEM_BYTES>>>(qkv, hhi, hlo);

        gemm_ldsm_kernel<EPI_RES><<<dim3(DMODEL/64, MTOK/128), 256, GEMM_SMEM_BYTES>>>(
            hhi, hlo, wp_hi + l*wp_s, wp_lo + l*wp_s,
            bproj + (size_t)l*DMODEL, x, x, nullptr, nullptr,
            MTOK, DMODEL, DMODEL);

        ln_bf16_kernel<<<MTOK, 256>>>(x, ln2w + l*DMODEL, ln2b + l*DMODEL, hhi, hlo);

        gemm_ldsm_kernel<EPI_GELU><<<dim3(DFF/64, MTOK/128), 256, GEMM_SMEM_BYTES>>>(
            hhi, hlo, w1_hi + l*w1_s, w1_lo + l*w1_s,
            b1 + (size_t)l*DFF, nullptr, nullptr, mhi, mlo,
            MTOK, DFF, DMODEL);

        gemm_ldsm_kernel<EPI_RES><<<dim3(DMODEL/64, MTOK/128), 256, GEMM_SMEM_BYTES>>>(
            mhi, mlo, w2_hi + l*w2_s, w2_lo + l*w2_s,
            b2 + (size_t)l*DMODEL, x, x, nullptr, nullptr,
            MTOK, DMODEL, DFF);
    }

    ln_bf16_kernel<<<MTOK, 256>>>(x, lnfw, lnfb, hhi, hlo);

    gemm_ldsm_kernel<EPI_NONE><<<dim3(VOCAB/64, MTOK/128), 256, GEMM_SMEM_BYTES>>>(
        hhi, hlo, lm_hi, lm_lo, nullptr, nullptr, out, nullptr, nullptr,
        MTOK, VOCAB, DMODEL);

    if (out_size > MTOK * VOCAB) {
        loss_token_kernel<<<MTOK, 256>>>(out, tgts, vmask, tce, tw);
        loss_final_kernel<<<1, 256>>>(tce, tw, out + (size_t)MTOK * VOCAB);
    }
}

// round 16
// speedup vs baseline: 4.1658x; 1.2286x over previous
#include <cuda_runtime.h>
#include <cuda_bf16.h>
#include <cuda_fp16.h>
#include <math.h>
#include <stdint.h>

// ---------------- problem constants ----------------
#define NLAYER   8
#define DMODEL   1024
#define NHEAD    16
#define HEADDIM  64
#define DFF      4096
#define VOCAB    4096
#define BATCH    4
#define SEQ      2048
#define MTOK     (BATCH*SEQ)      // 8192 tokens

// ---------------- scratch (device globals; no allocation allowed) ----------------
__device__ float g_x  [MTOK*DMODEL];       // residual stream (fp32)
__device__ float g_qkv[MTOK*3*DMODEL];     // qkv (fp32, attention input)
__device__ __half g_hhi[MTOK*DMODEL];      // activation hi/lo (fp16)
__device__ __half g_hlo[MTOK*DMODEL];
__device__ __half g_mhi[MTOK*DFF];
__device__ __half g_mlo[MTOK*DFF];
// layer weights: fp16 single-precision, N-major [L][N][K]
__device__ __half g_wqkv_h[NLAYER*3*DMODEL*DMODEL];
__device__ __half g_wproj_h[NLAYER*DMODEL*DMODEL];
__device__ __half g_w1_h[NLAYER*DFF*DMODEL];
__device__ __half g_w2_h[NLAYER*DMODEL*DFF];
// lm_head: fp16 hi/lo (3-product for logits accuracy)
__device__ __half g_lmh_hi[VOCAB*DMODEL];
__device__ __half g_lmh_lo[VOCAB*DMODEL];
__device__ float g_tce[MTOK];
__device__ float g_tw [MTOK];
__device__ int   g_mflag;

// ---------------- block reductions ----------------
__device__ __forceinline__ float blockReduceSum(float val) {
    __shared__ float sh[32];
    const int lane = threadIdx.x & 31, wid = threadIdx.x >> 5;
    #pragma unroll
    for (int o = 16; o; o >>= 1) val += __shfl_xor_sync(0xffffffffu, val, o);
    if (lane == 0) sh[wid] = val;
    __syncthreads();
    const int nw = (blockDim.x + 31) >> 5;
    float t = (threadIdx.x < nw) ? sh[threadIdx.x] : 0.0f;
    #pragma unroll
    for (int o = 16; o; o >>= 1) t += __shfl_xor_sync(0xffffffffu, t, o);
    if (threadIdx.x == 0) sh[0] = t;
    __syncthreads();
    t = sh[0];
    __syncthreads();
    return t;
}

__device__ __forceinline__ float blockReduceMax(float val) {
    __shared__ float sh[32];
    const int lane = threadIdx.x & 31, wid = threadIdx.x >> 5;
    #pragma unroll
    for (int o = 16; o; o >>= 1) val = fmaxf(val, __shfl_xor_sync(0xffffffffu, val, o));
    if (lane == 0) sh[wid] = val;
    __syncthreads();
    const int nw = (blockDim.x + 31) >> 5;
    float t = (threadIdx.x < nw) ? sh[threadIdx.x] : -INFINITY;
    #pragma unroll
    for (int o = 16; o; o >>= 1) t = fmaxf(t, __shfl_xor_sync(0xffffffffu, t, o));
    if (threadIdx.x == 0) sh[0] = t;
    __syncthreads();
    t = sh[0];
    __syncthreads();
    return t;
}

// ---------------- helpers ----------------
__device__ __forceinline__ void split_bf16(float a, __nv_bfloat16& hi, __nv_bfloat16& lo) {
    hi = __float2bfloat16(a);
    lo = __float2bfloat16(a - __bfloat162float(hi));
}
__device__ __forceinline__ void split_h(float a, __half& hi, __half& lo) {
    hi = __float2half_rn(a);
    lo = __float2half_rn(a - __half2float(hi));
}
__device__ __forceinline__ uint32_t packbf(__nv_bfloat16 c0, __nv_bfloat16 c1) {
    return (uint32_t)__bfloat16_as_ushort(c0) | ((uint32_t)__bfloat16_as_ushort(c1) << 16);
}
__device__ __forceinline__ uint32_t packh(__half c0, __half c1) {
    return (uint32_t)__half_as_ushort(c0) | ((uint32_t)__half_as_ushort(c1) << 16);
}

__device__ __forceinline__ void cp16(void* sdst, const void* gsrc) {
    uint32_t sa = (uint32_t)__cvta_generic_to_shared(sdst);
    asm volatile("cp.async.cg.shared.global [%0], [%1], 16;" :: "r"(sa), "l"(gsrc));
}
#define CP_COMMIT() asm volatile("cp.async.commit_group;" ::: "memory")

__device__ __forceinline__ uint32_t smem_u32(const void* p) {
    return (uint32_t)__cvta_generic_to_shared(p);
}

#define SWZ128(off) ((off) ^ (((off) >> 3) & 0x70))

__device__ __forceinline__ void mma16816bf(float* d, const uint32_t* a, const uint32_t* b) {
    asm volatile(
        "mma.sync.aligned.m16n8k16.row.col.f32.bf16.bf16.f32 "
        "{%0,%1,%2,%3}, {%4,%5,%6,%7}, {%8,%9}, {%0,%1,%2,%3};"
        : "+f"(d[0]), "+f"(d[1]), "+f"(d[2]), "+f"(d[3])
        : "r"(a[0]), "r"(a[1]), "r"(a[2]), "r"(a[3]), "r"(b[0]), "r"(b[1]));
}
__device__ __forceinline__ void mma16816h(float* d, const uint32_t* a, const uint32_t* b) {
    asm volatile(
        "mma.sync.aligned.m16n8k16.row.col.f32.f16.f16.f32 "
        "{%0,%1,%2,%3}, {%4,%5,%6,%7}, {%8,%9}, {%0,%1,%2,%3};"
        : "+f"(d[0]), "+f"(d[1]), "+f"(d[2]), "+f"(d[3])
        : "r"(a[0]), "r"(a[1]), "r"(a[2]), "r"(a[3]), "r"(b[0]), "r"(b[1]));
}

__device__ __forceinline__ void ldsm4(uint32_t* r, uint32_t addr) {
    asm volatile("ldmatrix.sync.aligned.m8n8.x4.shared.b16 {%0,%1,%2,%3}, [%4];"
                 : "=r"(r[0]), "=r"(r[1]), "=r"(r[2]), "=r"(r[3]) : "r"(addr));
}

// ---------------- weight pack kernels ----------------
// W [K][N] fp32 -> Wh fp16 [N][K] (tiled transpose)
__global__ __launch_bounds__(256) void convw_h(
    const float* __restrict__ W, __half* __restrict__ Wh, int K, int N)
{
    __shared__ float tile[32][33];
    const int tx = threadIdx.x & 31, ty = threadIdx.x >> 5;
    const int n0 = blockIdx.x * 32, k0 = blockIdx.y * 32;
    const int l = blockIdx.z;
    const float* Wl = W + (size_t)l * K * N;
    #pragma unroll
    for (int i = ty; i < 32; i += 8)
        tile[i][tx] = Wl[(size_t)(k0 + i) * N + n0 + tx];
    __syncthreads();
    __half* Hl = Wh + (size_t)l * N * K;
    #pragma unroll
    for (int i = ty; i < 32; i += 8)
        Hl[(size_t)(n0 + i) * K + k0 + tx] = __float2half_rn(tile[tx][i]);
}

// lm_head split (tok already [V][K])
__global__ __launch_bounds__(256) void convsplit(
    const float* __restrict__ W, __half* __restrict__ hi, __half* __restrict__ lo)
{
    const int i = blockIdx.x * 256 + threadIdx.x;
    __half h, l;
    split_h(W[i], h, l);
    hi[i] = h; lo[i] = l;
}

// ---------------- value_mask dtype probe ----------------
__global__ __launch_bounds__(256) void detect_mask_kernel(const unsigned char* __restrict__ m)
{
    __shared__ int sh[32];
    int s = 0;
    for (int i = threadIdx.x; i < 8192; i += 256)
        if (i & 3) s += m[i];
    #pragma unroll
    for (int o = 16; o; o >>= 1) s += __shfl_xor_sync(0xffffffffu, s, o);
    const int lane = threadIdx.x & 31, wid = threadIdx.x >> 5;
    if (lane == 0) sh[wid] = s;
    __syncthreads();
    if (threadIdx.x < 8) {
        int t = sh[threadIdx.x];
        #pragma unroll
        for (int o = 4; o; o >>= 1) t += __shfl_xor_sync(0xffu, t, o);
        if (threadIdx.x == 0) g_mflag = (t != 0) ? 1 : 0;
    }
}

// ---------------- embed ----------------
__global__ __launch_bounds__(256) void embed_kernel(
    const int* __restrict__ ids, const float* __restrict__ tok,
    const float* __restrict__ pos, float* __restrict__ x)
{
    const int m = blockIdx.x;
    const int t = m & (SEQ - 1);
    const int id = ids[m];
    const float4 a = ((const float4*)(tok + (size_t)id * DMODEL))[threadIdx.x];
    const float4 b = ((const float4*)(pos + (size_t)t  * DMODEL))[threadIdx.x];
    ((float4*)(x + (size_t)m * DMODEL))[threadIdx.x] =
        make_float4(a.x + b.x, a.y + b.y, a.z + b.z, a.w + b.w);
}

// ---------------- layernorm -> split fp16 ----------------
__global__ __launch_bounds__(256) void ln_h_kernel(
    const float* __restrict__ x, const float* __restrict__ w,
    const float* __restrict__ b, __half* __restrict__ yhi,
    __half* __restrict__ ylo)
{
    const int row = blockIdx.x;
    const float4 v = ((const float4*)(x + (size_t)row * DMODEL))[threadIdx.x];
    float s = v.x + v.y + v.z + v.w;
    s = blockReduceSum(s);
    const float mu = s * (1.0f / DMODEL);
    const float d0 = v.x - mu, d1 = v.y - mu, d2 = v.z - mu, d3 = v.w - mu;
    float q = d0*d0 + d1*d1 + d2*d2 + d3*d3;
    q = blockReduceSum(q);
    const float rs = rsqrtf(q * (1.0f / DMODEL) + 1e-5f);
    const float4 w4 = ((const float4*)w)[threadIdx.x];
    const float4 b4 = ((const float4*)b)[threadIdx.x];
    float o0 = d0 * rs * w4.x + b4.x;
    float o1 = d1 * rs * w4.y + b4.y;
    float o2 = d2 * rs * w4.z + b4.z;
    float o3 = d3 * rs * w4.w + b4.w;
    __half h0,l0,h1,l1,h2,l2,h3,l3;
    split_h(o0,h0,l0); split_h(o1,h1,l1); split_h(o2,h2,l2); split_h(o3,h3,l3);
    const size_t base = (size_t)row * DMODEL + threadIdx.x * 4;
    *(__half2*)(yhi + base)     = __halves2half2(h0, h1);
    *(__half2*)(yhi + base + 2) = __halves2half2(h2, h3);
    *(__half2*)(ylo + base)     = __halves2half2(l0, l1);
    *(__half2*)(ylo + base + 2) = __halves2half2(l2, l3);
}

// ---------------- fp16 mma GEMM: 2-product (layers) / 3-product (lm_head) -------
// C = (Ahi+Alo)[M][K] @ Bh[N][K]^T  (+ Ahi@Blo when THREE), fp32 accum.
// CTA 128x64, warp tile 32x32, BK=64, 2-stage cp.async, 2 CTAs/SM.
enum { EPI_NONE = 0, EPI_RES = 1, EPI_GELU = 2 };

#define GEMM_SMEM_2P (2*40960)   // Ah 16K + Al 16K + Bh 8K per stage
#define GEMM_SMEM_3P (2*49152)   // + Bl 8K

template<int EPI, bool THREE>
__global__ __launch_bounds__(256, 2) void gemm_ldsm_kernel(
    const __half* __restrict__ Ahi, const __half* __restrict__ Alo,
    const __half* __restrict__ Bhi, const __half* __restrict__ Blo,
    const float* __restrict__ bias, const float* __restrict__ res,
    float* __restrict__ C, __half* __restrict__ Chi, __half* __restrict__ Clo,
    int M, int N, int K)
{
    constexpr int STB = THREE ? 49152 : 40960;
    extern __shared__ __align__(1024) char smem[];
    const uint32_t sb = smem_u32(smem);
    const int tid = threadIdx.x, lane = tid & 31, wid = tid >> 5;
    const int wm = wid >> 1, wn = wid & 1;
    const int bm = blockIdx.y * 128, bn = blockIdx.x * 64;

    float acc[2][4][4];
    #pragma unroll
    for (int mt = 0; mt < 2; mt++)
        #pragma unroll
        for (int nt = 0; nt < 4; nt++)
            #pragma unroll
            for (int i = 0; i < 4; i++) acc[mt][nt][i] = 0.0f;

    auto fill = [&](int s, int kt) {
        char* st = smem + s * STB;
        const int k0 = kt << 6;
        #pragma unroll
        for (int i = 0; i < 4; i++) {
            const int idx = tid + i * 256;
            const int row = idx >> 3, c16 = idx & 7;
            const uint32_t sw = SWZ128((uint32_t)((row << 7) + (c16 << 4)));
            const size_t ga = (size_t)(bm + row) * K + k0 + c16 * 8;
            cp16(st + sw,         Ahi + ga);
            cp16(st + 16384 + sw, Alo + ga);
        }
        #pragma unroll
        for (int i = 0; i < 2; i++) {
            const int idx = tid + i * 256;
            const int row = idx >> 3, c16 = idx & 7;
            const uint32_t sw = SWZ128((uint32_t)((row << 7) + (c16 << 4)));
            const size_t gb = (size_t)(bn + row) * K + k0 + c16 * 8;
            cp16(st + 32768 + sw, Bhi + gb);
            if (THREE) cp16(st + 40960 + sw, Blo + gb);
        }
    };

    const int laneRA = lane & 15;
    const int laneCA = (lane >> 4) << 4;
    const int laneRB = (lane & 7) + ((lane >> 4) << 3);
    const int laneCB = ((lane >> 3) & 1) << 4;

    const int niter = K >> 6;
    fill(0, 0); CP_COMMIT();

    for (int it = 0; it < niter; it++) {
        const int s = it & 1;
        if (it + 1 < niter) {
            fill(s ^ 1, it + 1); CP_COMMIT();
            asm volatile("cp.async.wait_group 1;" ::: "memory");
        } else {
            asm volatile("cp.async.wait_group 0;" ::: "memory");
        }
        __syncthreads();

        const uint32_t aH = sb + s * STB;
        const uint32_t aL = aH + 16384;
        const uint32_t bH = aH + 32768;
        const uint32_t bL = aH + 40960;

        #pragma unroll
        for (int k16 = 0; k16 < 4; k16++) {
            const int kb = k16 * 32;
            uint32_t ah[2][4], al[2][4], bh[4][2], bl[4][2];
            #pragma unroll
            for (int mt = 0; mt < 2; mt++) {
                const uint32_t off = SWZ128(
                    (uint32_t)(((wm * 32 + mt * 16 + laneRA) << 7) + kb + laneCA));
                ldsm4(ah[mt], aH + off);
                ldsm4(al[mt], aL + off);
            }
            #pragma unroll
            for (int j = 0; j < 2; j++) {
                const uint32_t off = SWZ128(
                    (uint32_t)(((wn * 32 + j * 16 + laneRB) << 7) + kb + laneCB));
                ldsm4(&bh[j * 2][0], bH + off);
                if (THREE) ldsm4(&bl[j * 2][0], bL + off);
            }
            #pragma unroll
            for (int mt = 0; mt < 2; mt++)
                #pragma unroll
                for (int nt = 0; nt < 4; nt++) mma16816h(acc[mt][nt], ah[mt], bh[nt]);
            if (THREE) {
                #pragma unroll
                for (int mt = 0; mt < 2; mt++)
                    #pragma unroll
                    for (int nt = 0; nt < 4; nt++) mma16816h(acc[mt][nt], ah[mt], bl[nt]);
            }
            #pragma unroll
            for (int mt = 0; mt < 2; mt++)
                #pragma unroll
                for (int nt = 0; nt < 4; nt++) mma16816h(acc[mt][nt], al[mt], bh[nt]);
        }
        __syncthreads();
    }

    const int g = lane >> 2, t = lane & 3;
    #pragma unroll
    for (int mt = 0; mt < 2; mt++) {
        #pragma unroll
        for (int nt = 0; nt < 4; nt++) {
            const int col = bn + wn * 32 + nt * 8 + 2 * t;
            #pragma unroll
            for (int half = 0; half < 2; half++) {
                const int row = bm + wm * 32 + mt * 16 + g + half * 8;
                float v0 = acc[mt][nt][2 * half + 0];
                float v1 = acc[mt][nt][2 * half + 1];
                if (bias) { v0 += bias[col]; v1 += bias[col + 1]; }
                const size_t o = (size_t)row * N + col;
                if (EPI == EPI_GELU) {
                    v0 = 0.5f * v0 * (1.0f + erff(v0 * 0.70710678118654752f));
                    v1 = 0.5f * v1 * (1.0f + erff(v1 * 0.70710678118654752f));
                    __half h0, l0, h1, l1;
                    split_h(v0, h0, l0);
                    split_h(v1, h1, l1);
                    *(__half2*)(Chi + o) = __halves2half2(h0, h1);
                    *(__half2*)(Clo + o) = __halves2half2(l0, l1);
                } else {
                    if (EPI == EPI_RES) {
                        const float2 r2 = *(const float2*)(res + o);
                        v0 += r2.x; v1 += r2.y;
                    }
                    *(float2*)(C + o) = make_float2(v0, v1);
                }
            }
        }
    }
}

// ---------------- causal flash attention on tensor cores (R15-validated) ---------
// Internals bf16 3-product (proven); epilogue writes fp16 hi/lo splits.
#define ATTN_SMEM_BYTES 65536

__global__ __launch_bounds__(128) void attn_mma_kernel(
    const float* __restrict__ qkv,
    __half* __restrict__ ohi, __half* __restrict__ olo)
{
    extern __shared__ __align__(1024) char asmem[];
    char* Qh = asmem;                 // 128 x 128B
    char* Ql = asmem + 16384;
    char* Kh = asmem + 32768;         // 64 x 128B
    char* Kl = asmem + 40960;
    char* Vh = asmem + 49152;         // Vt[d][key] 64 x 128B
    char* Vl = asmem + 57344;
    const uint32_t uQh = smem_u32(Qh), uQl = smem_u32(Ql);
    const uint32_t uKh = smem_u32(Kh), uKl = smem_u32(Kl);
    const uint32_t uVh = smem_u32(Vh), uVl = smem_u32(Vl);

    const int qt = blockIdx.x, h = blockIdx.y, b = blockIdx.z;
    const int tid = threadIdx.x, lane = tid & 31, w = tid >> 5;
    const int g = lane >> 2, t = lane & 3;
    const int qBase = qt * 128;

    const float* qpB = qkv + (size_t)b * SEQ * (3 * DMODEL) + h * HEADDIM;
    const float* kpB = qpB + DMODEL;
    const float* vpB = qpB + 2 * DMODEL;

    {
        const float* qrow = qpB + (size_t)(qBase + tid) * (3 * DMODEL);
        #pragma unroll
        for (int i = 0; i < 16; i++) {
            const float4 v = *(const float4*)(qrow + 4 * i);
            __nv_bfloat16 h0,l0,h1,l1,h2,l2,h3,l3;
            split_bf16(v.x,h0,l0); split_bf16(v.y,h1,l1);
            split_bf16(v.z,h2,l2); split_bf16(v.w,h3,l3);
            const uint32_t sw = SWZ128((uint32_t)(tid * 128 + i * 8));
            *(uint32_t*)(Qh + sw)     = packbf(h0, h1);
            *(uint32_t*)(Qh + sw + 4) = packbf(h2, h3);
            *(uint32_t*)(Ql + sw)     = packbf(l0, l1);
            *(uint32_t*)(Ql + sw + 4) = packbf(l2, l3);
        }
    }

    float m_s[4], l_s[4];
    #pragma unroll
    for (int r = 0; r < 4; r++) { m_s[r] = -INFINITY; l_s[r] = 0.0f; }
    float acc_o[2][8][4];
    #pragma unroll
    for (int mt = 0; mt < 2; mt++)
        #pragma unroll
        for (int j = 0; j < 8; j++)
            #pragma unroll
            for (int i = 0; i < 4; i++) acc_o[mt][j][i] = 0.0f;

    const int laneRA = lane & 15;
    const int laneCA = (lane >> 4) << 4;
    const int laneRB = (lane & 7) + ((lane >> 4) << 3);
    const int laneCB = ((lane >> 3) & 1) << 4;

    const int nkt = 2 * qt + 2;
    for (int kt = 0; kt < nkt; kt++) {
        __syncthreads();
        {
            const int key = tid >> 1, hf = tid & 1;
            const float* krow = kpB + (size_t)(kt * 64 + key) * (3 * DMODEL) + hf * 32;
            const float* vrow = vpB + (size_t)(kt * 64 + key) * (3 * DMODEL) + hf * 32;
            #pragma unroll
            for (int i = 0; i < 8; i++) {
                const int d = hf * 32 + 4 * i;
                const float4 kv = *(const float4*)(krow + 4 * i);
                __nv_bfloat16 h0,l0,h1,l1,h2,l2,h3,l3;
                split_bf16(kv.x,h0,l0); split_bf16(kv.y,h1,l1);
                split_bf16(kv.z,h2,l2); split_bf16(kv.w,h3,l3);
                const uint32_t sw = SWZ128((uint32_t)(key * 128 + d * 2));
                *(uint32_t*)(Kh + sw)     = packbf(h0, h1);
                *(uint32_t*)(Kh + sw + 4) = packbf(h2, h3);
                *(uint32_t*)(Kl + sw)     = packbf(l0, l1);
                *(uint32_t*)(Kl + sw + 4) = packbf(l2, l3);

                const float4 vv = *(const float4*)(vrow + 4 * i);
                const float vf[4] = {vv.x, vv.y, vv.z, vv.w};
                #pragma unroll
                for (int c = 0; c < 4; c++) {
                    __nv_bfloat16 vh_, vl_;
                    split_bf16(vf[c], vh_, vl_);
                    const uint32_t swv = SWZ128((uint32_t)((d + c) * 128 + key * 2));
                    *(__nv_bfloat16*)(Vh + swv) = vh_;
                    *(__nv_bfloat16*)(Vl + swv) = vl_;
                }
            }
        }
        __syncthreads();

        float s[2][8][4];
        #pragma unroll
        for (int mt = 0; mt < 2; mt++)
            #pragma unroll
            for (int j = 0; j < 8; j++)
                #pragma unroll
                for (int i = 0; i < 4; i++) s[mt][j][i] = 0.0f;

        #pragma unroll
        for (int kk = 0; kk < 4; kk++) {
            const int kb = kk * 32;
            uint32_t qh[2][4], ql[2][4], kh[8][2], kl[8][2];
            #pragma unroll
            for (int mt = 0; mt < 2; mt++) {
                const uint32_t off = SWZ128(
                    (uint32_t)(((w * 32 + mt * 16 + laneRA) << 7) + kb + laneCA));
                ldsm4(qh[mt], uQh + off);
                ldsm4(ql[mt], uQl + off);
            }
            #pragma unroll
            for (int j = 0; j < 4; j++) {
                const uint32_t off = SWZ128(
                    (uint32_t)(((j * 16 + laneRB) << 7) + kb + laneCB));
                ldsm4(&kh[j * 2][0], uKh + off);
                ldsm4(&kl[j * 2][0], uKl + off);
            }
            #pragma unroll
            for (int mt = 0; mt < 2; mt++)
                #pragma unroll
                for (int n = 0; n < 8; n++) mma16816bf(s[mt][n], qh[mt], kh[n]);
            #pragma unroll
            for (int mt = 0; mt < 2; mt++)
                #pragma unroll
                for (int n = 0; n < 8; n++) mma16816bf(s[mt][n], qh[mt], kl[n]);
            #pragma unroll
            for (int mt = 0; mt < 2; mt++)
                #pragma unroll
                for (int n = 0; n < 8; n++) mma16816bf(s[mt][n], ql[mt], kh[n]);
        }

        const int k0g = kt * 64;
        #pragma unroll
        for (int mt = 0; mt < 2; mt++) {
            #pragma unroll
            for (int half = 0; half < 2; half++) {
                const int qrow = qBase + w * 32 + mt * 16 + g + half * 8;
                const int r = mt * 2 + half;
                float tmax = -INFINITY;
                #pragma unroll
                for (int j = 0; j < 8; j++) {
                    const int key = k0g + j * 8 + 2 * t;
                    float v0 = s[mt][j][2 * half]     * 0.125f;
                    float v1 = s[mt][j][2 * half + 1] * 0.125f;
                    v0 = (key     <= qrow) ? v0 : -INFINITY;
                    v1 = (key + 1 <= qrow) ? v1 : -INFINITY;
                    s[mt][j][2 * half]     = v0;
                    s[mt][j][2 * half + 1] = v1;
                    tmax = fmaxf(tmax, fmaxf(v0, v1));
                }
                tmax = fmaxf(tmax, __shfl_xor_sync(0xffffffffu, tmax, 1));
                tmax = fmaxf(tmax, __shfl_xor_sync(0xffffffffu, tmax, 2));
                const float mnew = fmaxf(m_s[r], tmax);
                const float corr = __expf(m_s[r] - mnew);
                float lsum = 0.0f;
                #pragma unroll
                for (int j = 0; j < 8; j++) {
                    const float e0 = __expf(s[mt][j][2 * half]     - mnew);
                    const float e1 = __expf(s[mt][j][2 * half + 1] - mnew);
                    s[mt][j][2 * half]     = e0;
                    s[mt][j][2 * half + 1] = e1;
                    lsum += e0 + e1;
                }
                lsum += __shfl_xor_sync(0xffffffffu, lsum, 1);
                lsum += __shfl_xor_sync(0xffffffffu, lsum, 2);
                l_s[r] = l_s[r] * corr + lsum;
                m_s[r] = mnew;
                #pragma unroll
                for (int j = 0; j < 8; j++) {
                    acc_o[mt][j][2 * half]     *= corr;
                    acc_o[mt][j][2 * half + 1] *= corr;
                }
            }
        }

        #pragma unroll
        for (int kk = 0; kk < 4; kk++) {
            uint32_t aPh[2][4], aPl[2][4];
            #pragma unroll
            for (int mt = 0; mt < 2; mt++) {
                #pragma unroll
                for (int half2 = 0; half2 < 2; half2++) {
                    const int j = 2 * kk + half2;
                    __nv_bfloat16 h0,l0,h1,l1,h2,l2,h3,l3;
                    split_bf16(s[mt][j][0], h0, l0);
                    split_bf16(s[mt][j][1], h1, l1);
                    split_bf16(s[mt][j][2], h2, l2);
                    split_bf16(s[mt][j][3], h3, l3);
                    aPh[mt][2 * half2]     = packbf(h0, h1);
                    aPh[mt][2 * half2 + 1] = packbf(h2, h3);
                    aPl[mt][2 * half2]     = packbf(l0, l1);
                    aPl[mt][2 * half2 + 1] = packbf(l2, l3);
                }
            }
            uint32_t vh[8][2], vl[8][2];
            #pragma unroll
            for (int j = 0; j < 4; j++) {
                const uint32_t off = SWZ128(
                    (uint32_t)(((j * 16 + laneRB) << 7) + kk * 32 + laneCB));
                ldsm4(&vh[j * 2][0], uVh + off);
                ldsm4(&vl[j * 2][0], uVl + off);
            }
            #pragma unroll
            for (int mt = 0; mt < 2; mt++)
                #pragma unroll
                for (int n = 0; n < 8; n++) mma16816bf(acc_o[mt][n], aPh[mt], vh[n]);
            #pragma unroll
            for (int mt = 0; mt < 2; mt++)
                #pragma unroll
                for (int n = 0; n < 8; n++) mma16816bf(acc_o[mt][n], aPh[mt], vl[n]);
            #pragma unroll
            for (int mt = 0; mt < 2; mt++)
                #pragma unroll
                for (int n = 0; n < 8; n++) mma16816bf(acc_o[mt][n], aPl[mt], vh[n]);
        }
    }

    #pragma unroll
    for (int mt = 0; mt < 2; mt++) {
        #pragma unroll
        for (int half = 0; half < 2; half++) {
            const int qrow = qBase + w * 32 + mt * 16 + g + half * 8;
            const float inv = 1.0f / l_s[mt * 2 + half];
            const size_t obase = ((size_t)b * SEQ + qrow) * DMODEL + h * HEADDIM;
            #pragma unroll
            for (int j = 0; j < 8; j++) {
                const float v0 = acc_o[mt][j][2 * half]     * inv;
                const float v1 = acc_o[mt][j][2 * half + 1] * inv;
                __half h0, l0, h1, l1;
                split_h(v0, h0, l0);
                split_h(v1, h1, l1);
                const size_t o = obase + j * 8 + 2 * t;
                *(__half2*)(ohi + o) = __halves2half2(h0, h1);
                *(__half2*)(olo + o) = __halves2half2(l0, l1);
            }
        }
    }
}

// ---------------- loss ----------------
__global__ __launch_bounds__(256) void loss_token_kernel(
    const float* __restrict__ logits, const int* __restrict__ targets,
    const void* __restrict__ vmask,
    float* __restrict__ tce, float* __restrict__ tw)
{
    const int row = blockIdx.x;
    const float* lr = logits + (size_t)row * VOCAB;
    float v[16];
    #pragma unroll
    for (int i = 0; i < 16; i++) v[i] = lr[threadIdx.x + 256 * i];
    float mx = v[0];
    #pragma unroll
    for (int i = 1; i < 16; i++) mx = fmaxf(mx, v[i]);
    mx = blockReduceMax(mx);
    float se = 0.0f;
    #pragma unroll
    for (int i = 0; i < 16; i++) se += __expf(v[i] - mx);
    se = blockReduceSum(se);
    if (threadIdx.x == 0) {
        const int tgt = targets[row];
        const float lse = mx + logf(se);
        const float nll = lse - lr[tgt];
        int mv;
        if (g_mflag) mv = ((const unsigned char*)vmask)[row];
        else         mv = ((const int*)vmask)[row];
        const float w = 1.0f + 4.0f * ((mv != 0) ? 1.0f : 0.0f);
        tce[row] = (tgt == 0) ? 0.0f : nll * w;
        tw[row]  = w;
    }
}

__global__ __launch_bounds__(256) void loss_final_kernel(
    const float* __restrict__ tce, const float* __restrict__ tw, float* __restrict__ out)
{
    float a = 0.0f, b = 0.0f;
    for (int i = threadIdx.x; i < MTOK; i += 256) { a += tce[i]; b += tw[i]; }
    a = blockReduceSum(a);
    b = blockReduceSum(b);
    if (threadIdx.x == 0) out[0] = a / b;
}

// ---------------- host driver ----------------
extern "C" void kernel_launch(void* const* d_in, const int* in_sizes, int n_in,
                              void* d_out, int out_size)
{
    (void)in_sizes; (void)n_in;
    const int*   ids   = (const int*)d_in[0];
    const int*   tgts  = (const int*)d_in[1];
    const void*  vmask = (const void*)d_in[2];
    const float* tok   = (const float*)d_in[3];
    const float* pos   = (const float*)d_in[4];
    const float* ln1w  = (const float*)d_in[5];
    const float* ln1b  = (const float*)d_in[6];
    const float* wqkv  = (const float*)d_in[7];
    const float* bqkv  = (const float*)d_in[8];
    const float* wproj = (const float*)d_in[9];
    const float* bproj = (const float*)d_in[10];
    const float* ln2w  = (const float*)d_in[11];
    const float* ln2b  = (const float*)d_in[12];
    const float* w1    = (const float*)d_in[13];
    const float* b1    = (const float*)d_in[14];
    const float* w2    = (const float*)d_in[15];
    const float* b2    = (const float*)d_in[16];
    const float* lnfw  = (const float*)d_in[17];
    const float* lnfb  = (const float*)d_in[18];
    float* out = (float*)d_out;

    float *x, *qkv, *tce, *tw;
    __half *hhi, *hlo, *mhi, *mlo;
    __half *wq_h, *wp_h, *w1_h, *w2_h, *lm_hi, *lm_lo;
    cudaGetSymbolAddress((void**)&x,    g_x);
    cudaGetSymbolAddress((void**)&qkv,  g_qkv);
    cudaGetSymbolAddress((void**)&hhi,  g_hhi);
    cudaGetSymbolAddress((void**)&hlo,  g_hlo);
    cudaGetSymbolAddress((void**)&mhi,  g_mhi);
    cudaGetSymbolAddress((void**)&mlo,  g_mlo);
    cudaGetSymbolAddress((void**)&wq_h, g_wqkv_h);
    cudaGetSymbolAddress((void**)&wp_h, g_wproj_h);
    cudaGetSymbolAddress((void**)&w1_h, g_w1_h);
    cudaGetSymbolAddress((void**)&w2_h, g_w2_h);
    cudaGetSymbolAddress((void**)&lm_hi, g_lmh_hi);
    cudaGetSymbolAddress((void**)&lm_lo, g_lmh_lo);
    cudaGetSymbolAddress((void**)&tce,  g_tce);
    cudaGetSymbolAddress((void**)&tw,   g_tw);

    cudaFuncSetAttribute(gemm_ldsm_kernel<EPI_NONE, false>,
                         cudaFuncAttributeMaxDynamicSharedMemorySize, GEMM_SMEM_2P);
    cudaFuncSetAttribute(gemm_ldsm_kernel<EPI_RES, false>,
                         cudaFuncAttributeMaxDynamicSharedMemorySize, GEMM_SMEM_2P);
    cudaFuncSetAttribute(gemm_ldsm_kernel<EPI_GELU, false>,
                         cudaFuncAttributeMaxDynamicSharedMemorySize, GEMM_SMEM_2P);
    cudaFuncSetAttribute(gemm_ldsm_kernel<EPI_NONE, true>,
                         cudaFuncAttributeMaxDynamicSharedMemorySize, GEMM_SMEM_3P);
    cudaFuncSetAttribute(attn_mma_kernel,
                         cudaFuncAttributeMaxDynamicSharedMemorySize, ATTN_SMEM_BYTES);

    // ---- pack weights: [K][N] fp32 -> [N][K] fp16 ----
    convw_h<<<dim3(3*DMODEL/32, DMODEL/32, NLAYER), 256>>>(wqkv,  wq_h, DMODEL, 3*DMODEL);
    convw_h<<<dim3(DMODEL/32,   DMODEL/32, NLAYER), 256>>>(wproj, wp_h, DMODEL, DMODEL);
    convw_h<<<dim3(DFF/32,      DMODEL/32, NLAYER), 256>>>(w1,    w1_h, DMODEL, DFF);
    convw_h<<<dim3(DMODEL/32,   DFF/32,    NLAYER), 256>>>(w2,    w2_h, DFF,    DMODEL);
    convsplit<<<VOCAB*DMODEL/256, 256>>>(tok, lm_hi, lm_lo);

    detect_mask_kernel<<<1, 256>>>((const unsigned char*)vmask);
    embed_kernel<<<MTOK, 256>>>(ids, tok, pos, x);

    const size_t wq_s = (size_t)3*DMODEL*DMODEL;
    const size_t wp_s = (size_t)DMODEL*DMODEL;
    const size_t w1_s = (size_t)DFF*DMODEL;
    const size_t w2_s = (size_t)DMODEL*DFF;

    for (int l = 0; l < NLAYER; l++) {
        ln_h_kernel<<<MTOK, 256>>>(x, ln1w + l*DMODEL, ln1b + l*DMODEL, hhi, hlo);

        gemm_ldsm_kernel<EPI_NONE, false><<<dim3(3*DMODEL/64, MTOK/128), 256, GEMM_SMEM_2P>>>(
            hhi, hlo, wq_h + l*wq_s, nullptr,
            bqkv + (size_t)l*3*DMODEL, nullptr, qkv, nullptr, nullptr,
            MTOK, 3*DMODEL, DMODEL);

        attn_mma_kernel<<<dim3(SEQ/128, NHEAD, BATCH), 128, ATTN_SMEM_BYTES>>>(qkv, hhi, hlo);

        gemm_ldsm_kernel<EPI_RES, false><<<dim3(DMODEL/64, MTOK/128), 256, GEMM_SMEM_2P>>>(
            hhi, hlo, wp_h + l*wp_s, nullptr,
            bproj + (size_t)l*DMODEL, x, x, nullptr, nullptr,
            MTOK, DMODEL, DMODEL);

        ln_h_kernel<<<MTOK, 256>>>(x, ln2w + l*DMODEL, ln2b + l*DMODEL, hhi, hlo);

        gemm_ldsm_kernel<EPI_GELU, false><<<dim3(DFF/64, MTOK/128), 256, GEMM_SMEM_2P>>>(
            hhi, hlo, w1_h + l*w1_s, nullptr,
            b1 + (size_t)l*DFF, nullptr, nullptr, mhi, mlo,
            MTOK, DFF, DMODEL);

        gemm_ldsm_kernel<EPI_RES, false><<<dim3(DMODEL/64, MTOK/128), 256, GEMM_SMEM_2P>>>(
            mhi, mlo, w2_h + l*w2_s, nullptr,
            b2 + (size_t)l*DMODEL, x, x, nullptr, nullptr,
            MTOK, DMODEL, DFF);
    }

    ln_h_kernel<<<MTOK, 256>>>(x, lnfw, lnfb, hhi, hlo);

    // lm_head: 3-product fp16 (logits accuracy)
    gemm_ldsm_kernel<EPI_NONE, true><<<dim3(VOCAB/64, MTOK/128), 256, GEMM_SMEM_3P>>>(
        hhi, hlo, lm_hi, lm_lo, nullptr, nullptr, out, nullptr, nullptr,
        MTOK, VOCAB, DMODEL);

    if (out_size > MTOK * VOCAB) {
        loss_token_kernel<<<MTOK, 256>>>(out, tgts, vmask, tce, tw);
        loss_final_kernel<<<1, 256>>>(tce, tw, out + (size_t)MTOK * VOCAB);
    }
}